// round 7
// baseline (speedup 1.0000x reference)
#include <cuda_runtime.h>
#include <math.h>

#define BATCH   128
#define TSTEPS  256
#define HORIZON 512
#define OBS     32
#define LAT     256
#define HID     1024
#define NB2     264              // 256 layer CTAs + 8 Whh CTAs, all co-resident
#define ZSTRIDE (BATCH * LAT)

// ---------------------------------------------------------------------------
// Scratch
// ---------------------------------------------------------------------------
__device__ float g_Z[(size_t)(HORIZON + 1) * ZSTRIDE];
__device__ float g_A[(size_t)128 * BATCH * HID];   // phase1b acts / phase2 partials
__device__ float g_B[(size_t)128 * BATCH * HID];
__device__ float g_C[BATCH * LAT];
__device__ unsigned g_ctr;                 // barrier arrival counter
__device__ unsigned g_rel[NB2 * 32];       // per-CTA release words, 128B apart

// ---------------------------------------------------------------------------
// f32x2 helpers
// ---------------------------------------------------------------------------
typedef unsigned long long u64;
__device__ __forceinline__ u64 f2dup(float s) {
    u64 r; asm("mov.b64 %0, {%1, %1};" : "=l"(r) : "f"(s)); return r;
}
__device__ __forceinline__ void f2fma(u64& d, u64 a, u64 b) {
    asm("fma.rn.f32x2 %0, %1, %2, %0;" : "+l"(d) : "l"(a), "l"(b));
}
__device__ __forceinline__ float2 f2unpack(u64 v) {
    float2 r; asm("mov.b64 {%0, %1}, %2;" : "=f"(r.x), "=f"(r.y) : "l"(v)); return r;
}

// ---------------------------------------------------------------------------
// Distributed-flag grid barrier.
// Arrival: one atomicAdd per CTA (single address, cheap drain).
// Release: CTA 0 polls the counter, then writes one epoch word per CTA,
//          each on its own 128B line; every CTA polls only ITS line.
// ---------------------------------------------------------------------------
__device__ __forceinline__ void gsync(unsigned& epoch) {
    epoch++;
    __syncthreads();
    __threadfence();
    const int bid = blockIdx.x, tid = threadIdx.x;
    if (bid == 0) {
        if (tid == 0) {
            atomicAdd(&g_ctr, 1u);
            const unsigned goal = epoch * gridDim.x;
            while (*((volatile unsigned*)&g_ctr) < goal) {}
            __threadfence();
        }
        __syncthreads();
        for (int i = tid; i < (int)gridDim.x; i += blockDim.x)
            *((volatile unsigned*)&g_rel[i * 32]) = epoch;
        __syncthreads();
    } else {
        if (tid == 0) {
            atomicAdd(&g_ctr, 1u);
            volatile unsigned* my = &g_rel[bid * 32];
            while (*my < epoch) {}
            __threadfence();
        }
        __syncthreads();
    }
}

// ---------------------------------------------------------------------------
// Phase 1a: barrier-free recurrence. CTA b owns batch row b.
// ---------------------------------------------------------------------------
__global__ void __launch_bounds__(256) phase1a_kernel(
    const float* __restrict__ y,
    const float* __restrict__ Wih, const float* __restrict__ Whh,
    const float* __restrict__ bih, const float* __restrict__ bhh,
    float* __restrict__ Z)
{
    const int b = blockIdx.x, tid = threadIdx.x;
    __shared__ float sz[LAT];
    __shared__ float sy[OBS];

    sz[tid] = 0.0f;
    __stcg(Z + (size_t)b * LAT + tid, 0.0f);
    float bsum = __ldg(bih + tid) + __ldg(bhh + tid);

    float4 wi[8];
    const float4* wip = (const float4*)(Wih + (size_t)tid * OBS);
#pragma unroll
    for (int k = 0; k < 8; k++) wi[k] = __ldg(wip + k);
    const float4* wh = (const float4*)(Whh + (size_t)tid * LAT);
    __syncthreads();

    for (int t = 0; t < TSTEPS; t++) {
        if (tid < OBS) sy[tid] = __ldg(y + ((size_t)b * TSTEPS + t) * OBS + tid);
        __syncthreads();
        float acc = bsum;
#pragma unroll
        for (int k = 0; k < 8; k++) {
            float4 w = wi[k];
            acc += sy[k*4+0]*w.x + sy[k*4+1]*w.y + sy[k*4+2]*w.z + sy[k*4+3]*w.w;
        }
#pragma unroll 8
        for (int k = 0; k < 64; k++) {
            float4 w = __ldg(wh + k);
            acc += sz[k*4+0]*w.x + sz[k*4+1]*w.y + sz[k*4+2]*w.z + sz[k*4+3]*w.w;
        }
        float zn = tanhf(acc);
        __syncthreads();
        sz[tid] = zn;
        __stcg(Z + ((size_t)t + 1) * ZSTRIDE + (size_t)b * LAT + tid, zn);
    }
}

// ---------------------------------------------------------------------------
// Phase 1b GEMM: 128x128 tile, 8x8 microtile, f32x2.
// ---------------------------------------------------------------------------
template<int ACT>
__global__ void __launch_bounds__(256, 2) gemm_big(
    const float* __restrict__ X, int ldx,
    const float* __restrict__ W, int ldw,
    const float* __restrict__ bias,
    float* __restrict__ Y, int ldy, int K)
{
    __shared__ __align__(16) float sX[16 * 132];
    __shared__ __align__(16) float sW[16 * 132];
    const int tid = threadIdx.x;
    const int ty = tid >> 4, tx = tid & 15;
    const int mB = blockIdx.y * 128, nB = blockIdx.x * 128;
    const int xr = tid >> 2, xc = tid & 3;

    const float* Xp0 = X + (size_t)(mB + xr) * ldx + xc * 4;
    const float* Xp1 = Xp0 + (size_t)64 * ldx;
    const float* Wp0 = W + (size_t)(nB + xr) * ldw + xc * 4;
    const float* Wp1 = Wp0 + (size_t)64 * ldw;

    float4 xv0 = __ldg((const float4*)Xp0);
    float4 xv1 = __ldg((const float4*)Xp1);
    float4 wv0 = __ldg((const float4*)Wp0);
    float4 wv1 = __ldg((const float4*)Wp1);

    u64 acc[4][8];
#pragma unroll
    for (int i = 0; i < 4; i++)
#pragma unroll
        for (int j = 0; j < 8; j++) acc[i][j] = 0ull;

    for (int k0 = 0;;) {
        sX[(xc*4+0)*132 + xr] = xv0.x; sX[(xc*4+1)*132 + xr] = xv0.y;
        sX[(xc*4+2)*132 + xr] = xv0.z; sX[(xc*4+3)*132 + xr] = xv0.w;
        sX[(xc*4+0)*132 + xr+64] = xv1.x; sX[(xc*4+1)*132 + xr+64] = xv1.y;
        sX[(xc*4+2)*132 + xr+64] = xv1.z; sX[(xc*4+3)*132 + xr+64] = xv1.w;
        sW[(xc*4+0)*132 + xr] = wv0.x; sW[(xc*4+1)*132 + xr] = wv0.y;
        sW[(xc*4+2)*132 + xr] = wv0.z; sW[(xc*4+3)*132 + xr] = wv0.w;
        sW[(xc*4+0)*132 + xr+64] = wv1.x; sW[(xc*4+1)*132 + xr+64] = wv1.y;
        sW[(xc*4+2)*132 + xr+64] = wv1.z; sW[(xc*4+3)*132 + xr+64] = wv1.w;
        __syncthreads();

        const int k1 = k0 + 16;
        if (k1 < K) {
            xv0 = __ldg((const float4*)(Xp0 + k1));
            xv1 = __ldg((const float4*)(Xp1 + k1));
            wv0 = __ldg((const float4*)(Wp0 + k1));
            wv1 = __ldg((const float4*)(Wp1 + k1));
        }
#pragma unroll
        for (int kk = 0; kk < 16; kk++) {
            ulonglong2 aA = *(const ulonglong2*)&sX[kk*132 + ty*8];
            ulonglong2 aB = *(const ulonglong2*)&sX[kk*132 + ty*8 + 4];
            float4 b0 = *(const float4*)&sW[kk*132 + tx*8];
            float4 b1 = *(const float4*)&sW[kk*132 + tx*8 + 4];
            u64 bd[8];
            bd[0]=f2dup(b0.x); bd[1]=f2dup(b0.y); bd[2]=f2dup(b0.z); bd[3]=f2dup(b0.w);
            bd[4]=f2dup(b1.x); bd[5]=f2dup(b1.y); bd[6]=f2dup(b1.z); bd[7]=f2dup(b1.w);
#pragma unroll
            for (int j = 0; j < 8; j++) {
                f2fma(acc[0][j], aA.x, bd[j]);
                f2fma(acc[1][j], aA.y, bd[j]);
                f2fma(acc[2][j], aB.x, bd[j]);
                f2fma(acc[3][j], aB.y, bd[j]);
            }
        }
        __syncthreads();
        if (k1 >= K) break;
        k0 = k1;
    }

    float4 bb0 = __ldg((const float4*)(bias + nB + tx * 8));
    float4 bb1 = __ldg((const float4*)(bias + nB + tx * 8 + 4));
#pragma unroll
    for (int mp = 0; mp < 4; mp++) {
        float2 u[8];
#pragma unroll
        for (int j = 0; j < 8; j++) u[j] = f2unpack(acc[mp][j]);
        float4 r0a = make_float4(u[0].x+bb0.x, u[1].x+bb0.y, u[2].x+bb0.z, u[3].x+bb0.w);
        float4 r0b = make_float4(u[4].x+bb1.x, u[5].x+bb1.y, u[6].x+bb1.z, u[7].x+bb1.w);
        float4 r1a = make_float4(u[0].y+bb0.x, u[1].y+bb0.y, u[2].y+bb0.z, u[3].y+bb0.w);
        float4 r1b = make_float4(u[4].y+bb1.x, u[5].y+bb1.y, u[6].y+bb1.z, u[7].y+bb1.w);
        if (ACT) {
            r0a.x=fmaxf(r0a.x,0.f); r0a.y=fmaxf(r0a.y,0.f); r0a.z=fmaxf(r0a.z,0.f); r0a.w=fmaxf(r0a.w,0.f);
            r0b.x=fmaxf(r0b.x,0.f); r0b.y=fmaxf(r0b.y,0.f); r0b.z=fmaxf(r0b.z,0.f); r0b.w=fmaxf(r0b.w,0.f);
            r1a.x=fmaxf(r1a.x,0.f); r1a.y=fmaxf(r1a.y,0.f); r1a.z=fmaxf(r1a.z,0.f); r1a.w=fmaxf(r1a.w,0.f);
            r1b.x=fmaxf(r1b.x,0.f); r1b.y=fmaxf(r1b.y,0.f); r1b.z=fmaxf(r1b.z,0.f); r1b.w=fmaxf(r1b.w,0.f);
        }
        const int row0 = mB + ty * 8 + mp * 2;
        float* y0 = Y + (size_t)row0 * ldy + nB + tx * 8;
        float* y1 = y0 + ldy;
        *(float4*)y0 = r0a; *(float4*)(y0 + 4) = r0b;
        *(float4*)y1 = r1a; *(float4*)(y1 + 4) = r1b;
    }
}

// ---------------------------------------------------------------------------
// Phase 1b output layer.
// ---------------------------------------------------------------------------
__global__ void __launch_bounds__(256) gemm_out(
    const float* __restrict__ X, int ldx,
    const float* __restrict__ W, int ldw,
    const float* __restrict__ bias,
    float* __restrict__ out, int K, int t0)
{
    __shared__ __align__(16) float sX[16 * 132];
    __shared__ __align__(16) float sW[16 * 36];
    const int tid = threadIdx.x;
    const int ty = tid >> 4, tx = tid & 15;
    const int mB = blockIdx.y * 128;
    const int xr = tid >> 2, xc = tid & 3;

    const float* Xp0 = X + (size_t)(mB + xr) * ldx + xc * 4;
    const float* Xp1 = Xp0 + (size_t)64 * ldx;
    const bool wp = tid < 128;
    const float* Wp = W + (size_t)xr * ldw + xc * 4;

    float4 xv0 = __ldg((const float4*)Xp0);
    float4 xv1 = __ldg((const float4*)Xp1);
    float4 wv = make_float4(0,0,0,0);
    if (wp) wv = __ldg((const float4*)Wp);

    float acc[8][2];
#pragma unroll
    for (int i = 0; i < 8; i++) { acc[i][0] = 0.f; acc[i][1] = 0.f; }

    for (int k0 = 0;;) {
        sX[(xc*4+0)*132 + xr] = xv0.x; sX[(xc*4+1)*132 + xr] = xv0.y;
        sX[(xc*4+2)*132 + xr] = xv0.z; sX[(xc*4+3)*132 + xr] = xv0.w;
        sX[(xc*4+0)*132 + xr+64] = xv1.x; sX[(xc*4+1)*132 + xr+64] = xv1.y;
        sX[(xc*4+2)*132 + xr+64] = xv1.z; sX[(xc*4+3)*132 + xr+64] = xv1.w;
        if (wp) {
            sW[(xc*4+0)*36 + xr] = wv.x; sW[(xc*4+1)*36 + xr] = wv.y;
            sW[(xc*4+2)*36 + xr] = wv.z; sW[(xc*4+3)*36 + xr] = wv.w;
        }
        __syncthreads();
        const int k1 = k0 + 16;
        if (k1 < K) {
            xv0 = __ldg((const float4*)(Xp0 + k1));
            xv1 = __ldg((const float4*)(Xp1 + k1));
            if (wp) wv = __ldg((const float4*)(Wp + k1));
        }
#pragma unroll
        for (int kk = 0; kk < 16; kk++) {
            float4 a0 = *(const float4*)&sX[kk*132 + ty*8];
            float4 a1 = *(const float4*)&sX[kk*132 + ty*8 + 4];
            float2 b  = *(const float2*)&sW[kk*36 + tx*2];
            acc[0][0]+=a0.x*b.x; acc[0][1]+=a0.x*b.y;
            acc[1][0]+=a0.y*b.x; acc[1][1]+=a0.y*b.y;
            acc[2][0]+=a0.z*b.x; acc[2][1]+=a0.z*b.y;
            acc[3][0]+=a0.w*b.x; acc[3][1]+=a0.w*b.y;
            acc[4][0]+=a1.x*b.x; acc[4][1]+=a1.x*b.y;
            acc[5][0]+=a1.y*b.x; acc[5][1]+=a1.y*b.y;
            acc[6][0]+=a1.z*b.x; acc[6][1]+=a1.z*b.y;
            acc[7][0]+=a1.w*b.x; acc[7][1]+=a1.w*b.y;
        }
        __syncthreads();
        if (k1 >= K) break;
        k0 = k1;
    }

    float2 bb = *(const float2*)(bias + tx * 2);
#pragma unroll
    for (int i = 0; i < 8; i++) {
        int r = mB + ty * 8 + i;
        int b = r & (BATCH - 1);
        int t = t0 + (r >> 7);
        float2 v = make_float2(acc[i][0] + bb.x, acc[i][1] + bb.y);
        *(float2*)(out + ((size_t)b * HORIZON + t) * OBS + tx * 2) = v;
    }
}

// ---------------------------------------------------------------------------
// Phase-2 split-K tile: 16x64, 128 thr; raw partial over [kOff, kOff+Keff).
// COMBINE: X element = relu(X0 + X1 + bIn) fused at load time.
// ---------------------------------------------------------------------------
template<bool COMBINE>
__device__ __forceinline__ void tile16x64(
    int mB, int nB, int kOff, int Keff,
    const float* __restrict__ X0, const float* __restrict__ X1,
    const float* __restrict__ bIn, int ldx,
    const float* __restrict__ W, int ldw,
    float* __restrict__ Pout, int ldp,
    float* sX, float* sW)
{
    const int tid = threadIdx.x;
    const int ty = tid >> 4, tx = tid & 15;
    const int xr = tid >> 3, xc = tid & 7;

    const float* Xp = X0 + (size_t)(mB + xr) * ldx + kOff + xc * 4;
    const float* Xq = X1 + (size_t)(mB + xr) * ldx + kOff + xc * 4;
    const float* Bp = bIn + kOff + xc * 4;
    const float* Wp = W + (size_t)(nB + xr) * ldw + kOff + xc * 4;

    float4 xv;
    {
        float4 a = __ldcg((const float4*)Xp);
        if constexpr (COMBINE) {
            float4 b = __ldcg((const float4*)Xq);
            float4 c = __ldg((const float4*)Bp);
            xv = make_float4(fmaxf(a.x+b.x+c.x, 0.f), fmaxf(a.y+b.y+c.y, 0.f),
                             fmaxf(a.z+b.z+c.z, 0.f), fmaxf(a.w+b.w+c.w, 0.f));
        } else xv = a;
    }
    float4 wv[4];
#pragma unroll
    for (int j = 0; j < 4; j++)
        wv[j] = __ldg((const float4*)(Wp + (size_t)(j * 16) * ldw));

    u64 acc[2][2] = {{0ull,0ull},{0ull,0ull}};

    for (int k0 = 0;;) {
        sX[(xc*4+0)*17 + xr] = xv.x; sX[(xc*4+1)*17 + xr] = xv.y;
        sX[(xc*4+2)*17 + xr] = xv.z; sX[(xc*4+3)*17 + xr] = xv.w;
#pragma unroll
        for (int j = 0; j < 4; j++) {
            int wr = xr + j * 16;
            sW[(xc*4+0)*68 + wr] = wv[j].x; sW[(xc*4+1)*68 + wr] = wv[j].y;
            sW[(xc*4+2)*68 + wr] = wv[j].z; sW[(xc*4+3)*68 + wr] = wv[j].w;
        }
        __syncthreads();
        const int k1 = k0 + 32;
        if (k1 < Keff) {
            float4 a = __ldcg((const float4*)(Xp + k1));
            if constexpr (COMBINE) {
                float4 b = __ldcg((const float4*)(Xq + k1));
                float4 c = __ldg((const float4*)(Bp + k1));
                xv = make_float4(fmaxf(a.x+b.x+c.x, 0.f), fmaxf(a.y+b.y+c.y, 0.f),
                                 fmaxf(a.z+b.z+c.z, 0.f), fmaxf(a.w+b.w+c.w, 0.f));
            } else xv = a;
#pragma unroll
            for (int j = 0; j < 4; j++)
                wv[j] = __ldg((const float4*)(Wp + (size_t)(j * 16) * ldw + k1));
        }
#pragma unroll
        for (int kk = 0; kk < 32; kk++) {
            u64 a0 = f2dup(sX[kk*17 + ty]);
            u64 a1 = f2dup(sX[kk*17 + ty + 8]);
            ulonglong2 bp = *(const ulonglong2*)&sW[kk*68 + tx*4];
            f2fma(acc[0][0], a0, bp.x); f2fma(acc[0][1], a0, bp.y);
            f2fma(acc[1][0], a1, bp.x); f2fma(acc[1][1], a1, bp.y);
        }
        __syncthreads();
        if (k1 >= Keff) break;
        k0 = k1;
    }

#pragma unroll
    for (int i = 0; i < 2; i++) {
        int row = mB + ty + i * 8;
        float2 p0 = f2unpack(acc[i][0]);
        float2 p1 = f2unpack(acc[i][1]);
        float4 v = make_float4(p0.x, p0.y, p1.x, p1.y);
        __stcg((float4*)(Pout + (size_t)row * ldp + nB + tx * 4), v);
    }
}

// ---------------------------------------------------------------------------
// Phase 2: persistent AR rollout, 264 CTAs, 5 barriers/step.
// ---------------------------------------------------------------------------
__global__ void __launch_bounds__(128) phase2_kernel(
    const float* __restrict__ W1, const float* __restrict__ b1,
    const float* __restrict__ W2, const float* __restrict__ b2,
    const float* __restrict__ W3, const float* __restrict__ b3,
    const float* __restrict__ W4, const float* __restrict__ b4,
    const float* __restrict__ W5, const float* __restrict__ b5,
    const float* __restrict__ Wih, const float* __restrict__ Whh,
    const float* __restrict__ bih, const float* __restrict__ bhh,
    float* __restrict__ Z, float* __restrict__ P,
    float* __restrict__ C, float* __restrict__ out)
{
    __shared__ __align__(16) float sX[32 * 17];
    __shared__ __align__(16) float sW[32 * 68];
    unsigned epoch = 0;
    const int bid = blockIdx.x;
    const int tid = threadIdx.x;

    float* PA0 = P;
    float* PA1 = P + 131072;
    float* PB0 = P + 262144;
    float* PB1 = P + 393216;

    const int ksel = bid & 1;
    const int tile = bid >> 1;
    const int mT = (tile >> 4) * 16;
    const int nT = (tile & 15) * 64;

    for (int t = TSTEPS; t < HORIZON; t++) {
        const float* z = Z + (size_t)t * ZSTRIDE;

        // R1: L1 (K=256, split 128) -> PA ; Whh tiles 0..7
        if (bid < 256) {
            tile16x64<false>(mT, nT, ksel * 128, 128, z, z, b1, LAT,
                             W1, LAT, ksel ? PA1 : PA0, HID, sX, sW);
        } else {
            int wt = bid - 256;
            tile16x64<false>((wt >> 2) * 16, (wt & 3) * 64, 0, LAT, z, z, b1, LAT,
                             Whh, LAT, C, LAT, sX, sW);
        }
        gsync(epoch);

        // R2: L2 = relu(PA0+PA1+b1) @ W2 (split 512) -> PB ; Whh 8..15
        if (bid < 256) {
            tile16x64<true>(mT, nT, ksel * 512, 512, PA0, PA1, b1, HID,
                            W2, HID, ksel ? PB1 : PB0, HID, sX, sW);
        } else {
            int wt = 8 + (bid - 256);
            tile16x64<false>((wt >> 2) * 16, (wt & 3) * 64, 0, LAT, z, z, b1, LAT,
                             Whh, LAT, C, LAT, sX, sW);
        }
        gsync(epoch);

        // R3: L3 -> PA ; Whh 16..23
        if (bid < 256) {
            tile16x64<true>(mT, nT, ksel * 512, 512, PB0, PB1, b2, HID,
                            W3, HID, ksel ? PA1 : PA0, HID, sX, sW);
        } else {
            int wt = 16 + (bid - 256);
            tile16x64<false>((wt >> 2) * 16, (wt & 3) * 64, 0, LAT, z, z, b1, LAT,
                             Whh, LAT, C, LAT, sX, sW);
        }
        gsync(epoch);

        // R4: L4 -> PB ; Whh 24..31
        if (bid < 256) {
            tile16x64<true>(mT, nT, ksel * 512, 512, PA0, PA1, b3, HID,
                            W4, HID, ksel ? PB1 : PB0, HID, sX, sW);
        } else {
            int wt = 24 + (bid - 256);
            tile16x64<false>((wt >> 2) * 16, (wt & 3) * 64, 0, LAT, z, z, b1, LAT,
                             Whh, LAT, C, LAT, sX, sW);
        }
        gsync(epoch);

        // R5: CTA b: h4 = relu(PB0+PB1+b4); yh = h4 @ W5^T + b5; out; cell
        if (bid < 128) {
            const int b = bid;
            const float4* r0 = (const float4*)(PB0 + (size_t)b * HID);
            const float4* r1 = (const float4*)(PB1 + (size_t)b * HID);
            const float4* bb4 = (const float4*)b4;
            for (int i = tid; i < 256; i += 128) {
                float4 q0 = __ldcg(r0 + i);
                float4 q1 = __ldcg(r1 + i);
                float4 c4 = __ldg(bb4 + i);
                float4 v = make_float4(fmaxf(q0.x+q1.x+c4.x, 0.f),
                                       fmaxf(q0.y+q1.y+c4.y, 0.f),
                                       fmaxf(q0.z+q1.z+c4.z, 0.f),
                                       fmaxf(q0.w+q1.w+c4.w, 0.f));
                ((float4*)sW)[i] = v;
            }
            __syncthreads();
            {
                const int n = tid >> 2, q = tid & 3;
                const float4* w5 = (const float4*)(W5 + (size_t)n * HID) + q * 64;
                const float4* xb = (const float4*)sW + q * 64;
                float s = 0.f;
#pragma unroll 8
                for (int k = 0; k < 64; k++) {
                    float4 w = __ldg(w5 + k);
                    float4 x = xb[k];
                    s += x.x*w.x + x.y*w.y + x.z*w.z + x.w*w.w;
                }
                sX[tid] = s;
            }
            __syncthreads();
            if (tid < OBS) {
                float yh = sX[tid*4] + sX[tid*4+1] + sX[tid*4+2] + sX[tid*4+3]
                         + __ldg(b5 + tid);
                __stcg(out + ((size_t)b * HORIZON + t) * OBS + tid, yh);
                sX[256 + tid] = yh;
            }
            __syncthreads();
            if (t < HORIZON - 1) {
#pragma unroll
                for (int p = 0; p < 2; p++) {
                    const int n = tid + p * 128;
                    float acc = __ldcg(C + (size_t)b * LAT + n)
                              + __ldg(bih + n) + __ldg(bhh + n);
                    const float4* wr = (const float4*)(Wih + (size_t)n * OBS);
#pragma unroll
                    for (int k = 0; k < 8; k++) {
                        float4 w = __ldg(wr + k);
                        acc += sX[256+k*4+0]*w.x + sX[256+k*4+1]*w.y
                             + sX[256+k*4+2]*w.z + sX[256+k*4+3]*w.w;
                    }
                    __stcg(Z + ((size_t)t + 1) * ZSTRIDE + (size_t)b * LAT + n, tanhf(acc));
                }
            }
        }
        gsync(epoch);
    }
}

// ---------------------------------------------------------------------------
// Launch (~14 graph nodes)
// ---------------------------------------------------------------------------
extern "C" void kernel_launch(void* const* d_in, const int* in_sizes, int n_in,
                              void* d_out, int out_size)
{
    const float* y   = (const float*)d_in[0];
    const float* Wih = (const float*)d_in[2];
    const float* Whh = (const float*)d_in[3];
    const float* bih = (const float*)d_in[4];
    const float* bhh = (const float*)d_in[5];
    const float* W1  = (const float*)d_in[6];
    const float* b1  = (const float*)d_in[7];
    const float* W2  = (const float*)d_in[8];
    const float* b2  = (const float*)d_in[9];
    const float* W3  = (const float*)d_in[10];
    const float* b3  = (const float*)d_in[11];
    const float* W4  = (const float*)d_in[12];
    const float* b4  = (const float*)d_in[13];
    const float* W5  = (const float*)d_in[14];
    const float* b5  = (const float*)d_in[15];
    float* out = (float*)d_out;

    float *Z, *A, *Bf, *C;
    unsigned *ctr, *rel;
    cudaGetSymbolAddress((void**)&Z,   g_Z);
    cudaGetSymbolAddress((void**)&A,   g_A);
    cudaGetSymbolAddress((void**)&Bf,  g_B);
    cudaGetSymbolAddress((void**)&C,   g_C);
    cudaGetSymbolAddress((void**)&ctr, g_ctr);
    cudaGetSymbolAddress((void**)&rel, g_rel);

    // Phase 1a
    phase1a_kernel<<<BATCH, 256>>>(y, Wih, Whh, bih, bhh, Z);

    // Phase 1b: 2 chunks of 128 steps
    const int CHUNK = 128;
    const int MBIG  = CHUNK * BATCH;
    for (int c = 0; c < TSTEPS / CHUNK; c++) {
        const float* Xz = Z + (size_t)c * CHUNK * ZSTRIDE;
        gemm_big<1><<<dim3(HID/128, MBIG/128), 256>>>(Xz, LAT, W1, LAT, b1, A, HID, LAT);
        gemm_big<1><<<dim3(HID/128, MBIG/128), 256>>>(A, HID, W2, HID, b2, Bf, HID, HID);
        gemm_big<1><<<dim3(HID/128, MBIG/128), 256>>>(Bf, HID, W3, HID, b3, A, HID, HID);
        gemm_big<1><<<dim3(HID/128, MBIG/128), 256>>>(A, HID, W4, HID, b4, Bf, HID, HID);
        gemm_out<<<dim3(1, MBIG/128), 256>>>(Bf, HID, W5, HID, b5, out, HID, c * CHUNK);
    }

    // Phase 2: reset barrier state, then persistent rollout
    cudaMemsetAsync(ctr, 0, sizeof(unsigned));
    cudaMemsetAsync(rel, 0, sizeof(unsigned) * NB2 * 32);
    phase2_kernel<<<NB2, 128>>>(W1, b1, W2, b2, W3, b3, W4, b4, W5, b5,
                                Wih, Whh, bih, bhh, Z, A, C, out);
}

// round 8
// speedup vs baseline: 1.0760x; 1.0760x over previous
#include <cuda_runtime.h>
#include <math.h>
#include <stdint.h>

#define BATCH   128
#define TSTEPS  256
#define HORIZON 512
#define OBS     32
#define LAT     256
#define HID     1024
#define NB2     136
#define ZSTRIDE (BATCH * LAT)

__device__ float g_Z[(size_t)(HORIZON + 1) * ZSTRIDE];
__device__ float g_A[(size_t)128 * BATCH * HID];
__device__ float g_B[(size_t)128 * BATCH * HID];
__device__ float g_WH[3473408];
__device__ float g_WL[3473408];
__device__ unsigned g_ctr;
__device__ unsigned g_rel[NB2 * 32];

#define OFF_W1  0
#define OFF_W2  262144
#define OFF_W3  1310720
#define OFF_W4  2359296
#define OFF_WHH 3407872

#define P2_AH   0
#define P2_AL   131072
#define P2_BH   262144
#define P2_BL   393216
#define P2_ZH   524288
#define P2_ZL   557056
#define P2_C    589824

typedef unsigned long long u64;
__device__ __forceinline__ u64 f2dup(float s) {
    u64 r; asm("mov.b64 %0, {%1, %1};" : "=l"(r) : "f"(s)); return r;
}
__device__ __forceinline__ void f2fma(u64& d, u64 a, u64 b) {
    asm("fma.rn.f32x2 %0, %1, %2, %0;" : "+l"(d) : "l"(a), "l"(b));
}
__device__ __forceinline__ float2 f2unpack(u64 v) {
    float2 r; asm("mov.b64 {%0, %1}, %2;" : "=f"(r.x), "=f"(r.y) : "l"(v)); return r;
}
__device__ __forceinline__ float tf32_hi(float v) {
    uint32_t u; asm("cvt.rna.tf32.f32 %0, %1;" : "=r"(u) : "f"(v));
    return __uint_as_float(u);
}
__device__ __forceinline__ void mma8(float* d, const uint32_t* a, uint32_t b0, uint32_t b1) {
    asm volatile(
        "mma.sync.aligned.m16n8k8.row.col.f32.tf32.tf32.f32 "
        "{%0,%1,%2,%3},{%4,%5,%6,%7},{%8,%9},{%0,%1,%2,%3};"
        : "+f"(d[0]), "+f"(d[1]), "+f"(d[2]), "+f"(d[3])
        : "r"(a[0]), "r"(a[1]), "r"(a[2]), "r"(a[3]), "r"(b0), "r"(b1));
}
__device__ __forceinline__ void cpa16(uint32_t dst, const float* src) {
    asm volatile("cp.async.cg.shared.global [%0], [%1], 16;" :: "r"(dst), "l"(src));
}

__device__ __forceinline__ void gsync(unsigned& epoch) {
    epoch++;
    __syncthreads();
    __threadfence();
    const int bid = blockIdx.x, tid = threadIdx.x;
    if (bid == 0) {
        if (tid == 0) {
            atomicAdd(&g_ctr, 1u);
            const unsigned goal = epoch * gridDim.x;
            while (*((volatile unsigned*)&g_ctr) < goal) {}
            __threadfence();
        }
        __syncthreads();
        for (int i = tid; i < (int)gridDim.x; i += blockDim.x)
            *((volatile unsigned*)&g_rel[i * 32]) = epoch;
        __syncthreads();
    } else {
        if (tid == 0) {
            atomicAdd(&g_ctr, 1u);
            volatile unsigned* my = &g_rel[bid * 32];
            while (*my < epoch) {}
            __threadfence();
        }
        __syncthreads();
    }
}

__global__ void split_tf32(const float* __restrict__ src,
                           float* __restrict__ hi, float* __restrict__ lo, int n)
{
    int i = blockIdx.x * 256 + threadIdx.x;
    if (i < n) {
        float v = src[i];
        float h = tf32_hi(v);
        hi[i] = h;
        lo[i] = v - h;
    }
}

// ---------------------------------------------------------------------------
// Phase 1a (unchanged)
// ---------------------------------------------------------------------------
__global__ void __launch_bounds__(256) phase1a_kernel(
    const float* __restrict__ y,
    const float* __restrict__ Wih, const float* __restrict__ Whh,
    const float* __restrict__ bih, const float* __restrict__ bhh,
    float* __restrict__ Z)
{
    const int b = blockIdx.x, tid = threadIdx.x;
    __shared__ float sz[LAT];
    __shared__ float sy[OBS];

    sz[tid] = 0.0f;
    __stcg(Z + (size_t)b * LAT + tid, 0.0f);
    float bsum = __ldg(bih + tid) + __ldg(bhh + tid);

    float4 wi[8];
    const float4* wip = (const float4*)(Wih + (size_t)tid * OBS);
#pragma unroll
    for (int k = 0; k < 8; k++) wi[k] = __ldg(wip + k);
    const float4* wh = (const float4*)(Whh + (size_t)tid * LAT);
    __syncthreads();

    for (int t = 0; t < TSTEPS; t++) {
        if (tid < OBS) sy[tid] = __ldg(y + ((size_t)b * TSTEPS + t) * OBS + tid);
        __syncthreads();
        float acc = bsum;
#pragma unroll
        for (int k = 0; k < 8; k++) {
            float4 w = wi[k];
            acc += sy[k*4+0]*w.x + sy[k*4+1]*w.y + sy[k*4+2]*w.z + sy[k*4+3]*w.w;
        }
#pragma unroll 8
        for (int k = 0; k < 64; k++) {
            float4 w = __ldg(wh + k);
            acc += sz[k*4+0]*w.x + sz[k*4+1]*w.y + sz[k*4+2]*w.z + sz[k*4+3]*w.w;
        }
        float zn = tanhf(acc);
        __syncthreads();
        sz[tid] = zn;
        __stcg(Z + ((size_t)t + 1) * ZSTRIDE + (size_t)b * LAT + tid, zn);
    }
}

// ---------------------------------------------------------------------------
// Phase 1b GEMMs (unchanged fp32 SIMT)
// ---------------------------------------------------------------------------
template<int ACT>
__global__ void __launch_bounds__(256, 2) gemm_big(
    const float* __restrict__ X, int ldx,
    const float* __restrict__ W, int ldw,
    const float* __restrict__ bias,
    float* __restrict__ Y, int ldy, int K)
{
    __shared__ __align__(16) float sX[16 * 132];
    __shared__ __align__(16) float sW[16 * 132];
    const int tid = threadIdx.x;
    const int ty = tid >> 4, tx = tid & 15;
    const int mB = blockIdx.y * 128, nB = blockIdx.x * 128;
    const int xr = tid >> 2, xc = tid & 3;

    const float* Xp0 = X + (size_t)(mB + xr) * ldx + xc * 4;
    const float* Xp1 = Xp0 + (size_t)64 * ldx;
    const float* Wp0 = W + (size_t)(nB + xr) * ldw + xc * 4;
    const float* Wp1 = Wp0 + (size_t)64 * ldw;

    float4 xv0 = __ldg((const float4*)Xp0);
    float4 xv1 = __ldg((const float4*)Xp1);
    float4 wv0 = __ldg((const float4*)Wp0);
    float4 wv1 = __ldg((const float4*)Wp1);

    u64 acc[4][8];
#pragma unroll
    for (int i = 0; i < 4; i++)
#pragma unroll
        for (int j = 0; j < 8; j++) acc[i][j] = 0ull;

    for (int k0 = 0;;) {
        sX[(xc*4+0)*132 + xr] = xv0.x; sX[(xc*4+1)*132 + xr] = xv0.y;
        sX[(xc*4+2)*132 + xr] = xv0.z; sX[(xc*4+3)*132 + xr] = xv0.w;
        sX[(xc*4+0)*132 + xr+64] = xv1.x; sX[(xc*4+1)*132 + xr+64] = xv1.y;
        sX[(xc*4+2)*132 + xr+64] = xv1.z; sX[(xc*4+3)*132 + xr+64] = xv1.w;
        sW[(xc*4+0)*132 + xr] = wv0.x; sW[(xc*4+1)*132 + xr] = wv0.y;
        sW[(xc*4+2)*132 + xr] = wv0.z; sW[(xc*4+3)*132 + xr] = wv0.w;
        sW[(xc*4+0)*132 + xr+64] = wv1.x; sW[(xc*4+1)*132 + xr+64] = wv1.y;
        sW[(xc*4+2)*132 + xr+64] = wv1.z; sW[(xc*4+3)*132 + xr+64] = wv1.w;
        __syncthreads();

        const int k1 = k0 + 16;
        if (k1 < K) {
            xv0 = __ldg((const float4*)(Xp0 + k1));
            xv1 = __ldg((const float4*)(Xp1 + k1));
            wv0 = __ldg((const float4*)(Wp0 + k1));
            wv1 = __ldg((const float4*)(Wp1 + k1));
        }
#pragma unroll
        for (int kk = 0; kk < 16; kk++) {
            ulonglong2 aA = *(const ulonglong2*)&sX[kk*132 + ty*8];
            ulonglong2 aB = *(const ulonglong2*)&sX[kk*132 + ty*8 + 4];
            float4 b0 = *(const float4*)&sW[kk*132 + tx*8];
            float4 b1 = *(const float4*)&sW[kk*132 + tx*8 + 4];
            u64 bd[8];
            bd[0]=f2dup(b0.x); bd[1]=f2dup(b0.y); bd[2]=f2dup(b0.z); bd[3]=f2dup(b0.w);
            bd[4]=f2dup(b1.x); bd[5]=f2dup(b1.y); bd[6]=f2dup(b1.z); bd[7]=f2dup(b1.w);
#pragma unroll
            for (int j = 0; j < 8; j++) {
                f2fma(acc[0][j], aA.x, bd[j]);
                f2fma(acc[1][j], aA.y, bd[j]);
                f2fma(acc[2][j], aB.x, bd[j]);
                f2fma(acc[3][j], aB.y, bd[j]);
            }
        }
        __syncthreads();
        if (k1 >= K) break;
        k0 = k1;
    }

    float4 bb0 = __ldg((const float4*)(bias + nB + tx * 8));
    float4 bb1 = __ldg((const float4*)(bias + nB + tx * 8 + 4));
#pragma unroll
    for (int mp = 0; mp < 4; mp++) {
        float2 u[8];
#pragma unroll
        for (int j = 0; j < 8; j++) u[j] = f2unpack(acc[mp][j]);
        float4 r0a = make_float4(u[0].x+bb0.x, u[1].x+bb0.y, u[2].x+bb0.z, u[3].x+bb0.w);
        float4 r0b = make_float4(u[4].x+bb1.x, u[5].x+bb1.y, u[6].x+bb1.z, u[7].x+bb1.w);
        float4 r1a = make_float4(u[0].y+bb0.x, u[1].y+bb0.y, u[2].y+bb0.z, u[3].y+bb0.w);
        float4 r1b = make_float4(u[4].y+bb1.x, u[5].y+bb1.y, u[6].y+bb1.z, u[7].y+bb1.w);
        if (ACT) {
            r0a.x=fmaxf(r0a.x,0.f); r0a.y=fmaxf(r0a.y,0.f); r0a.z=fmaxf(r0a.z,0.f); r0a.w=fmaxf(r0a.w,0.f);
            r0b.x=fmaxf(r0b.x,0.f); r0b.y=fmaxf(r0b.y,0.f); r0b.z=fmaxf(r0b.z,0.f); r0b.w=fmaxf(r0b.w,0.f);
            r1a.x=fmaxf(r1a.x,0.f); r1a.y=fmaxf(r1a.y,0.f); r1a.z=fmaxf(r1a.z,0.f); r1a.w=fmaxf(r1a.w,0.f);
            r1b.x=fmaxf(r1b.x,0.f); r1b.y=fmaxf(r1b.y,0.f); r1b.z=fmaxf(r1b.z,0.f); r1b.w=fmaxf(r1b.w,0.f);
        }
        const int row0 = mB + ty * 8 + mp * 2;
        float* y0 = Y + (size_t)row0 * ldy + nB + tx * 8;
        float* y1 = y0 + ldy;
        *(float4*)y0 = r0a; *(float4*)(y0 + 4) = r0b;
        *(float4*)y1 = r1a; *(float4*)(y1 + 4) = r1b;
    }
}

__global__ void __launch_bounds__(256) gemm_out(
    const float* __restrict__ X, int ldx,
    const float* __restrict__ W, int ldw,
    const float* __restrict__ bias,
    float* __restrict__ out, int K, int t0)
{
    __shared__ __align__(16) float sX[16 * 132];
    __shared__ __align__(16) float sW[16 * 36];
    const int tid = threadIdx.x;
    const int ty = tid >> 4, tx = tid & 15;
    const int mB = blockIdx.y * 128;
    const int xr = tid >> 2, xc = tid & 3;

    const float* Xp0 = X + (size_t)(mB + xr) * ldx + xc * 4;
    const float* Xp1 = Xp0 + (size_t)64 * ldx;
    const bool wp = tid < 128;
    const float* Wp = W + (size_t)xr * ldw + xc * 4;

    float4 xv0 = __ldg((const float4*)Xp0);
    float4 xv1 = __ldg((const float4*)Xp1);
    float4 wv = make_float4(0,0,0,0);
    if (wp) wv = __ldg((const float4*)Wp);

    float acc[8][2];
#pragma unroll
    for (int i = 0; i < 8; i++) { acc[i][0] = 0.f; acc[i][1] = 0.f; }

    for (int k0 = 0;;) {
        sX[(xc*4+0)*132 + xr] = xv0.x; sX[(xc*4+1)*132 + xr] = xv0.y;
        sX[(xc*4+2)*132 + xr] = xv0.z; sX[(xc*4+3)*132 + xr] = xv0.w;
        sX[(xc*4+0)*132 + xr+64] = xv1.x; sX[(xc*4+1)*132 + xr+64] = xv1.y;
        sX[(xc*4+2)*132 + xr+64] = xv1.z; sX[(xc*4+3)*132 + xr+64] = xv1.w;
        if (wp) {
            sW[(xc*4+0)*36 + xr] = wv.x; sW[(xc*4+1)*36 + xr] = wv.y;
            sW[(xc*4+2)*36 + xr] = wv.z; sW[(xc*4+3)*36 + xr] = wv.w;
        }
        __syncthreads();
        const int k1 = k0 + 16;
        if (k1 < K) {
            xv0 = __ldg((const float4*)(Xp0 + k1));
            xv1 = __ldg((const float4*)(Xp1 + k1));
            if (wp) wv = __ldg((const float4*)(Wp + k1));
        }
#pragma unroll
        for (int kk = 0; kk < 16; kk++) {
            float4 a0 = *(const float4*)&sX[kk*132 + ty*8];
            float4 a1 = *(const float4*)&sX[kk*132 + ty*8 + 4];
            float2 b  = *(const float2*)&sW[kk*36 + tx*2];
            acc[0][0]+=a0.x*b.x; acc[0][1]+=a0.x*b.y;
            acc[1][0]+=a0.y*b.x; acc[1][1]+=a0.y*b.y;
            acc[2][0]+=a0.z*b.x; acc[2][1]+=a0.z*b.y;
            acc[3][0]+=a0.w*b.x; acc[3][1]+=a0.w*b.y;
            acc[4][0]+=a1.x*b.x; acc[4][1]+=a1.x*b.y;
            acc[5][0]+=a1.y*b.x; acc[5][1]+=a1.y*b.y;
            acc[6][0]+=a1.z*b.x; acc[6][1]+=a1.z*b.y;
            acc[7][0]+=a1.w*b.x; acc[7][1]+=a1.w*b.y;
        }
        __syncthreads();
        if (k1 >= K) break;
        k0 = k1;
    }

    float2 bb = *(const float2*)(bias + tx * 2);
#pragma unroll
    for (int i = 0; i < 8; i++) {
        int r = mB + ty * 8 + i;
        int b = r & (BATCH - 1);
        int t = t0 + (r >> 7);
        float2 v = make_float2(acc[i][0] + bb.x, acc[i][1] + bb.y);
        *(float2*)(out + ((size_t)b * HORIZON + t) * OBS + tx * 2) = v;
    }
}

// ---------------------------------------------------------------------------
// Phase-2 3xTF32 MMA tile: 16m x 64n, 256 threads (8 warps x n8).
// Stage layout (floats): XH 0, XL 576, WH 1152, WL 3456; stage size 5760.
// ---------------------------------------------------------------------------
template<bool RELU, bool HILO>
__device__ void mma_tile(
    float* SM, uint32_t sbase,
    int mB, int nT, int K,
    const float* __restrict__ Xh, const float* __restrict__ Xl, int ldx,
    const float* __restrict__ Wh_, const float* __restrict__ Wl_, int ldw,
    const float* __restrict__ bias,
    float* __restrict__ Yh, float* __restrict__ Yl, int ldy)
{
    const int tid = threadIdx.x;
    const int lane = tid & 31, w = tid >> 5;
    const int nchunks = K >> 5;

    float hh[4] = {0,0,0,0}, hl[4] = {0,0,0,0}, lh[4] = {0,0,0,0};

    auto issue = [&](int c, int s) {
        const int k0 = c << 5;
        const uint32_t sb = sbase + (uint32_t)s * 5760u * 4u;
        if (tid < 128) {
            int row = tid >> 3, cc = (tid & 7) << 2;
            uint32_t off = (uint32_t)(row * 36 + cc) * 4u;
            cpa16(sb + off,           Xh + (size_t)(mB + row) * ldx + k0 + cc);
            cpa16(sb + 576u*4u + off, Xl + (size_t)(mB + row) * ldx + k0 + cc);
        }
#pragma unroll
        for (int j = 0; j < 2; j++) {
            int cid = tid * 2 + j;
            int row = cid >> 3, cc = (cid & 7) << 2;
            uint32_t off = (uint32_t)(row * 36 + cc) * 4u;
            cpa16(sb + 1152u*4u + off, Wh_ + (size_t)(nT + row) * ldw + k0 + cc);
            cpa16(sb + 3456u*4u + off, Wl_ + (size_t)(nT + row) * ldw + k0 + cc);
        }
        asm volatile("cp.async.commit_group;" ::: "memory");
    };

    issue(0, 0);
    if (nchunks > 1) issue(1, 1);

    const int ar = lane >> 2, ac = lane & 3;
    const int brow = w * 8 + (lane >> 2);
    const int bk = lane & 3;

    for (int c = 0; c < nchunks; c++) {
        if (c == nchunks - 1) asm volatile("cp.async.wait_group 0;" ::: "memory");
        else                  asm volatile("cp.async.wait_group 1;" ::: "memory");
        __syncthreads();
        const float* S  = SM + (c & 1) * 5760;
        const float* XH = S;
        const float* XL = S + 576;
        const float* WHs = S + 1152;
        const float* WLs = S + 3456;
#pragma unroll
        for (int k8 = 0; k8 < 32; k8 += 8) {
            uint32_t ah[4], al[4];
            ah[0] = __float_as_uint(XH[ar*36 + k8 + ac]);
            ah[1] = __float_as_uint(XH[(ar+8)*36 + k8 + ac]);
            ah[2] = __float_as_uint(XH[ar*36 + k8 + ac + 4]);
            ah[3] = __float_as_uint(XH[(ar+8)*36 + k8 + ac + 4]);
            al[0] = __float_as_uint(XL[ar*36 + k8 + ac]);
            al[1] = __float_as_uint(XL[(ar+8)*36 + k8 + ac]);
            al[2] = __float_as_uint(XL[ar*36 + k8 + ac + 4]);
            al[3] = __float_as_uint(XL[(ar+8)*36 + k8 + ac + 4]);
            uint32_t bh0 = __float_as_uint(WHs[brow*36 + k8 + bk]);
            uint32_t bh1 = __float_as_uint(WHs[brow*36 + k8 + bk + 4]);
            uint32_t bl0 = __float_as_uint(WLs[brow*36 + k8 + bk]);
            uint32_t bl1 = __float_as_uint(WLs[brow*36 + k8 + bk + 4]);
            mma8(hh, ah, bh0, bh1);
            mma8(hl, ah, bl0, bl1);
            mma8(lh, al, bh0, bh1);
        }
        __syncthreads();
        if (c + 2 < nchunks) issue(c + 2, c & 1);
    }

    const int col = nT + w * 8 + ((lane & 3) << 1);
    float2 bb = make_float2(0.f, 0.f);
    if (bias) bb = *(const float2*)(bias + col);
    float d0 = hh[0] + hl[0] + lh[0] + bb.x;
    float d1 = hh[1] + hl[1] + lh[1] + bb.y;
    float d2 = hh[2] + hl[2] + lh[2] + bb.x;
    float d3 = hh[3] + hl[3] + lh[3] + bb.y;
    if (RELU) {
        d0 = fmaxf(d0, 0.f); d1 = fmaxf(d1, 0.f);
        d2 = fmaxf(d2, 0.f); d3 = fmaxf(d3, 0.f);
    }
    const int r0 = mB + (lane >> 2), r1 = r0 + 8;
    if (HILO) {
        float h0 = tf32_hi(d0), h1 = tf32_hi(d1), h2 = tf32_hi(d2), h3 = tf32_hi(d3);
        __stcg((float2*)(Yh + (size_t)r0 * ldy + col), make_float2(h0, h1));
        __stcg((float2*)(Yl + (size_t)r0 * ldy + col), make_float2(d0 - h0, d1 - h1));
        __stcg((float2*)(Yh + (size_t)r1 * ldy + col), make_float2(h2, h3));
        __stcg((float2*)(Yl + (size_t)r1 * ldy + col), make_float2(d2 - h2, d3 - h3));
    } else {
        __stcg((float2*)(Yh + (size_t)r0 * ldy + col), make_float2(d0, d1));
        __stcg((float2*)(Yh + (size_t)r1 * ldy + col), make_float2(d2, d3));
    }
}

// ---------------------------------------------------------------------------
// Phase 2: persistent AR rollout. 136 CTAs x 256 thr, 5 barriers/step.
// ---------------------------------------------------------------------------
__global__ void __launch_bounds__(256, 1) phase2_kernel(
    const float* __restrict__ b1, const float* __restrict__ b2,
    const float* __restrict__ b3, const float* __restrict__ b4,
    const float* __restrict__ W5, const float* __restrict__ b5,
    const float* __restrict__ Wih,
    const float* __restrict__ bih, const float* __restrict__ bhh,
    float* __restrict__ Z, float* __restrict__ SCR,
    float* __restrict__ out)
{
    __shared__ __align__(16) float SM[2 * 5760];
    const uint32_t sbase = (uint32_t)__cvta_generic_to_shared(SM);
    unsigned epoch = 0;
    const int bid = blockIdx.x;
    const int tid = threadIdx.x;

    float* AH = SCR + P2_AH;  float* AL = SCR + P2_AL;
    float* BH = SCR + P2_BH;  float* BL = SCR + P2_BL;
    float* ZH = SCR + P2_ZH;  float* ZL = SCR + P2_ZL;
    float* C  = SCR + P2_C;

    const float* W1H = g_WH + OFF_W1;  const float* W1L = g_WL + OFF_W1;
    const float* W2H = g_WH + OFF_W2;  const float* W2L = g_WL + OFF_W2;
    const float* W3H = g_WH + OFF_W3;  const float* W3L = g_WL + OFF_W3;
    const float* W4H = g_WH + OFF_W4;  const float* W4L = g_WL + OFF_W4;
    const float* WHH = g_WH + OFF_WHH; const float* WHL = g_WL + OFF_WHH;

    {
        int idx = bid * 256 + tid;
        if (idx < BATCH * LAT) {
            float z = __ldcg(Z + (size_t)TSTEPS * ZSTRIDE + idx);
            float zh = tf32_hi(z);
            __stcg(ZH + idx, zh);
            __stcg(ZL + idx, z - zh);
        }
        gsync(epoch);
    }

    const int mT = (bid >> 4) * 16;
    const int nTt = (bid & 15) * 64;

    for (int t = TSTEPS; t < HORIZON; t++) {
        if (bid < 128) {
            mma_tile<true, true>(SM, sbase, mT, nTt, LAT,
                                 ZH, ZL, LAT, W1H, W1L, LAT, b1, AH, AL, HID);
        } else {
            int wt = bid - 128;
            mma_tile<false, false>(SM, sbase, (wt >> 2) * 16, (wt & 3) * 64, LAT,
                                   ZH, ZL, LAT, WHH, WHL, LAT,
                                   (const float*)0, C, (float*)0, LAT);
        }
        gsync(epoch);

        if (bid < 128) {
            mma_tile<true, true>(SM, sbase, mT, nTt, HID,
                                 AH, AL, HID, W2H, W2L, HID, b2, BH, BL, HID);
        } else {
            int wt = (bid - 128) + 8;
            mma_tile<false, false>(SM, sbase, (wt >> 2) * 16, (wt & 3) * 64, LAT,
                                   ZH, ZL, LAT, WHH, WHL, LAT,
                                   (const float*)0, C, (float*)0, LAT);
        }
        gsync(epoch);

        if (bid < 128) {
            mma_tile<true, true>(SM, sbase, mT, nTt, HID,
                                 BH, BL, HID, W3H, W3L, HID, b3, AH, AL, HID);
        } else {
            int wt = (bid - 128) + 16;
            mma_tile<false, false>(SM, sbase, (wt >> 2) * 16, (wt & 3) * 64, LAT,
                                   ZH, ZL, LAT, WHH, WHL, LAT,
                                   (const float*)0, C, (float*)0, LAT);
        }
        gsync(epoch);

        if (bid < 128) {
            mma_tile<true, true>(SM, sbase, mT, nTt, HID,
                                 AH, AL, HID, W4H, W4L, HID, b4, BH, BL, HID);
        } else {
            int wt = (bid - 128) + 24;
            mma_tile<false, false>(SM, sbase, (wt >> 2) * 16, (wt & 3) * 64, LAT,
                                   ZH, ZL, LAT, WHH, WHL, LAT,
                                   (const float*)0, C, (float*)0, LAT);
        }
        gsync(epoch);

        // R5: per-batch-row fused L5 + out + cell finish
        if (bid < 128) {
            const int b = bid;
            {
                const float4* ph = (const float4*)(BH + (size_t)b * HID);
                const float4* pl = (const float4*)(BL + (size_t)b * HID);
                float4 h = __ldcg(ph + tid), l = __ldcg(pl + tid);
                ((float4*)SM)[tid] = make_float4(h.x+l.x, h.y+l.y, h.z+l.z, h.w+l.w);
            }
            __syncthreads();
            {
                const int n = tid >> 3, q = tid & 7;
                const float4* w5 = (const float4*)(W5 + (size_t)n * HID) + q * 32;
                const float4* xb = (const float4*)SM + q * 32;
                float s = 0.f;
#pragma unroll 8
                for (int k = 0; k < 32; k++) {
                    float4 wv = __ldg(w5 + k);
                    float4 xv = xb[k];
                    s += xv.x*wv.x + xv.y*wv.y + xv.z*wv.z + xv.w*wv.w;
                }
                SM[1024 + tid] = s;
            }
            __syncthreads();
            if (tid < OBS) {
                float yh = __ldg(b5 + tid);
#pragma unroll
                for (int q = 0; q < 8; q++) yh += SM[1024 + tid * 8 + q];
                __stcg(out + ((size_t)b * HORIZON + t) * OBS + tid, yh);
                SM[1280 + tid] = yh;
            }
            __syncthreads();
            if (t < HORIZON - 1) {
                const int n = tid;
                float acc = __ldcg(C + (size_t)b * LAT + n)
                          + __ldg(bih + n) + __ldg(bhh + n);
                const float4* wr = (const float4*)(Wih + (size_t)n * OBS);
#pragma unroll
                for (int k = 0; k < 8; k++) {
                    float4 wv = __ldg(wr + k);
                    acc += SM[1280+k*4+0]*wv.x + SM[1280+k*4+1]*wv.y
                         + SM[1280+k*4+2]*wv.z + SM[1280+k*4+3]*wv.w;
                }
                float z = tanhf(acc);
                float zh = tf32_hi(z);
                __stcg(ZH + (size_t)b * LAT + n, zh);
                __stcg(ZL + (size_t)b * LAT + n, z - zh);
            }
        }
        gsync(epoch);
    }
}

// ---------------------------------------------------------------------------
// Launch
// ---------------------------------------------------------------------------
extern "C" void kernel_launch(void* const* d_in, const int* in_sizes, int n_in,
                              void* d_out, int out_size)
{
    const float* y   = (const float*)d_in[0];
    const float* Wih = (const float*)d_in[2];
    const float* Whh = (const float*)d_in[3];
    const float* bih = (const float*)d_in[4];
    const float* bhh = (const float*)d_in[5];
    const float* W1  = (const float*)d_in[6];
    const float* b1  = (const float*)d_in[7];
    const float* W2  = (const float*)d_in[8];
    const float* b2  = (const float*)d_in[9];
    const float* W3  = (const float*)d_in[10];
    const float* b3  = (const float*)d_in[11];
    const float* W4  = (const float*)d_in[12];
    const float* b4  = (const float*)d_in[13];
    const float* W5  = (const float*)d_in[14];
    const float* b5  = (const float*)d_in[15];
    float* out = (float*)d_out;

    float *Z, *A, *Bf, *WH, *WL;
    unsigned *ctr, *rel;
    cudaGetSymbolAddress((void**)&Z,   g_Z);
    cudaGetSymbolAddress((void**)&A,   g_A);
    cudaGetSymbolAddress((void**)&Bf,  g_B);
    cudaGetSymbolAddress((void**)&WH,  g_WH);
    cudaGetSymbolAddress((void**)&WL,  g_WL);
    cudaGetSymbolAddress((void**)&ctr, g_ctr);
    cudaGetSymbolAddress((void**)&rel, g_rel);

    // weight hi/lo prepass
    split_tf32<<<(262144 + 255)/256, 256>>>(W1,  WH + OFF_W1,  WL + OFF_W1,  262144);
    split_tf32<<<(1048576 + 255)/256, 256>>>(W2, WH + OFF_W2,  WL + OFF_W2,  1048576);
    split_tf32<<<(1048576 + 255)/256, 256>>>(W3, WH + OFF_W3,  WL + OFF_W3,  1048576);
    split_tf32<<<(1048576 + 255)/256, 256>>>(W4, WH + OFF_W4,  WL + OFF_W4,  1048576);
    split_tf32<<<(65536 + 255)/256, 256>>>(Whh, WH + OFF_WHH, WL + OFF_WHH, 65536);

    // Phase 1a
    phase1a_kernel<<<BATCH, 256>>>(y, Wih, Whh, bih, bhh, Z);

    // Phase 1b: 2 chunks of 128 steps (fp32 SIMT)
    const int CHUNK = 128;
    const int MBIG  = CHUNK * BATCH;
    for (int c = 0; c < TSTEPS / CHUNK; c++) {
        const float* Xz = Z + (size_t)c * CHUNK * ZSTRIDE;
        gemm_big<1><<<dim3(HID/128, MBIG/128), 256>>>(Xz, LAT, W1, LAT, b1, A, HID, LAT);
        gemm_big<1><<<dim3(HID/128, MBIG/128), 256>>>(A, HID, W2, HID, b2, Bf, HID, HID);
        gemm_big<1><<<dim3(HID/128, MBIG/128), 256>>>(Bf, HID, W3, HID, b3, A, HID, HID);
        gemm_big<1><<<dim3(HID/128, MBIG/128), 256>>>(A, HID, W4, HID, b4, Bf, HID, HID);
        gemm_out<<<dim3(1, MBIG/128), 256>>>(Bf, HID, W5, HID, b5, out, HID, c * CHUNK);
    }

    // Phase 2: reset barrier state, persistent tensor-core rollout
    cudaMemsetAsync(ctr, 0, sizeof(unsigned));
    cudaMemsetAsync(rel, 0, sizeof(unsigned) * NB2 * 32);
    phase2_kernel<<<NB2, 256>>>(b1, b2, b3, b4, W5, b5, Wih, bih, bhh,
                                Z, A, out);
}

// round 9
// speedup vs baseline: 1.6077x; 1.4941x over previous
#include <cuda_runtime.h>
#include <cuda_bf16.h>
#include <math.h>
#include <stdint.h>

#define BATCH   128
#define TSTEPS  256
#define HORIZON 512
#define OBS     32
#define LAT     256
#define HID     1024
#define ZSTRIDE (BATCH * LAT)

typedef __nv_bfloat16 bf16;
typedef unsigned long long u64;

// ---------------------------------------------------------------------------
// Scratch
// ---------------------------------------------------------------------------
__device__ float g_Z[(size_t)(HORIZON + 1) * ZSTRIDE];
__device__ float g_A[(size_t)128 * BATCH * HID];   // 1b acts; phase2 planes carve
__device__ float g_B[(size_t)128 * BATCH * HID];
__device__ bf16  g_WHB[3473408];                   // bf16 hi planes: W1,W2,W3,W4,Whh
__device__ bf16  g_WLB[3473408];                   // bf16 lo planes
__device__ unsigned g_gbar[4 * 32];                // per-group barrier counters

#define OFF_W1  0
#define OFF_W2  262144
#define OFF_W3  1310720
#define OFF_W4  2359296
#define OFF_WHH 3407872

// ---------------------------------------------------------------------------
// helpers
// ---------------------------------------------------------------------------
__device__ __forceinline__ u64 f2dup(float s) {
    u64 r; asm("mov.b64 %0, {%1, %1};" : "=l"(r) : "f"(s)); return r;
}
__device__ __forceinline__ void f2fma(u64& d, u64 a, u64 b) {
    asm("fma.rn.f32x2 %0, %1, %2, %0;" : "+l"(d) : "l"(a), "l"(b));
}
__device__ __forceinline__ float2 f2unpack(u64 v) {
    float2 r; asm("mov.b64 {%0, %1}, %2;" : "=f"(r.x), "=f"(r.y) : "l"(v)); return r;
}
__device__ __forceinline__ void mma16(float* d, const uint32_t* a, uint32_t b0, uint32_t b1) {
    asm volatile(
        "mma.sync.aligned.m16n8k16.row.col.f32.bf16.bf16.f32 "
        "{%0,%1,%2,%3},{%4,%5,%6,%7},{%8,%9},{%0,%1,%2,%3};"
        : "+f"(d[0]), "+f"(d[1]), "+f"(d[2]), "+f"(d[3])
        : "r"(a[0]), "r"(a[1]), "r"(a[2]), "r"(a[3]), "r"(b0), "r"(b1));
}
__device__ __forceinline__ void cpa16(uint32_t dst, const void* src) {
    asm volatile("cp.async.cg.shared.global [%0], [%1], 16;" :: "r"(dst), "l"(src));
}
__device__ __forceinline__ void split_pack(float v0, float v1, uint32_t& hw, uint32_t& lw) {
    bf16 h0 = __float2bfloat16(v0);
    bf16 h1 = __float2bfloat16(v1);
    bf16 l0 = __float2bfloat16(v0 - __bfloat162float(h0));
    bf16 l1 = __float2bfloat16(v1 - __bfloat162float(h1));
    hw = ((uint32_t)__bfloat16_as_ushort(h1) << 16) | __bfloat16_as_ushort(h0);
    lw = ((uint32_t)__bfloat16_as_ushort(l1) << 16) | __bfloat16_as_ushort(l0);
}

// group barrier: 32 CTAs per group, counter per group on its own 128B line
__device__ __forceinline__ void ggsync(int g, unsigned& target) {
    target += 32;
    __syncthreads();
    __threadfence();
    if (threadIdx.x == 0) {
        atomicAdd(&g_gbar[g * 32], 1u);
        while (*((volatile unsigned*)&g_gbar[g * 32]) < target) {}
        __threadfence();
    }
    __syncthreads();
}

// weight hi/lo bf16 split prepass
__global__ void splitw_bf16(const float* __restrict__ src,
                            bf16* __restrict__ hi, bf16* __restrict__ lo, int n)
{
    int i = blockIdx.x * 256 + threadIdx.x;
    if (i < n) {
        float v = src[i];
        bf16 h = __float2bfloat16(v);
        hi[i] = h;
        lo[i] = __float2bfloat16(v - __bfloat162float(h));
    }
}

// ---------------------------------------------------------------------------
// Phase 1a (unchanged): barrier-free recurrence, CTA b owns batch row b.
// ---------------------------------------------------------------------------
__global__ void __launch_bounds__(256) phase1a_kernel(
    const float* __restrict__ y,
    const float* __restrict__ Wih, const float* __restrict__ Whh,
    const float* __restrict__ bih, const float* __restrict__ bhh,
    float* __restrict__ Z)
{
    const int b = blockIdx.x, tid = threadIdx.x;
    __shared__ float sz[LAT];
    __shared__ float sy[OBS];

    sz[tid] = 0.0f;
    __stcg(Z + (size_t)b * LAT + tid, 0.0f);
    float bsum = __ldg(bih + tid) + __ldg(bhh + tid);

    float4 wi[8];
    const float4* wip = (const float4*)(Wih + (size_t)tid * OBS);
#pragma unroll
    for (int k = 0; k < 8; k++) wi[k] = __ldg(wip + k);
    const float4* wh = (const float4*)(Whh + (size_t)tid * LAT);
    __syncthreads();

    for (int t = 0; t < TSTEPS; t++) {
        if (tid < OBS) sy[tid] = __ldg(y + ((size_t)b * TSTEPS + t) * OBS + tid);
        __syncthreads();
        float acc = bsum;
#pragma unroll
        for (int k = 0; k < 8; k++) {
            float4 w = wi[k];
            acc += sy[k*4+0]*w.x + sy[k*4+1]*w.y + sy[k*4+2]*w.z + sy[k*4+3]*w.w;
        }
#pragma unroll 8
        for (int k = 0; k < 64; k++) {
            float4 w = __ldg(wh + k);
            acc += sz[k*4+0]*w.x + sz[k*4+1]*w.y + sz[k*4+2]*w.z + sz[k*4+3]*w.w;
        }
        float zn = tanhf(acc);
        __syncthreads();
        sz[tid] = zn;
        __stcg(Z + ((size_t)t + 1) * ZSTRIDE + (size_t)b * LAT + tid, zn);
    }
}

// ---------------------------------------------------------------------------
// Phase 1b GEMMs (unchanged fp32 SIMT)
// ---------------------------------------------------------------------------
template<int ACT>
__global__ void __launch_bounds__(256, 2) gemm_big(
    const float* __restrict__ X, int ldx,
    const float* __restrict__ W, int ldw,
    const float* __restrict__ bias,
    float* __restrict__ Y, int ldy, int K)
{
    __shared__ __align__(16) float sX[16 * 132];
    __shared__ __align__(16) float sW[16 * 132];
    const int tid = threadIdx.x;
    const int ty = tid >> 4, tx = tid & 15;
    const int mB = blockIdx.y * 128, nB = blockIdx.x * 128;
    const int xr = tid >> 2, xc = tid & 3;

    const float* Xp0 = X + (size_t)(mB + xr) * ldx + xc * 4;
    const float* Xp1 = Xp0 + (size_t)64 * ldx;
    const float* Wp0 = W + (size_t)(nB + xr) * ldw + xc * 4;
    const float* Wp1 = Wp0 + (size_t)64 * ldw;

    float4 xv0 = __ldg((const float4*)Xp0);
    float4 xv1 = __ldg((const float4*)Xp1);
    float4 wv0 = __ldg((const float4*)Wp0);
    float4 wv1 = __ldg((const float4*)Wp1);

    u64 acc[4][8];
#pragma unroll
    for (int i = 0; i < 4; i++)
#pragma unroll
        for (int j = 0; j < 8; j++) acc[i][j] = 0ull;

    for (int k0 = 0;;) {
        sX[(xc*4+0)*132 + xr] = xv0.x; sX[(xc*4+1)*132 + xr] = xv0.y;
        sX[(xc*4+2)*132 + xr] = xv0.z; sX[(xc*4+3)*132 + xr] = xv0.w;
        sX[(xc*4+0)*132 + xr+64] = xv1.x; sX[(xc*4+1)*132 + xr+64] = xv1.y;
        sX[(xc*4+2)*132 + xr+64] = xv1.z; sX[(xc*4+3)*132 + xr+64] = xv1.w;
        sW[(xc*4+0)*132 + xr] = wv0.x; sW[(xc*4+1)*132 + xr] = wv0.y;
        sW[(xc*4+2)*132 + xr] = wv0.z; sW[(xc*4+3)*132 + xr] = wv0.w;
        sW[(xc*4+0)*132 + xr+64] = wv1.x; sW[(xc*4+1)*132 + xr+64] = wv1.y;
        sW[(xc*4+2)*132 + xr+64] = wv1.z; sW[(xc*4+3)*132 + xr+64] = wv1.w;
        __syncthreads();

        const int k1 = k0 + 16;
        if (k1 < K) {
            xv0 = __ldg((const float4*)(Xp0 + k1));
            xv1 = __ldg((const float4*)(Xp1 + k1));
            wv0 = __ldg((const float4*)(Wp0 + k1));
            wv1 = __ldg((const float4*)(Wp1 + k1));
        }
#pragma unroll
        for (int kk = 0; kk < 16; kk++) {
            ulonglong2 aA = *(const ulonglong2*)&sX[kk*132 + ty*8];
            ulonglong2 aB = *(const ulonglong2*)&sX[kk*132 + ty*8 + 4];
            float4 b0 = *(const float4*)&sW[kk*132 + tx*8];
            float4 b1 = *(const float4*)&sW[kk*132 + tx*8 + 4];
            u64 bd[8];
            bd[0]=f2dup(b0.x); bd[1]=f2dup(b0.y); bd[2]=f2dup(b0.z); bd[3]=f2dup(b0.w);
            bd[4]=f2dup(b1.x); bd[5]=f2dup(b1.y); bd[6]=f2dup(b1.z); bd[7]=f2dup(b1.w);
#pragma unroll
            for (int j = 0; j < 8; j++) {
                f2fma(acc[0][j], aA.x, bd[j]);
                f2fma(acc[1][j], aA.y, bd[j]);
                f2fma(acc[2][j], aB.x, bd[j]);
                f2fma(acc[3][j], aB.y, bd[j]);
            }
        }
        __syncthreads();
        if (k1 >= K) break;
        k0 = k1;
    }

    float4 bb0 = __ldg((const float4*)(bias + nB + tx * 8));
    float4 bb1 = __ldg((const float4*)(bias + nB + tx * 8 + 4));
#pragma unroll
    for (int mp = 0; mp < 4; mp++) {
        float2 u[8];
#pragma unroll
        for (int j = 0; j < 8; j++) u[j] = f2unpack(acc[mp][j]);
        float4 r0a = make_float4(u[0].x+bb0.x, u[1].x+bb0.y, u[2].x+bb0.z, u[3].x+bb0.w);
        float4 r0b = make_float4(u[4].x+bb1.x, u[5].x+bb1.y, u[6].x+bb1.z, u[7].x+bb1.w);
        float4 r1a = make_float4(u[0].y+bb0.x, u[1].y+bb0.y, u[2].y+bb0.z, u[3].y+bb0.w);
        float4 r1b = make_float4(u[4].y+bb1.x, u[5].y+bb1.y, u[6].y+bb1.z, u[7].y+bb1.w);
        if (ACT) {
            r0a.x=fmaxf(r0a.x,0.f); r0a.y=fmaxf(r0a.y,0.f); r0a.z=fmaxf(r0a.z,0.f); r0a.w=fmaxf(r0a.w,0.f);
            r0b.x=fmaxf(r0b.x,0.f); r0b.y=fmaxf(r0b.y,0.f); r0b.z=fmaxf(r0b.z,0.f); r0b.w=fmaxf(r0b.w,0.f);
            r1a.x=fmaxf(r1a.x,0.f); r1a.y=fmaxf(r1a.y,0.f); r1a.z=fmaxf(r1a.z,0.f); r1a.w=fmaxf(r1a.w,0.f);
            r1b.x=fmaxf(r1b.x,0.f); r1b.y=fmaxf(r1b.y,0.f); r1b.z=fmaxf(r1b.z,0.f); r1b.w=fmaxf(r1b.w,0.f);
        }
        const int row0 = mB + ty * 8 + mp * 2;
        float* y0 = Y + (size_t)row0 * ldy + nB + tx * 8;
        float* y1 = y0 + ldy;
        *(float4*)y0 = r0a; *(float4*)(y0 + 4) = r0b;
        *(float4*)y1 = r1a; *(float4*)(y1 + 4) = r1b;
    }
}

__global__ void __launch_bounds__(256) gemm_out(
    const float* __restrict__ X, int ldx,
    const float* __restrict__ W, int ldw,
    const float* __restrict__ bias,
    float* __restrict__ out, int K, int t0)
{
    __shared__ __align__(16) float sX[16 * 132];
    __shared__ __align__(16) float sW[16 * 36];
    const int tid = threadIdx.x;
    const int ty = tid >> 4, tx = tid & 15;
    const int mB = blockIdx.y * 128;
    const int xr = tid >> 2, xc = tid & 3;

    const float* Xp0 = X + (size_t)(mB + xr) * ldx + xc * 4;
    const float* Xp1 = Xp0 + (size_t)64 * ldx;
    const bool wp = tid < 128;
    const float* Wp = W + (size_t)xr * ldw + xc * 4;

    float4 xv0 = __ldg((const float4*)Xp0);
    float4 xv1 = __ldg((const float4*)Xp1);
    float4 wv = make_float4(0,0,0,0);
    if (wp) wv = __ldg((const float4*)Wp);

    float acc[8][2];
#pragma unroll
    for (int i = 0; i < 8; i++) { acc[i][0] = 0.f; acc[i][1] = 0.f; }

    for (int k0 = 0;;) {
        sX[(xc*4+0)*132 + xr] = xv0.x; sX[(xc*4+1)*132 + xr] = xv0.y;
        sX[(xc*4+2)*132 + xr] = xv0.z; sX[(xc*4+3)*132 + xr] = xv0.w;
        sX[(xc*4+0)*132 + xr+64] = xv1.x; sX[(xc*4+1)*132 + xr+64] = xv1.y;
        sX[(xc*4+2)*132 + xr+64] = xv1.z; sX[(xc*4+3)*132 + xr+64] = xv1.w;
        if (wp) {
            sW[(xc*4+0)*36 + xr] = wv.x; sW[(xc*4+1)*36 + xr] = wv.y;
            sW[(xc*4+2)*36 + xr] = wv.z; sW[(xc*4+3)*36 + xr] = wv.w;
        }
        __syncthreads();
        const int k1 = k0 + 16;
        if (k1 < K) {
            xv0 = __ldg((const float4*)(Xp0 + k1));
            xv1 = __ldg((const float4*)(Xp1 + k1));
            if (wp) wv = __ldg((const float4*)(Wp + k1));
        }
#pragma unroll
        for (int kk = 0; kk < 16; kk++) {
            float4 a0 = *(const float4*)&sX[kk*132 + ty*8];
            float4 a1 = *(const float4*)&sX[kk*132 + ty*8 + 4];
            float2 b  = *(const float2*)&sW[kk*36 + tx*2];
            acc[0][0]+=a0.x*b.x; acc[0][1]+=a0.x*b.y;
            acc[1][0]+=a0.y*b.x; acc[1][1]+=a0.y*b.y;
            acc[2][0]+=a0.z*b.x; acc[2][1]+=a0.z*b.y;
            acc[3][0]+=a0.w*b.x; acc[3][1]+=a0.w*b.y;
            acc[4][0]+=a1.x*b.x; acc[4][1]+=a1.x*b.y;
            acc[5][0]+=a1.y*b.x; acc[5][1]+=a1.y*b.y;
            acc[6][0]+=a1.z*b.x; acc[6][1]+=a1.z*b.y;
            acc[7][0]+=a1.w*b.x; acc[7][1]+=a1.w*b.y;
        }
        __syncthreads();
        if (k1 >= K) break;
        k0 = k1;
    }

    float2 bb = *(const float2*)(bias + tx * 2);
#pragma unroll
    for (int i = 0; i < 8; i++) {
        int r = mB + ty * 8 + i;
        int b = r & (BATCH - 1);
        int t = t0 + (r >> 7);
        float2 v = make_float2(acc[i][0] + bb.x, acc[i][1] + bb.y);
        *(float2*)(out + ((size_t)b * HORIZON + t) * OBS + tx * 2) = v;
    }
}

// ---------------------------------------------------------------------------
// Phase-2 bf16-pair MMA region: 32m x 32n tile, 256 threads (8 warps 2m x 4n),
// K-chunk 64, cp.async double buffer. Stage layout (u32 words, stride 36/row):
//   XH 0, XL 1152, WH 2304, WL 3456, VH 4608, VL 4896; stage = 5184 words.
// acc accumulates hh+hl+lh directly. DOWHH: warps 0,4 also do z@Whh^T n8 strip.
// ---------------------------------------------------------------------------
template<bool RELU, bool DOWHH>
__device__ void mma_region(
    uint32_t* SW, uint32_t sbase,
    int mT, int nT, int K,
    const bf16* __restrict__ Xh, const bf16* __restrict__ Xl, int ldx,
    const bf16* __restrict__ Wh, const bf16* __restrict__ Wl, int ldw,
    const bf16* __restrict__ Vh, const bf16* __restrict__ Vl, int whCol0,
    const float* __restrict__ bias,
    bf16* __restrict__ Yh, bf16* __restrict__ Yl, int ldy,
    float* __restrict__ Cout)
{
    const int tid = threadIdx.x, lane = tid & 31, wid = tid >> 5;
    const int mw = wid >> 2, nw = wid & 3;
    const int nch = K >> 6;

    auto issue = [&](int c, int s) {
        const int k0 = c << 6;
        const uint32_t base = (uint32_t)s * 5184u;
#pragma unroll
        for (int ii = 0; ii < 4; ii++) {
            const int o = tid + ii * 256;
            const int p = o >> 8, q = o & 255, row = q >> 3, sg = q & 7;
            const uint32_t dw = base + (uint32_t)p * 1152u + row * 36u + sg * 4u;
            const bf16* src;
            if (p == 0)      src = Xh + (size_t)(mT + row) * ldx + k0 + sg * 8;
            else if (p == 1) src = Xl + (size_t)(mT + row) * ldx + k0 + sg * 8;
            else if (p == 2) src = Wh + (size_t)(nT + row) * ldw + k0 + sg * 8;
            else             src = Wl + (size_t)(nT + row) * ldw + k0 + sg * 8;
            cpa16(sbase + dw * 4u, src);
        }
        if (DOWHH && tid < 128) {
            const int p = tid >> 6, q = tid & 63, row = q >> 3, sg = q & 7;
            const uint32_t dw = base + 4608u + (uint32_t)p * 288u + row * 36u + sg * 4u;
            const bf16* src = (p ? Vl : Vh) + (size_t)(whCol0 + row) * 256 + k0 + sg * 8;
            cpa16(sbase + dw * 4u, src);
        }
        asm volatile("cp.async.commit_group;" ::: "memory");
    };

    float acc[4]  = {0, 0, 0, 0};
    float accW[4] = {0, 0, 0, 0};

    issue(0, 0);
    if (nch > 1) issue(1, 1);

    const int r0 = mw * 16 + (lane >> 2);
    const int wc = lane & 3;
    const int aoff0 = r0 * 36 + wc;
    const int aoff1 = (r0 + 8) * 36 + wc;
    const int boff = (nw * 8 + (lane >> 2)) * 36 + wc;
    const int voff = (lane >> 2) * 36 + wc;

    for (int c = 0; c < nch; c++) {
        if (c == nch - 1) asm volatile("cp.async.wait_group 0;" ::: "memory");
        else              asm volatile("cp.async.wait_group 1;" ::: "memory");
        __syncthreads();
        const uint32_t* S   = SW + (c & 1) * 5184;
        const uint32_t* XHs = S;
        const uint32_t* XLs = S + 1152;
        const uint32_t* WHs = S + 2304;
        const uint32_t* WLs = S + 3456;
        const uint32_t* VHs = S + 4608;
        const uint32_t* VLs = S + 4896;
#pragma unroll
        for (int wb = 0; wb < 32; wb += 8) {
            uint32_t ah[4], al[4];
            ah[0] = XHs[aoff0 + wb];     ah[1] = XHs[aoff1 + wb];
            ah[2] = XHs[aoff0 + wb + 4]; ah[3] = XHs[aoff1 + wb + 4];
            al[0] = XLs[aoff0 + wb];     al[1] = XLs[aoff1 + wb];
            al[2] = XLs[aoff0 + wb + 4]; al[3] = XLs[aoff1 + wb + 4];
            uint32_t bh0 = WHs[boff + wb], bh1 = WHs[boff + wb + 4];
            uint32_t bl0 = WLs[boff + wb], bl1 = WLs[boff + wb + 4];
            mma16(acc, ah, bh0, bh1);
            mma16(acc, ah, bl0, bl1);
            mma16(acc, al, bh0, bh1);
            if (DOWHH && nw == 0) {
                uint32_t vh0 = VHs[voff + wb], vh1 = VHs[voff + wb + 4];
                uint32_t vl0 = VLs[voff + wb], vl1 = VLs[voff + wb + 4];
                mma16(accW, ah, vh0, vh1);
                mma16(accW, ah, vl0, vl1);
                mma16(accW, al, vh0, vh1);
            }
        }
        __syncthreads();
        if (c + 2 < nch) issue(c + 2, c & 1);
    }

    // epilogue: bias + relu + bf16-pair split into Yh/Yl planes
    const int orow = mT + r0;
    const int ocol = nT + nw * 8 + wc * 2;
    float2 bb = *(const float2*)(bias + ocol);
    float v0 = acc[0] + bb.x, v1 = acc[1] + bb.y;
    float v2 = acc[2] + bb.x, v3 = acc[3] + bb.y;
    if (RELU) {
        v0 = fmaxf(v0, 0.f); v1 = fmaxf(v1, 0.f);
        v2 = fmaxf(v2, 0.f); v3 = fmaxf(v3, 0.f);
    }
    uint32_t hw, lw;
    split_pack(v0, v1, hw, lw);
    __stcg((uint32_t*)&Yh[(size_t)orow * ldy + ocol], hw);
    __stcg((uint32_t*)&Yl[(size_t)orow * ldy + ocol], lw);
    split_pack(v2, v3, hw, lw);
    __stcg((uint32_t*)&Yh[(size_t)(orow + 8) * ldy + ocol], hw);
    __stcg((uint32_t*)&Yl[(size_t)(orow + 8) * ldy + ocol], lw);

    if (DOWHH && nw == 0) {
        const int wcol = whCol0 + wc * 2;
        __stcg((float2*)&Cout[(size_t)orow * LAT + wcol], make_float2(accW[0], accW[1]));
        __stcg((float2*)&Cout[(size_t)(orow + 8) * LAT + wcol], make_float2(accW[2], accW[3]));
    }
}

// ---------------------------------------------------------------------------
// Phase 2: persistent AR rollout. 128 CTAs x 256 thr; 4 independent groups of
// 32 CTAs (group g owns batch rows [g*32, g*32+32)); 5 group barriers/step.
// ---------------------------------------------------------------------------
__global__ void __launch_bounds__(256, 1) phase2_kernel(
    const float* __restrict__ b1, const float* __restrict__ b2,
    const float* __restrict__ b3, const float* __restrict__ b4,
    const float* __restrict__ W5, const float* __restrict__ b5,
    const float* __restrict__ Wih,
    const float* __restrict__ bih, const float* __restrict__ bhh,
    const float* __restrict__ Z,
    float* __restrict__ PL,      // = g_A carve
    float* __restrict__ out)
{
    __shared__ __align__(16) uint32_t SW[2 * 5184];
    const uint32_t sbase = (uint32_t)__cvta_generic_to_shared(SW);
    const int bid = blockIdx.x, tid = threadIdx.x;
    const int g = bid >> 5, j = bid & 31;
    const int mT = g * 32, nT = j * 32;
    const int b = bid;                        // this CTA's batch row for R5
    unsigned target = 0;

    bf16* AH = (bf16*)(PL);
    bf16* AL = (bf16*)(PL + 65536);
    bf16* BH = (bf16*)(PL + 131072);
    bf16* BL = (bf16*)(PL + 196608);
    bf16* ZH = (bf16*)(PL + 262144);
    bf16* ZL = (bf16*)(PL + 278528);
    float* C = PL + 294912;

    const bf16 *W1H = g_WHB + OFF_W1,  *W1L = g_WLB + OFF_W1;
    const bf16 *W2H = g_WHB + OFF_W2,  *W2L = g_WLB + OFF_W2;
    const bf16 *W3H = g_WHB + OFF_W3,  *W3L = g_WLB + OFF_W3;
    const bf16 *W4H = g_WHB + OFF_W4,  *W4L = g_WLB + OFF_W4;
    const bf16 *VH  = g_WHB + OFF_WHH, *VL  = g_WLB + OFF_WHH;

    // init: split z_256 (this CTA's row) into ZH/ZL bf16 planes
    if (tid < 128) {
        float2 z2 = __ldcg((const float2*)(Z + (size_t)TSTEPS * ZSTRIDE + (size_t)b * LAT) + tid);
        uint32_t hw, lw;
        split_pack(z2.x, z2.y, hw, lw);
        __stcg((uint32_t*)(ZH + (size_t)b * LAT) + tid, hw);
        __stcg((uint32_t*)(ZL + (size_t)b * LAT) + tid, lw);
    }
    ggsync(g, target);

    for (int t = TSTEPS; t < HORIZON; t++) {
        // R1: L1 (K=256) + Whh strip -> AH/AL, C
        mma_region<true, true>(SW, sbase, mT, nT, LAT,
                               ZH, ZL, LAT, W1H, W1L, LAT,
                               VH, VL, j * 8, b1, AH, AL, HID, C);
        ggsync(g, target);
        // R2
        mma_region<true, false>(SW, sbase, mT, nT, HID,
                                AH, AL, HID, W2H, W2L, HID,
                                (const bf16*)0, (const bf16*)0, 0, b2, BH, BL, HID, (float*)0);
        ggsync(g, target);
        // R3
        mma_region<true, false>(SW, sbase, mT, nT, HID,
                                BH, BL, HID, W3H, W3L, HID,
                                (const bf16*)0, (const bf16*)0, 0, b3, AH, AL, HID, (float*)0);
        ggsync(g, target);
        // R4
        mma_region<true, false>(SW, sbase, mT, nT, HID,
                                AH, AL, HID, W4H, W4L, HID,
                                (const bf16*)0, (const bf16*)0, 0, b4, BH, BL, HID, (float*)0);
        ggsync(g, target);

        // R5: this CTA handles batch row b: h4 = BH+BL; yh = h4@W5^T + b5;
        //     write out; cell: z_{t+1} = tanh(C + yh@Wih^T + biases) -> ZH/ZL
        {
            float* FS = (float*)SW;
            const uint32_t* bhrow = (const uint32_t*)(BH + (size_t)b * HID);
            const uint32_t* blrow = (const uint32_t*)(BL + (size_t)b * HID);
            for (int i = tid; i < 512; i += 256) {
                uint32_t hwv = __ldcg(bhrow + i);
                uint32_t lwv = __ldcg(blrow + i);
                float h0 = __bfloat162float(__ushort_as_bfloat16((unsigned short)(hwv & 0xffff)));
                float h1 = __bfloat162float(__ushort_as_bfloat16((unsigned short)(hwv >> 16)));
                float l0 = __bfloat162float(__ushort_as_bfloat16((unsigned short)(lwv & 0xffff)));
                float l1 = __bfloat162float(__ushort_as_bfloat16((unsigned short)(lwv >> 16)));
                FS[2*i]   = h0 + l0;
                FS[2*i+1] = h1 + l1;
            }
            __syncthreads();
            {
                const int n = tid >> 3, q = tid & 7;
                const float4* w5 = (const float4*)(W5 + (size_t)n * HID) + q * 32;
                const float4* xb = (const float4*)FS + q * 32;
                float s = 0.f;
#pragma unroll 8
                for (int k = 0; k < 32; k++) {
                    float4 wv = __ldg(w5 + k);
                    float4 xv = xb[k];
                    s += xv.x*wv.x + xv.y*wv.y + xv.z*wv.z + xv.w*wv.w;
                }
                FS[1024 + tid] = s;
            }
            __syncthreads();
            if (tid < OBS) {
                float yh = __ldg(b5 + tid);
#pragma unroll
                for (int q = 0; q < 8; q++) yh += FS[1024 + tid * 8 + q];
                __stcg(out + ((size_t)b * HORIZON + t) * OBS + tid, yh);
                FS[1280 + tid] = yh;
            }
            __syncthreads();
            if (t < HORIZON - 1) {
                const int n = tid;
                float acc = __ldcg(C + (size_t)b * LAT + n)
                          + __ldg(bih + n) + __ldg(bhh + n);
                const float4* wr = (const float4*)(Wih + (size_t)n * OBS);
#pragma unroll
                for (int k = 0; k < 8; k++) {
                    float4 wv = __ldg(wr + k);
                    acc += FS[1280+k*4+0]*wv.x + FS[1280+k*4+1]*wv.y
                         + FS[1280+k*4+2]*wv.z + FS[1280+k*4+3]*wv.w;
                }
                FS[1536 + n] = tanhf(acc);
                __syncthreads();
                if (tid < 128) {
                    float z0 = FS[1536 + 2*tid], z1 = FS[1536 + 2*tid + 1];
                    uint32_t hw, lw;
                    split_pack(z0, z1, hw, lw);
                    __stcg((uint32_t*)(ZH + (size_t)b * LAT) + tid, hw);
                    __stcg((uint32_t*)(ZL + (size_t)b * LAT) + tid, lw);
                }
            }
        }
        ggsync(g, target);
    }
}

// ---------------------------------------------------------------------------
// Launch (~18 graph nodes)
// ---------------------------------------------------------------------------
extern "C" void kernel_launch(void* const* d_in, const int* in_sizes, int n_in,
                              void* d_out, int out_size)
{
    const float* y   = (const float*)d_in[0];
    const float* Wih = (const float*)d_in[2];
    const float* Whh = (const float*)d_in[3];
    const float* bih = (const float*)d_in[4];
    const float* bhh = (const float*)d_in[5];
    const float* W1  = (const float*)d_in[6];
    const float* b1  = (const float*)d_in[7];
    const float* W2  = (const float*)d_in[8];
    const float* b2  = (const float*)d_in[9];
    const float* W3  = (const float*)d_in[10];
    const float* b3  = (const float*)d_in[11];
    const float* W4  = (const float*)d_in[12];
    const float* b4  = (const float*)d_in[13];
    const float* W5  = (const float*)d_in[14];
    const float* b5  = (const float*)d_in[15];
    float* out = (float*)d_out;

    float *Z, *A, *Bf;
    bf16 *WHB, *WLB;
    unsigned* gbar;
    cudaGetSymbolAddress((void**)&Z,    g_Z);
    cudaGetSymbolAddress((void**)&A,    g_A);
    cudaGetSymbolAddress((void**)&Bf,   g_B);
    cudaGetSymbolAddress((void**)&WHB,  g_WHB);
    cudaGetSymbolAddress((void**)&WLB,  g_WLB);
    cudaGetSymbolAddress((void**)&gbar, g_gbar);

    // weight bf16 hi/lo prepass
    splitw_bf16<<<(262144 + 255)/256, 256>>>(W1,  WHB + OFF_W1,  WLB + OFF_W1,  262144);
    splitw_bf16<<<(1048576 + 255)/256, 256>>>(W2, WHB + OFF_W2,  WLB + OFF_W2,  1048576);
    splitw_bf16<<<(1048576 + 255)/256, 256>>>(W3, WHB + OFF_W3,  WLB + OFF_W3,  1048576);
    splitw_bf16<<<(1048576 + 255)/256, 256>>>(W4, WHB + OFF_W4,  WLB + OFF_W4,  1048576);
    splitw_bf16<<<(65536 + 255)/256, 256>>>(Whh, WHB + OFF_WHH, WLB + OFF_WHH, 65536);

    // Phase 1a
    phase1a_kernel<<<BATCH, 256>>>(y, Wih, Whh, bih, bhh, Z);

    // Phase 1b: 2 chunks of 128 steps (fp32 SIMT)
    const int CHUNK = 128;
    const int MBIG  = CHUNK * BATCH;
    for (int c = 0; c < TSTEPS / CHUNK; c++) {
        const float* Xz = Z + (size_t)c * CHUNK * ZSTRIDE;
        gemm_big<1><<<dim3(HID/128, MBIG/128), 256>>>(Xz, LAT, W1, LAT, b1, A, HID, LAT);
        gemm_big<1><<<dim3(HID/128, MBIG/128), 256>>>(A, HID, W2, HID, b2, Bf, HID, HID);
        gemm_big<1><<<dim3(HID/128, MBIG/128), 256>>>(Bf, HID, W3, HID, b3, A, HID, HID);
        gemm_big<1><<<dim3(HID/128, MBIG/128), 256>>>(A, HID, W4, HID, b4, Bf, HID, HID);
        gemm_out<<<dim3(1, MBIG/128), 256>>>(Bf, HID, W5, HID, b5, out, HID, c * CHUNK);
    }

    // Phase 2: reset group barriers, persistent bf16-pair MMA rollout
    cudaMemsetAsync(gbar, 0, sizeof(unsigned) * 4 * 32);
    phase2_kernel<<<128, 256>>>(b1, b2, b3, b4, W5, b5, Wih, bih, bhh,
                                Z, A, out);
}

// round 10
// speedup vs baseline: 1.7885x; 1.1125x over previous
#include <cuda_runtime.h>
#include <cuda_bf16.h>
#include <math.h>
#include <stdint.h>

#define BATCH   128
#define TSTEPS  256
#define HORIZON 512
#define OBS     32
#define LAT     256
#define HID     1024
#define ZSTRIDE (BATCH * LAT)

typedef __nv_bfloat16 bf16;

// ---------------------------------------------------------------------------
// Scratch
// ---------------------------------------------------------------------------
__device__ float g_Z[(size_t)(HORIZON + 1) * ZSTRIDE];
__device__ float g_A[(size_t)128 * BATCH * HID];   // bf16 plane pair carve (1b) / phase2 carve
__device__ float g_B[(size_t)128 * BATCH * HID];
__device__ bf16  g_ZPH[(size_t)TSTEPS * ZSTRIDE];  // teacher-forced z hi plane
__device__ bf16  g_ZPL[(size_t)TSTEPS * ZSTRIDE];  // lo plane
__device__ bf16  g_WHB[3473408];                   // bf16 hi planes: W1,W2,W3,W4,Whh
__device__ bf16  g_WLB[3473408];                   // bf16 lo planes
__device__ unsigned g_gbar[4 * 32];

#define OFF_W1  0
#define OFF_W2  262144
#define OFF_W3  1310720
#define OFF_W4  2359296
#define OFF_WHH 3407872

// ---------------------------------------------------------------------------
// helpers
// ---------------------------------------------------------------------------
__device__ __forceinline__ void mma16(float* d, const uint32_t* a, uint32_t b0, uint32_t b1) {
    asm volatile(
        "mma.sync.aligned.m16n8k16.row.col.f32.bf16.bf16.f32 "
        "{%0,%1,%2,%3},{%4,%5,%6,%7},{%8,%9},{%0,%1,%2,%3};"
        : "+f"(d[0]), "+f"(d[1]), "+f"(d[2]), "+f"(d[3])
        : "r"(a[0]), "r"(a[1]), "r"(a[2]), "r"(a[3]), "r"(b0), "r"(b1));
}
__device__ __forceinline__ void cpa16(uint32_t dst, const void* src) {
    asm volatile("cp.async.cg.shared.global [%0], [%1], 16;" :: "r"(dst), "l"(src));
}
__device__ __forceinline__ void split_pack(float v0, float v1, uint32_t& hw, uint32_t& lw) {
    bf16 h0 = __float2bfloat16(v0);
    bf16 h1 = __float2bfloat16(v1);
    bf16 l0 = __float2bfloat16(v0 - __bfloat162float(h0));
    bf16 l1 = __float2bfloat16(v1 - __bfloat162float(h1));
    hw = ((uint32_t)__bfloat16_as_ushort(h1) << 16) | __bfloat16_as_ushort(h0);
    lw = ((uint32_t)__bfloat16_as_ushort(l1) << 16) | __bfloat16_as_ushort(l0);
}
__device__ __forceinline__ float2 comb2(uint32_t h, uint32_t l) {
    float2 r;
    r.x = __bfloat162float(__ushort_as_bfloat16((unsigned short)(h & 0xffff)))
        + __bfloat162float(__ushort_as_bfloat16((unsigned short)(l & 0xffff)));
    r.y = __bfloat162float(__ushort_as_bfloat16((unsigned short)(h >> 16)))
        + __bfloat162float(__ushort_as_bfloat16((unsigned short)(l >> 16)));
    return r;
}

// group barrier: 32 CTAs per group, counter on its own 128B line
__device__ __forceinline__ void ggsync(int g, unsigned& target) {
    target += 32;
    __syncthreads();
    __threadfence();
    if (threadIdx.x == 0) {
        atomicAdd(&g_gbar[g * 32], 1u);
        while (*((volatile unsigned*)&g_gbar[g * 32]) < target) {}
        __threadfence();
    }
    __syncthreads();
}

// hi/lo bf16 split prepass (weights + teacher-forced z states)
__global__ void splitw_bf16(const float* __restrict__ src,
                            bf16* __restrict__ hi, bf16* __restrict__ lo, int n)
{
    int i = blockIdx.x * 256 + threadIdx.x;
    if (i < n) {
        float v = src[i];
        bf16 h = __float2bfloat16(v);
        hi[i] = h;
        lo[i] = __float2bfloat16(v - __bfloat162float(h));
    }
}

// ---------------------------------------------------------------------------
// Phase 1a (unchanged): barrier-free recurrence, CTA b owns batch row b.
// ---------------------------------------------------------------------------
__global__ void __launch_bounds__(256) phase1a_kernel(
    const float* __restrict__ y,
    const float* __restrict__ Wih, const float* __restrict__ Whh,
    const float* __restrict__ bih, const float* __restrict__ bhh,
    float* __restrict__ Z)
{
    const int b = blockIdx.x, tid = threadIdx.x;
    __shared__ float sz[LAT];
    __shared__ float sy[OBS];

    sz[tid] = 0.0f;
    __stcg(Z + (size_t)b * LAT + tid, 0.0f);
    float bsum = __ldg(bih + tid) + __ldg(bhh + tid);

    float4 wi[8];
    const float4* wip = (const float4*)(Wih + (size_t)tid * OBS);
#pragma unroll
    for (int k = 0; k < 8; k++) wi[k] = __ldg(wip + k);
    const float4* wh = (const float4*)(Whh + (size_t)tid * LAT);
    __syncthreads();

    for (int t = 0; t < TSTEPS; t++) {
        if (tid < OBS) sy[tid] = __ldg(y + ((size_t)b * TSTEPS + t) * OBS + tid);
        __syncthreads();
        float acc = bsum;
#pragma unroll
        for (int k = 0; k < 8; k++) {
            float4 w = wi[k];
            acc += sy[k*4+0]*w.x + sy[k*4+1]*w.y + sy[k*4+2]*w.z + sy[k*4+3]*w.w;
        }
#pragma unroll 8
        for (int k = 0; k < 64; k++) {
            float4 w = __ldg(wh + k);
            acc += sz[k*4+0]*w.x + sz[k*4+1]*w.y + sz[k*4+2]*w.z + sz[k*4+3]*w.w;
        }
        float zn = tanhf(acc);
        __syncthreads();
        sz[tid] = zn;
        __stcg(Z + ((size_t)t + 1) * ZSTRIDE + (size_t)b * LAT + tid, zn);
    }
}

// ---------------------------------------------------------------------------
// Phase 1b bf16-pair MMA GEMM: Y = relu(X @ W^T + bias), planes in/out.
// 64m x 64n tile, 256 thr (8 warps = 2m x 4n, warp tile 32m x 16n),
// K-chunk 32, cp.async double buffer.
// Stage (u32 words, row stride 20): XH 0, XL 1280, WH 2560, WL 3840; 5120/stage.
// ---------------------------------------------------------------------------
__global__ void __launch_bounds__(256, 2) gemm_mma_big(
    const bf16* __restrict__ Xh, const bf16* __restrict__ Xl, int ldx,
    const bf16* __restrict__ Wh, const bf16* __restrict__ Wl, int ldw,
    const float* __restrict__ bias,
    bf16* __restrict__ Yh, bf16* __restrict__ Yl, int ldy, int K)
{
    __shared__ __align__(16) uint32_t SW[2 * 5120];
    const uint32_t sbase = (uint32_t)__cvta_generic_to_shared(SW);
    const int tid = threadIdx.x, lane = tid & 31, wid = tid >> 5;
    const int mw = wid >> 2, nw = wid & 3;
    const int mB = blockIdx.y * 64, nB = blockIdx.x * 64;
    const int nch = K >> 5;

    auto issue = [&](int c, int s) {
        const int k0 = c << 5;
        const uint32_t base = (uint32_t)s * 5120u;
        const int row = tid >> 2, sg = tid & 3;
#pragma unroll
        for (int p = 0; p < 4; p++) {
            const uint32_t dw = base + (uint32_t)p * 1280u + row * 20u + sg * 4u;
            const bf16* src;
            if (p == 0)      src = Xh + (size_t)(mB + row) * ldx + k0 + sg * 8;
            else if (p == 1) src = Xl + (size_t)(mB + row) * ldx + k0 + sg * 8;
            else if (p == 2) src = Wh + (size_t)(nB + row) * ldw + k0 + sg * 8;
            else             src = Wl + (size_t)(nB + row) * ldw + k0 + sg * 8;
            cpa16(sbase + dw * 4u, src);
        }
        asm volatile("cp.async.commit_group;" ::: "memory");
    };

    float acc[2][2][4];
#pragma unroll
    for (int f = 0; f < 2; f++)
#pragma unroll
        for (int g = 0; g < 2; g++)
#pragma unroll
            for (int i = 0; i < 4; i++) acc[f][g][i] = 0.0f;

    issue(0, 0);
    if (nch > 1) issue(1, 1);

    const int arow = lane >> 2, acol = lane & 3;

    for (int c = 0; c < nch; c++) {
        if (c == nch - 1) asm volatile("cp.async.wait_group 0;" ::: "memory");
        else              asm volatile("cp.async.wait_group 1;" ::: "memory");
        __syncthreads();
        const uint32_t* S   = SW + (c & 1) * 5120;
        const uint32_t* XHs = S;
        const uint32_t* XLs = S + 1280;
        const uint32_t* WHs = S + 2560;
        const uint32_t* WLs = S + 3840;
#pragma unroll
        for (int wb = 0; wb < 16; wb += 8) {       // two k16 steps
            uint32_t bh[2][2], bl[2][2];
#pragma unroll
            for (int g = 0; g < 2; g++) {
                int boff = (nw * 16 + g * 8 + arow) * 20 + acol + wb;
                bh[g][0] = WHs[boff]; bh[g][1] = WHs[boff + 4];
                bl[g][0] = WLs[boff]; bl[g][1] = WLs[boff + 4];
            }
#pragma unroll
            for (int f = 0; f < 2; f++) {
                int r = mw * 32 + f * 16 + arow;
                int aoff  = r * 20 + acol + wb;
                int aoff8 = (r + 8) * 20 + acol + wb;
                uint32_t ah[4] = {XHs[aoff], XHs[aoff8], XHs[aoff + 4], XHs[aoff8 + 4]};
                uint32_t al[4] = {XLs[aoff], XLs[aoff8], XLs[aoff + 4], XLs[aoff8 + 4]};
#pragma unroll
                for (int g = 0; g < 2; g++) {
                    mma16(acc[f][g], ah, bh[g][0], bh[g][1]);
                    mma16(acc[f][g], ah, bl[g][0], bl[g][1]);
                    mma16(acc[f][g], al, bh[g][0], bh[g][1]);
                }
            }
        }
        __syncthreads();
        if (c + 2 < nch) issue(c + 2, c & 1);
    }

    // epilogue: bias + relu + bf16-pair split
#pragma unroll
    for (int f = 0; f < 2; f++) {
#pragma unroll
        for (int g = 0; g < 2; g++) {
            const int r0 = mB + mw * 32 + f * 16 + arow;
            const int col = nB + nw * 16 + g * 8 + acol * 2;
            float2 bb = *(const float2*)(bias + col);
            float v0 = fmaxf(acc[f][g][0] + bb.x, 0.f);
            float v1 = fmaxf(acc[f][g][1] + bb.y, 0.f);
            float v2 = fmaxf(acc[f][g][2] + bb.x, 0.f);
            float v3 = fmaxf(acc[f][g][3] + bb.y, 0.f);
            uint32_t hw, lw;
            split_pack(v0, v1, hw, lw);
            __stcg((uint32_t*)&Yh[(size_t)r0 * ldy + col], hw);
            __stcg((uint32_t*)&Yl[(size_t)r0 * ldy + col], lw);
            split_pack(v2, v3, hw, lw);
            __stcg((uint32_t*)&Yh[(size_t)(r0 + 8) * ldy + col], hw);
            __stcg((uint32_t*)&Yl[(size_t)(r0 + 8) * ldy + col], lw);
        }
    }
}

// ---------------------------------------------------------------------------
// Phase 1b output layer: X from bf16 planes, W5 fp32. N=32, scatter to out.
// ---------------------------------------------------------------------------
__global__ void __launch_bounds__(256) gemm_out_bf(
    const bf16* __restrict__ Xh, const bf16* __restrict__ Xl, int ldx,
    const float* __restrict__ W, int ldw,
    const float* __restrict__ bias,
    float* __restrict__ out, int K, int t0)
{
    __shared__ __align__(16) float sX[16 * 132];
    __shared__ __align__(16) float sW[16 * 36];
    const int tid = threadIdx.x;
    const int ty = tid >> 4, tx = tid & 15;
    const int mB = blockIdx.y * 128;
    const int xr = tid >> 2, xc = tid & 3;

    const bf16* XpH0 = Xh + (size_t)(mB + xr) * ldx + xc * 4;
    const bf16* XpL0 = Xl + (size_t)(mB + xr) * ldx + xc * 4;
    const bf16* XpH1 = XpH0 + (size_t)64 * ldx;
    const bf16* XpL1 = XpL0 + (size_t)64 * ldx;
    const bool wp = tid < 128;
    const float* Wp = W + (size_t)xr * ldw + xc * 4;

    uint2 xh0 = __ldg((const uint2*)XpH0);
    uint2 xl0 = __ldg((const uint2*)XpL0);
    uint2 xh1 = __ldg((const uint2*)XpH1);
    uint2 xl1 = __ldg((const uint2*)XpL1);
    float4 wv = make_float4(0,0,0,0);
    if (wp) wv = __ldg((const float4*)Wp);

    float acc[8][2];
#pragma unroll
    for (int i = 0; i < 8; i++) { acc[i][0] = 0.f; acc[i][1] = 0.f; }

    for (int k0 = 0;;) {
        {
            float2 a = comb2(xh0.x, xl0.x), b = comb2(xh0.y, xl0.y);
            sX[(xc*4+0)*132 + xr] = a.x; sX[(xc*4+1)*132 + xr] = a.y;
            sX[(xc*4+2)*132 + xr] = b.x; sX[(xc*4+3)*132 + xr] = b.y;
            float2 c = comb2(xh1.x, xl1.x), d = comb2(xh1.y, xl1.y);
            sX[(xc*4+0)*132 + xr+64] = c.x; sX[(xc*4+1)*132 + xr+64] = c.y;
            sX[(xc*4+2)*132 + xr+64] = d.x; sX[(xc*4+3)*132 + xr+64] = d.y;
        }
        if (wp) {
            sW[(xc*4+0)*36 + xr] = wv.x; sW[(xc*4+1)*36 + xr] = wv.y;
            sW[(xc*4+2)*36 + xr] = wv.z; sW[(xc*4+3)*36 + xr] = wv.w;
        }
        __syncthreads();
        const int k1 = k0 + 16;
        if (k1 < K) {
            xh0 = __ldg((const uint2*)(XpH0 + k1));
            xl0 = __ldg((const uint2*)(XpL0 + k1));
            xh1 = __ldg((const uint2*)(XpH1 + k1));
            xl1 = __ldg((const uint2*)(XpL1 + k1));
            if (wp) wv = __ldg((const float4*)(Wp + k1));
        }
#pragma unroll
        for (int kk = 0; kk < 16; kk++) {
            float4 a0 = *(const float4*)&sX[kk*132 + ty*8];
            float4 a1 = *(const float4*)&sX[kk*132 + ty*8 + 4];
            float2 b  = *(const float2*)&sW[kk*36 + tx*2];
            acc[0][0]+=a0.x*b.x; acc[0][1]+=a0.x*b.y;
            acc[1][0]+=a0.y*b.x; acc[1][1]+=a0.y*b.y;
            acc[2][0]+=a0.z*b.x; acc[2][1]+=a0.z*b.y;
            acc[3][0]+=a0.w*b.x; acc[3][1]+=a0.w*b.y;
            acc[4][0]+=a1.x*b.x; acc[4][1]+=a1.x*b.y;
            acc[5][0]+=a1.y*b.x; acc[5][1]+=a1.y*b.y;
            acc[6][0]+=a1.z*b.x; acc[6][1]+=a1.z*b.y;
            acc[7][0]+=a1.w*b.x; acc[7][1]+=a1.w*b.y;
        }
        __syncthreads();
        if (k1 >= K) break;
        k0 = k1;
    }

    float2 bb = *(const float2*)(bias + tx * 2);
#pragma unroll
    for (int i = 0; i < 8; i++) {
        int r = mB + ty * 8 + i;
        int b = r & (BATCH - 1);
        int t = t0 + (r >> 7);
        float2 v = make_float2(acc[i][0] + bb.x, acc[i][1] + bb.y);
        *(float2*)(out + ((size_t)b * HORIZON + t) * OBS + tx * 2) = v;
    }
}

// ---------------------------------------------------------------------------
// Phase-2 bf16-pair MMA region (unchanged from round 9).
// ---------------------------------------------------------------------------
template<bool RELU, bool DOWHH>
__device__ void mma_region(
    uint32_t* SW, uint32_t sbase,
    int mT, int nT, int K,
    const bf16* __restrict__ Xh, const bf16* __restrict__ Xl, int ldx,
    const bf16* __restrict__ Wh, const bf16* __restrict__ Wl, int ldw,
    const bf16* __restrict__ Vh, const bf16* __restrict__ Vl, int whCol0,
    const float* __restrict__ bias,
    bf16* __restrict__ Yh, bf16* __restrict__ Yl, int ldy,
    float* __restrict__ Cout)
{
    const int tid = threadIdx.x, lane = tid & 31, wid = tid >> 5;
    const int mw = wid >> 2, nw = wid & 3;
    const int nch = K >> 6;

    auto issue = [&](int c, int s) {
        const int k0 = c << 6;
        const uint32_t base = (uint32_t)s * 5184u;
#pragma unroll
        for (int ii = 0; ii < 4; ii++) {
            const int o = tid + ii * 256;
            const int p = o >> 8, q = o & 255, row = q >> 3, sg = q & 7;
            const uint32_t dw = base + (uint32_t)p * 1152u + row * 36u + sg * 4u;
            const bf16* src;
            if (p == 0)      src = Xh + (size_t)(mT + row) * ldx + k0 + sg * 8;
            else if (p == 1) src = Xl + (size_t)(mT + row) * ldx + k0 + sg * 8;
            else if (p == 2) src = Wh + (size_t)(nT + row) * ldw + k0 + sg * 8;
            else             src = Wl + (size_t)(nT + row) * ldw + k0 + sg * 8;
            cpa16(sbase + dw * 4u, src);
        }
        if (DOWHH && tid < 128) {
            const int p = tid >> 6, q = tid & 63, row = q >> 3, sg = q & 7;
            const uint32_t dw = base + 4608u + (uint32_t)p * 288u + row * 36u + sg * 4u;
            const bf16* src = (p ? Vl : Vh) + (size_t)(whCol0 + row) * 256 + k0 + sg * 8;
            cpa16(sbase + dw * 4u, src);
        }
        asm volatile("cp.async.commit_group;" ::: "memory");
    };

    float acc[4]  = {0, 0, 0, 0};
    float accW[4] = {0, 0, 0, 0};

    issue(0, 0);
    if (nch > 1) issue(1, 1);

    const int r0 = mw * 16 + (lane >> 2);
    const int wc = lane & 3;
    const int aoff0 = r0 * 36 + wc;
    const int aoff1 = (r0 + 8) * 36 + wc;
    const int boff = (nw * 8 + (lane >> 2)) * 36 + wc;
    const int voff = (lane >> 2) * 36 + wc;

    for (int c = 0; c < nch; c++) {
        if (c == nch - 1) asm volatile("cp.async.wait_group 0;" ::: "memory");
        else              asm volatile("cp.async.wait_group 1;" ::: "memory");
        __syncthreads();
        const uint32_t* S   = SW + (c & 1) * 5184;
        const uint32_t* XHs = S;
        const uint32_t* XLs = S + 1152;
        const uint32_t* WHs = S + 2304;
        const uint32_t* WLs = S + 3456;
        const uint32_t* VHs = S + 4608;
        const uint32_t* VLs = S + 4896;
#pragma unroll
        for (int wb = 0; wb < 32; wb += 8) {
            uint32_t ah[4], al[4];
            ah[0] = XHs[aoff0 + wb];     ah[1] = XHs[aoff1 + wb];
            ah[2] = XHs[aoff0 + wb + 4]; ah[3] = XHs[aoff1 + wb + 4];
            al[0] = XLs[aoff0 + wb];     al[1] = XLs[aoff1 + wb];
            al[2] = XLs[aoff0 + wb + 4]; al[3] = XLs[aoff1 + wb + 4];
            uint32_t bh0 = WHs[boff + wb], bh1 = WHs[boff + wb + 4];
            uint32_t bl0 = WLs[boff + wb], bl1 = WLs[boff + wb + 4];
            mma16(acc, ah, bh0, bh1);
            mma16(acc, ah, bl0, bl1);
            mma16(acc, al, bh0, bh1);
            if (DOWHH && nw == 0) {
                uint32_t vh0 = VHs[voff + wb], vh1 = VHs[voff + wb + 4];
                uint32_t vl0 = VLs[voff + wb], vl1 = VLs[voff + wb + 4];
                mma16(accW, ah, vh0, vh1);
                mma16(accW, ah, vl0, vl1);
                mma16(accW, al, vh0, vh1);
            }
        }
        __syncthreads();
        if (c + 2 < nch) issue(c + 2, c & 1);
    }

    const int orow = mT + r0;
    const int ocol = nT + nw * 8 + wc * 2;
    float2 bb = *(const float2*)(bias + ocol);
    float v0 = acc[0] + bb.x, v1 = acc[1] + bb.y;
    float v2 = acc[2] + bb.x, v3 = acc[3] + bb.y;
    if (RELU) {
        v0 = fmaxf(v0, 0.f); v1 = fmaxf(v1, 0.f);
        v2 = fmaxf(v2, 0.f); v3 = fmaxf(v3, 0.f);
    }
    uint32_t hw, lw;
    split_pack(v0, v1, hw, lw);
    __stcg((uint32_t*)&Yh[(size_t)orow * ldy + ocol], hw);
    __stcg((uint32_t*)&Yl[(size_t)orow * ldy + ocol], lw);
    split_pack(v2, v3, hw, lw);
    __stcg((uint32_t*)&Yh[(size_t)(orow + 8) * ldy + ocol], hw);
    __stcg((uint32_t*)&Yl[(size_t)(orow + 8) * ldy + ocol], lw);

    if (DOWHH && nw == 0) {
        const int wcol = whCol0 + wc * 2;
        __stcg((float2*)&Cout[(size_t)orow * LAT + wcol], make_float2(accW[0], accW[1]));
        __stcg((float2*)&Cout[(size_t)(orow + 8) * LAT + wcol], make_float2(accW[2], accW[3]));
    }
}

// ---------------------------------------------------------------------------
// Phase 2 (unchanged from round 9): 128 CTAs, 4 groups of 32, 5 barriers/step.
// ---------------------------------------------------------------------------
__global__ void __launch_bounds__(256, 1) phase2_kernel(
    const float* __restrict__ b1, const float* __restrict__ b2,
    const float* __restrict__ b3, const float* __restrict__ b4,
    const float* __restrict__ W5, const float* __restrict__ b5,
    const float* __restrict__ Wih,
    const float* __restrict__ bih, const float* __restrict__ bhh,
    const float* __restrict__ Z,
    float* __restrict__ PL,
    float* __restrict__ out)
{
    __shared__ __align__(16) uint32_t SW[2 * 5184];
    const uint32_t sbase = (uint32_t)__cvta_generic_to_shared(SW);
    const int bid = blockIdx.x, tid = threadIdx.x;
    const int g = bid >> 5, j = bid & 31;
    const int mT = g * 32, nT = j * 32;
    const int b = bid;
    unsigned target = 0;

    bf16* AH = (bf16*)(PL);
    bf16* AL = (bf16*)(PL + 65536);
    bf16* BH = (bf16*)(PL + 131072);
    bf16* BL = (bf16*)(PL + 196608);
    bf16* ZH = (bf16*)(PL + 262144);
    bf16* ZL = (bf16*)(PL + 278528);
    float* C = PL + 294912;

    const bf16 *W1H = g_WHB + OFF_W1,  *W1L = g_WLB + OFF_W1;
    const bf16 *W2H = g_WHB + OFF_W2,  *W2L = g_WLB + OFF_W2;
    const bf16 *W3H = g_WHB + OFF_W3,  *W3L = g_WLB + OFF_W3;
    const bf16 *W4H = g_WHB + OFF_W4,  *W4L = g_WLB + OFF_W4;
    const bf16 *VH  = g_WHB + OFF_WHH, *VL  = g_WLB + OFF_WHH;

    if (tid < 128) {
        float2 z2 = __ldcg((const float2*)(Z + (size_t)TSTEPS * ZSTRIDE + (size_t)b * LAT) + tid);
        uint32_t hw, lw;
        split_pack(z2.x, z2.y, hw, lw);
        __stcg((uint32_t*)(ZH + (size_t)b * LAT) + tid, hw);
        __stcg((uint32_t*)(ZL + (size_t)b * LAT) + tid, lw);
    }
    ggsync(g, target);

    for (int t = TSTEPS; t < HORIZON; t++) {
        mma_region<true, true>(SW, sbase, mT, nT, LAT,
                               ZH, ZL, LAT, W1H, W1L, LAT,
                               VH, VL, j * 8, b1, AH, AL, HID, C);
        ggsync(g, target);
        mma_region<true, false>(SW, sbase, mT, nT, HID,
                                AH, AL, HID, W2H, W2L, HID,
                                (const bf16*)0, (const bf16*)0, 0, b2, BH, BL, HID, (float*)0);
        ggsync(g, target);
        mma_region<true, false>(SW, sbase, mT, nT, HID,
                                BH, BL, HID, W3H, W3L, HID,
                                (const bf16*)0, (const bf16*)0, 0, b3, AH, AL, HID, (float*)0);
        ggsync(g, target);
        mma_region<true, false>(SW, sbase, mT, nT, HID,
                                AH, AL, HID, W4H, W4L, HID,
                                (const bf16*)0, (const bf16*)0, 0, b4, BH, BL, HID, (float*)0);
        ggsync(g, target);

        {
            float* FS = (float*)SW;
            const uint32_t* bhrow = (const uint32_t*)(BH + (size_t)b * HID);
            const uint32_t* blrow = (const uint32_t*)(BL + (size_t)b * HID);
            for (int i = tid; i < 512; i += 256) {
                uint32_t hwv = __ldcg(bhrow + i);
                uint32_t lwv = __ldcg(blrow + i);
                float2 u = comb2(hwv, lwv);
                FS[2*i]   = u.x;
                FS[2*i+1] = u.y;
            }
            __syncthreads();
            {
                const int n = tid >> 3, q = tid & 7;
                const float4* w5 = (const float4*)(W5 + (size_t)n * HID) + q * 32;
                const float4* xb = (const float4*)FS + q * 32;
                float s = 0.f;
#pragma unroll 8
                for (int k = 0; k < 32; k++) {
                    float4 wv = __ldg(w5 + k);
                    float4 xv = xb[k];
                    s += xv.x*wv.x + xv.y*wv.y + xv.z*wv.z + xv.w*wv.w;
                }
                FS[1024 + tid] = s;
            }
            __syncthreads();
            if (tid < OBS) {
                float yh = __ldg(b5 + tid);
#pragma unroll
                for (int q = 0; q < 8; q++) yh += FS[1024 + tid * 8 + q];
                __stcg(out + ((size_t)b * HORIZON + t) * OBS + tid, yh);
                FS[1280 + tid] = yh;
            }
            __syncthreads();
            if (t < HORIZON - 1) {
                const int n = tid;
                float acc = __ldcg(C + (size_t)b * LAT + n)
                          + __ldg(bih + n) + __ldg(bhh + n);
                const float4* wr = (const float4*)(Wih + (size_t)n * OBS);
#pragma unroll
                for (int k = 0; k < 8; k++) {
                    float4 wv = __ldg(wr + k);
                    acc += FS[1280+k*4+0]*wv.x + FS[1280+k*4+1]*wv.y
                         + FS[1280+k*4+2]*wv.z + FS[1280+k*4+3]*wv.w;
                }
                FS[1536 + n] = tanhf(acc);
                __syncthreads();
                if (tid < 128) {
                    float z0 = FS[1536 + 2*tid], z1 = FS[1536 + 2*tid + 1];
                    uint32_t hw, lw;
                    split_pack(z0, z1, hw, lw);
                    __stcg((uint32_t*)(ZH + (size_t)b * LAT) + tid, hw);
                    __stcg((uint32_t*)(ZL + (size_t)b * LAT) + tid, lw);
                }
            }
        }
        ggsync(g, target);
    }
}

// ---------------------------------------------------------------------------
// Launch
// ---------------------------------------------------------------------------
extern "C" void kernel_launch(void* const* d_in, const int* in_sizes, int n_in,
                              void* d_out, int out_size)
{
    const float* y   = (const float*)d_in[0];
    const float* Wih = (const float*)d_in[2];
    const float* Whh = (const float*)d_in[3];
    const float* bih = (const float*)d_in[4];
    const float* bhh = (const float*)d_in[5];
    const float* W1  = (const float*)d_in[6];
    const float* b1  = (const float*)d_in[7];
    const float* W2  = (const float*)d_in[8];
    const float* b2  = (const float*)d_in[9];
    const float* W3  = (const float*)d_in[10];
    const float* b3  = (const float*)d_in[11];
    const float* W4  = (const float*)d_in[12];
    const float* b4  = (const float*)d_in[13];
    const float* W5  = (const float*)d_in[14];
    const float* b5  = (const float*)d_in[15];
    float* out = (float*)d_out;

    float *Z, *A, *Bf;
    bf16 *WHB, *WLB, *ZPH, *ZPL;
    unsigned* gbar;
    cudaGetSymbolAddress((void**)&Z,    g_Z);
    cudaGetSymbolAddress((void**)&A,    g_A);
    cudaGetSymbolAddress((void**)&Bf,   g_B);
    cudaGetSymbolAddress((void**)&WHB,  g_WHB);
    cudaGetSymbolAddress((void**)&WLB,  g_WLB);
    cudaGetSymbolAddress((void**)&ZPH,  g_ZPH);
    cudaGetSymbolAddress((void**)&ZPL,  g_ZPL);
    cudaGetSymbolAddress((void**)&gbar, g_gbar);

    // weight bf16 hi/lo prepass
    splitw_bf16<<<(262144 + 255)/256, 256>>>(W1,  WHB + OFF_W1,  WLB + OFF_W1,  262144);
    splitw_bf16<<<(1048576 + 255)/256, 256>>>(W2, WHB + OFF_W2,  WLB + OFF_W2,  1048576);
    splitw_bf16<<<(1048576 + 255)/256, 256>>>(W3, WHB + OFF_W3,  WLB + OFF_W3,  1048576);
    splitw_bf16<<<(1048576 + 255)/256, 256>>>(W4, WHB + OFF_W4,  WLB + OFF_W4,  1048576);
    splitw_bf16<<<(65536 + 255)/256, 256>>>(Whh, WHB + OFF_WHH, WLB + OFF_WHH, 65536);

    // Phase 1a
    phase1a_kernel<<<BATCH, 256>>>(y, Wih, Whh, bih, bhh, Z);

    // split all teacher-forced z states (z_0..z_255) into bf16 planes
    splitw_bf16<<<(TSTEPS * ZSTRIDE + 255)/256, 256>>>(Z, ZPH, ZPL, TSTEPS * ZSTRIDE);

    // Phase 1b: 2 chunks of 128 steps, bf16-pair MMA
    const int CHUNK = 128;
    const int MBIG  = CHUNK * BATCH;   // 16384 rows
    bf16* AH = (bf16*)A;
    bf16* AL = (bf16*)A + (size_t)MBIG * HID;
    bf16* BH = (bf16*)Bf;
    bf16* BL = (bf16*)Bf + (size_t)MBIG * HID;
    for (int c = 0; c < TSTEPS / CHUNK; c++) {
        const bf16* XzH = ZPH + (size_t)c * CHUNK * ZSTRIDE;
        const bf16* XzL = ZPL + (size_t)c * CHUNK * ZSTRIDE;
        gemm_mma_big<<<dim3(HID/64, MBIG/64), 256>>>(
            XzH, XzL, LAT, WHB + OFF_W1, WLB + OFF_W1, LAT, b1, AH, AL, HID, LAT);
        gemm_mma_big<<<dim3(HID/64, MBIG/64), 256>>>(
            AH, AL, HID, WHB + OFF_W2, WLB + OFF_W2, HID, b2, BH, BL, HID, HID);
        gemm_mma_big<<<dim3(HID/64, MBIG/64), 256>>>(
            BH, BL, HID, WHB + OFF_W3, WLB + OFF_W3, HID, b3, AH, AL, HID, HID);
        gemm_mma_big<<<dim3(HID/64, MBIG/64), 256>>>(
            AH, AL, HID, WHB + OFF_W4, WLB + OFF_W4, HID, b4, BH, BL, HID, HID);
        gemm_out_bf<<<dim3(1, MBIG/128), 256>>>(
            BH, BL, HID, W5, HID, b5, out, HID, c * CHUNK);
    }

    // Phase 2: reset group barriers, persistent bf16-pair MMA rollout
    cudaMemsetAsync(gbar, 0, sizeof(unsigned) * 4 * 32);
    phase2_kernel<<<128, 256>>>(b1, b2, b3, b4, W5, b5, Wih, bih, bhh,
                                Z, A, out);
}

// round 11
// speedup vs baseline: 1.8084x; 1.0111x over previous
#include <cuda_runtime.h>
#include <cuda_bf16.h>
#include <math.h>
#include <stdint.h>

#define BATCH   128
#define TSTEPS  256
#define HORIZON 512
#define OBS     32
#define LAT     256
#define HID     1024
#define ZSTRIDE (BATCH * LAT)

typedef __nv_bfloat16 bf16;

#define STAGE_W 5184                       // u32 words per pipeline stage
#define NSTAGE  4
#define P2_SMEM (NSTAGE * STAGE_W * 4)     // 82,944 B dynamic smem

// ---------------------------------------------------------------------------
// Scratch
// ---------------------------------------------------------------------------
__device__ float g_Z[(size_t)(HORIZON + 1) * ZSTRIDE];
__device__ float g_A[(size_t)128 * BATCH * HID];
__device__ float g_B[(size_t)128 * BATCH * HID];
__device__ bf16  g_ZPH[(size_t)TSTEPS * ZSTRIDE];
__device__ bf16  g_ZPL[(size_t)TSTEPS * ZSTRIDE];
__device__ bf16  g_WHB[3473408];
__device__ bf16  g_WLB[3473408];
__device__ unsigned g_gbar[4 * 32];

#define OFF_W1  0
#define OFF_W2  262144
#define OFF_W3  1310720
#define OFF_W4  2359296
#define OFF_WHH 3407872

// ---------------------------------------------------------------------------
// helpers
// ---------------------------------------------------------------------------
__device__ __forceinline__ void mma16(float* d, const uint32_t* a, uint32_t b0, uint32_t b1) {
    asm volatile(
        "mma.sync.aligned.m16n8k16.row.col.f32.bf16.bf16.f32 "
        "{%0,%1,%2,%3},{%4,%5,%6,%7},{%8,%9},{%0,%1,%2,%3};"
        : "+f"(d[0]), "+f"(d[1]), "+f"(d[2]), "+f"(d[3])
        : "r"(a[0]), "r"(a[1]), "r"(a[2]), "r"(a[3]), "r"(b0), "r"(b1));
}
__device__ __forceinline__ void cpa16(uint32_t dst, const void* src) {
    asm volatile("cp.async.cg.shared.global [%0], [%1], 16;" :: "r"(dst), "l"(src));
}
__device__ __forceinline__ void wait_ahead(int rem) {
    if (rem >= 3)      asm volatile("cp.async.wait_group 3;" ::: "memory");
    else if (rem == 2) asm volatile("cp.async.wait_group 2;" ::: "memory");
    else if (rem == 1) asm volatile("cp.async.wait_group 1;" ::: "memory");
    else               asm volatile("cp.async.wait_group 0;" ::: "memory");
}
__device__ __forceinline__ void split_pack(float v0, float v1, uint32_t& hw, uint32_t& lw) {
    bf16 h0 = __float2bfloat16(v0);
    bf16 h1 = __float2bfloat16(v1);
    bf16 l0 = __float2bfloat16(v0 - __bfloat162float(h0));
    bf16 l1 = __float2bfloat16(v1 - __bfloat162float(h1));
    hw = ((uint32_t)__bfloat16_as_ushort(h1) << 16) | __bfloat16_as_ushort(h0);
    lw = ((uint32_t)__bfloat16_as_ushort(l1) << 16) | __bfloat16_as_ushort(l0);
}
__device__ __forceinline__ float2 comb2(uint32_t h, uint32_t l) {
    float2 r;
    r.x = __bfloat162float(__ushort_as_bfloat16((unsigned short)(h & 0xffff)))
        + __bfloat162float(__ushort_as_bfloat16((unsigned short)(l & 0xffff)));
    r.y = __bfloat162float(__ushort_as_bfloat16((unsigned short)(h >> 16)))
        + __bfloat162float(__ushort_as_bfloat16((unsigned short)(l >> 16)));
    return r;
}

// group barrier: 32 CTAs per group, counter on its own 128B line
__device__ __forceinline__ void ggsync(int g, unsigned& target) {
    target += 32;
    __syncthreads();
    __threadfence();
    if (threadIdx.x == 0) {
        atomicAdd(&g_gbar[g * 32], 1u);
        while (*((volatile unsigned*)&g_gbar[g * 32]) < target) {}
        __threadfence();
    }
    __syncthreads();
}

// hi/lo bf16 split prepass
__global__ void splitw_bf16(const float* __restrict__ src,
                            bf16* __restrict__ hi, bf16* __restrict__ lo, int n)
{
    int i = blockIdx.x * 256 + threadIdx.x;
    if (i < n) {
        float v = src[i];
        bf16 h = __float2bfloat16(v);
        hi[i] = h;
        lo[i] = __float2bfloat16(v - __bfloat162float(h));
    }
}

// ---------------------------------------------------------------------------
// Phase 1a (unchanged)
// ---------------------------------------------------------------------------
__global__ void __launch_bounds__(256) phase1a_kernel(
    const float* __restrict__ y,
    const float* __restrict__ Wih, const float* __restrict__ Whh,
    const float* __restrict__ bih, const float* __restrict__ bhh,
    float* __restrict__ Z)
{
    const int b = blockIdx.x, tid = threadIdx.x;
    __shared__ float sz[LAT];
    __shared__ float sy[OBS];

    sz[tid] = 0.0f;
    __stcg(Z + (size_t)b * LAT + tid, 0.0f);
    float bsum = __ldg(bih + tid) + __ldg(bhh + tid);

    float4 wi[8];
    const float4* wip = (const float4*)(Wih + (size_t)tid * OBS);
#pragma unroll
    for (int k = 0; k < 8; k++) wi[k] = __ldg(wip + k);
    const float4* wh = (const float4*)(Whh + (size_t)tid * LAT);
    __syncthreads();

    for (int t = 0; t < TSTEPS; t++) {
        if (tid < OBS) sy[tid] = __ldg(y + ((size_t)b * TSTEPS + t) * OBS + tid);
        __syncthreads();
        float acc = bsum;
#pragma unroll
        for (int k = 0; k < 8; k++) {
            float4 w = wi[k];
            acc += sy[k*4+0]*w.x + sy[k*4+1]*w.y + sy[k*4+2]*w.z + sy[k*4+3]*w.w;
        }
#pragma unroll 8
        for (int k = 0; k < 64; k++) {
            float4 w = __ldg(wh + k);
            acc += sz[k*4+0]*w.x + sz[k*4+1]*w.y + sz[k*4+2]*w.z + sz[k*4+3]*w.w;
        }
        float zn = tanhf(acc);
        __syncthreads();
        sz[tid] = zn;
        __stcg(Z + ((size_t)t + 1) * ZSTRIDE + (size_t)b * LAT + tid, zn);
    }
}

// ---------------------------------------------------------------------------
// Phase 1b bf16-pair MMA GEMM (unchanged from round 10).
// ---------------------------------------------------------------------------
__global__ void __launch_bounds__(256, 2) gemm_mma_big(
    const bf16* __restrict__ Xh, const bf16* __restrict__ Xl, int ldx,
    const bf16* __restrict__ Wh, const bf16* __restrict__ Wl, int ldw,
    const float* __restrict__ bias,
    bf16* __restrict__ Yh, bf16* __restrict__ Yl, int ldy, int K)
{
    __shared__ __align__(16) uint32_t SW[2 * 5120];
    const uint32_t sbase = (uint32_t)__cvta_generic_to_shared(SW);
    const int tid = threadIdx.x, lane = tid & 31, wid = tid >> 5;
    const int mw = wid >> 2, nw = wid & 3;
    const int mB = blockIdx.y * 64, nB = blockIdx.x * 64;
    const int nch = K >> 5;

    auto issue = [&](int c, int s) {
        const int k0 = c << 5;
        const uint32_t base = (uint32_t)s * 5120u;
        const int row = tid >> 2, sg = tid & 3;
#pragma unroll
        for (int p = 0; p < 4; p++) {
            const uint32_t dw = base + (uint32_t)p * 1280u + row * 20u + sg * 4u;
            const bf16* src;
            if (p == 0)      src = Xh + (size_t)(mB + row) * ldx + k0 + sg * 8;
            else if (p == 1) src = Xl + (size_t)(mB + row) * ldx + k0 + sg * 8;
            else if (p == 2) src = Wh + (size_t)(nB + row) * ldw + k0 + sg * 8;
            else             src = Wl + (size_t)(nB + row) * ldw + k0 + sg * 8;
            cpa16(sbase + dw * 4u, src);
        }
        asm volatile("cp.async.commit_group;" ::: "memory");
    };

    float acc[2][2][4];
#pragma unroll
    for (int f = 0; f < 2; f++)
#pragma unroll
        for (int g = 0; g < 2; g++)
#pragma unroll
            for (int i = 0; i < 4; i++) acc[f][g][i] = 0.0f;

    issue(0, 0);
    if (nch > 1) issue(1, 1);

    const int arow = lane >> 2, acol = lane & 3;

    for (int c = 0; c < nch; c++) {
        if (c == nch - 1) asm volatile("cp.async.wait_group 0;" ::: "memory");
        else              asm volatile("cp.async.wait_group 1;" ::: "memory");
        __syncthreads();
        const uint32_t* S   = SW + (c & 1) * 5120;
        const uint32_t* XHs = S;
        const uint32_t* XLs = S + 1280;
        const uint32_t* WHs = S + 2560;
        const uint32_t* WLs = S + 3840;
#pragma unroll
        for (int wb = 0; wb < 16; wb += 8) {
            uint32_t bh[2][2], bl[2][2];
#pragma unroll
            for (int g = 0; g < 2; g++) {
                int boff = (nw * 16 + g * 8 + arow) * 20 + acol + wb;
                bh[g][0] = WHs[boff]; bh[g][1] = WHs[boff + 4];
                bl[g][0] = WLs[boff]; bl[g][1] = WLs[boff + 4];
            }
#pragma unroll
            for (int f = 0; f < 2; f++) {
                int r = mw * 32 + f * 16 + arow;
                int aoff  = r * 20 + acol + wb;
                int aoff8 = (r + 8) * 20 + acol + wb;
                uint32_t ah[4] = {XHs[aoff], XHs[aoff8], XHs[aoff + 4], XHs[aoff8 + 4]};
                uint32_t al[4] = {XLs[aoff], XLs[aoff8], XLs[aoff + 4], XLs[aoff8 + 4]};
#pragma unroll
                for (int g = 0; g < 2; g++) {
                    mma16(acc[f][g], ah, bh[g][0], bh[g][1]);
                    mma16(acc[f][g], ah, bl[g][0], bl[g][1]);
                    mma16(acc[f][g], al, bh[g][0], bh[g][1]);
                }
            }
        }
        __syncthreads();
        if (c + 2 < nch) issue(c + 2, c & 1);
    }

#pragma unroll
    for (int f = 0; f < 2; f++) {
#pragma unroll
        for (int g = 0; g < 2; g++) {
            const int r0 = mB + mw * 32 + f * 16 + arow;
            const int col = nB + nw * 16 + g * 8 + acol * 2;
            float2 bb = *(const float2*)(bias + col);
            float v0 = fmaxf(acc[f][g][0] + bb.x, 0.f);
            float v1 = fmaxf(acc[f][g][1] + bb.y, 0.f);
            float v2 = fmaxf(acc[f][g][2] + bb.x, 0.f);
            float v3 = fmaxf(acc[f][g][3] + bb.y, 0.f);
            uint32_t hw, lw;
            split_pack(v0, v1, hw, lw);
            __stcg((uint32_t*)&Yh[(size_t)r0 * ldy + col], hw);
            __stcg((uint32_t*)&Yl[(size_t)r0 * ldy + col], lw);
            split_pack(v2, v3, hw, lw);
            __stcg((uint32_t*)&Yh[(size_t)(r0 + 8) * ldy + col], hw);
            __stcg((uint32_t*)&Yl[(size_t)(r0 + 8) * ldy + col], lw);
        }
    }
}

// ---------------------------------------------------------------------------
// Phase 1b output layer (unchanged from round 10).
// ---------------------------------------------------------------------------
__global__ void __launch_bounds__(256) gemm_out_bf(
    const bf16* __restrict__ Xh, const bf16* __restrict__ Xl, int ldx,
    const float* __restrict__ W, int ldw,
    const float* __restrict__ bias,
    float* __restrict__ out, int K, int t0)
{
    __shared__ __align__(16) float sX[16 * 132];
    __shared__ __align__(16) float sW[16 * 36];
    const int tid = threadIdx.x;
    const int ty = tid >> 4, tx = tid & 15;
    const int mB = blockIdx.y * 128;
    const int xr = tid >> 2, xc = tid & 3;

    const bf16* XpH0 = Xh + (size_t)(mB + xr) * ldx + xc * 4;
    const bf16* XpL0 = Xl + (size_t)(mB + xr) * ldx + xc * 4;
    const bf16* XpH1 = XpH0 + (size_t)64 * ldx;
    const bf16* XpL1 = XpL0 + (size_t)64 * ldx;
    const bool wp = tid < 128;
    const float* Wp = W + (size_t)xr * ldw + xc * 4;

    uint2 xh0 = __ldg((const uint2*)XpH0);
    uint2 xl0 = __ldg((const uint2*)XpL0);
    uint2 xh1 = __ldg((const uint2*)XpH1);
    uint2 xl1 = __ldg((const uint2*)XpL1);
    float4 wv = make_float4(0,0,0,0);
    if (wp) wv = __ldg((const float4*)Wp);

    float acc[8][2];
#pragma unroll
    for (int i = 0; i < 8; i++) { acc[i][0] = 0.f; acc[i][1] = 0.f; }

    for (int k0 = 0;;) {
        {
            float2 a = comb2(xh0.x, xl0.x), b = comb2(xh0.y, xl0.y);
            sX[(xc*4+0)*132 + xr] = a.x; sX[(xc*4+1)*132 + xr] = a.y;
            sX[(xc*4+2)*132 + xr] = b.x; sX[(xc*4+3)*132 + xr] = b.y;
            float2 c = comb2(xh1.x, xl1.x), d = comb2(xh1.y, xl1.y);
            sX[(xc*4+0)*132 + xr+64] = c.x; sX[(xc*4+1)*132 + xr+64] = c.y;
            sX[(xc*4+2)*132 + xr+64] = d.x; sX[(xc*4+3)*132 + xr+64] = d.y;
        }
        if (wp) {
            sW[(xc*4+0)*36 + xr] = wv.x; sW[(xc*4+1)*36 + xr] = wv.y;
            sW[(xc*4+2)*36 + xr] = wv.z; sW[(xc*4+3)*36 + xr] = wv.w;
        }
        __syncthreads();
        const int k1 = k0 + 16;
        if (k1 < K) {
            xh0 = __ldg((const uint2*)(XpH0 + k1));
            xl0 = __ldg((const uint2*)(XpL0 + k1));
            xh1 = __ldg((const uint2*)(XpH1 + k1));
            xl1 = __ldg((const uint2*)(XpL1 + k1));
            if (wp) wv = __ldg((const float4*)(Wp + k1));
        }
#pragma unroll
        for (int kk = 0; kk < 16; kk++) {
            float4 a0 = *(const float4*)&sX[kk*132 + ty*8];
            float4 a1 = *(const float4*)&sX[kk*132 + ty*8 + 4];
            float2 b  = *(const float2*)&sW[kk*36 + tx*2];
            acc[0][0]+=a0.x*b.x; acc[0][1]+=a0.x*b.y;
            acc[1][0]+=a0.y*b.x; acc[1][1]+=a0.y*b.y;
            acc[2][0]+=a0.z*b.x; acc[2][1]+=a0.z*b.y;
            acc[3][0]+=a0.w*b.x; acc[3][1]+=a0.w*b.y;
            acc[4][0]+=a1.x*b.x; acc[4][1]+=a1.x*b.y;
            acc[5][0]+=a1.y*b.x; acc[5][1]+=a1.y*b.y;
            acc[6][0]+=a1.z*b.x; acc[6][1]+=a1.z*b.y;
            acc[7][0]+=a1.w*b.x; acc[7][1]+=a1.w*b.y;
        }
        __syncthreads();
        if (k1 >= K) break;
        k0 = k1;
    }

    float2 bb = *(const float2*)(bias + tx * 2);
#pragma unroll
    for (int i = 0; i < 8; i++) {
        int r = mB + ty * 8 + i;
        int b = r & (BATCH - 1);
        int t = t0 + (r >> 7);
        float2 v = make_float2(acc[i][0] + bb.x, acc[i][1] + bb.y);
        *(float2*)(out + ((size_t)b * HORIZON + t) * OBS + tx * 2) = v;
    }
}

// ---------------------------------------------------------------------------
// Phase-2 bf16-pair MMA region — 4-stage cp.async pipeline (dynamic smem).
// Indexing identical to round 10; only stage count / wait discipline changed.
// ---------------------------------------------------------------------------
template<bool RELU, bool DOWHH>
__device__ void mma_region(
    uint32_t* SW, uint32_t sbase,
    int mT, int nT, int K,
    const bf16* __restrict__ Xh, const bf16* __restrict__ Xl, int ldx,
    const bf16* __restrict__ Wh, const bf16* __restrict__ Wl, int ldw,
    const bf16* __restrict__ Vh, const bf16* __restrict__ Vl, int whCol0,
    const float* __restrict__ bias,
    bf16* __restrict__ Yh, bf16* __restrict__ Yl, int ldy,
    float* __restrict__ Cout)
{
    const int tid = threadIdx.x, lane = tid & 31, wid = tid >> 5;
    const int mw = wid >> 2, nw = wid & 3;
    const int nch = K >> 6;

    auto issue = [&](int c, int s) {
        const int k0 = c << 6;
        const uint32_t base = (uint32_t)s * (uint32_t)STAGE_W;
#pragma unroll
        for (int ii = 0; ii < 4; ii++) {
            const int o = tid + ii * 256;
            const int p = o >> 8, q = o & 255, row = q >> 3, sg = q & 7;
            const uint32_t dw = base + (uint32_t)p * 1152u + row * 36u + sg * 4u;
            const bf16* src;
            if (p == 0)      src = Xh + (size_t)(mT + row) * ldx + k0 + sg * 8;
            else if (p == 1) src = Xl + (size_t)(mT + row) * ldx + k0 + sg * 8;
            else if (p == 2) src = Wh + (size_t)(nT + row) * ldw + k0 + sg * 8;
            else             src = Wl + (size_t)(nT + row) * ldw + k0 + sg * 8;
            cpa16(sbase + dw * 4u, src);
        }
        if (DOWHH && tid < 128) {
            const int p = tid >> 6, q = tid & 63, row = q >> 3, sg = q & 7;
            const uint32_t dw = base + 4608u + (uint32_t)p * 288u + row * 36u + sg * 4u;
            const bf16* src = (p ? Vl : Vh) + (size_t)(whCol0 + row) * 256 + k0 + sg * 8;
            cpa16(sbase + dw * 4u, src);
        }
        asm volatile("cp.async.commit_group;" ::: "memory");
    };

    float acc[4]  = {0, 0, 0, 0};
    float accW[4] = {0, 0, 0, 0};

#pragma unroll
    for (int c0 = 0; c0 < NSTAGE; c0++)
        if (c0 < nch) issue(c0, c0);

    const int r0 = mw * 16 + (lane >> 2);
    const int wc = lane & 3;
    const int aoff0 = r0 * 36 + wc;
    const int aoff1 = (r0 + 8) * 36 + wc;
    const int boff = (nw * 8 + (lane >> 2)) * 36 + wc;
    const int voff = (lane >> 2) * 36 + wc;

    for (int c = 0; c < nch; c++) {
        wait_ahead(nch - 1 - c);
        __syncthreads();
        const uint32_t* S   = SW + (c & (NSTAGE - 1)) * STAGE_W;
        const uint32_t* XHs = S;
        const uint32_t* XLs = S + 1152;
        const uint32_t* WHs = S + 2304;
        const uint32_t* WLs = S + 3456;
        const uint32_t* VHs = S + 4608;
        const uint32_t* VLs = S + 4896;
#pragma unroll
        for (int wb = 0; wb < 32; wb += 8) {
            uint32_t ah[4], al[4];
            ah[0] = XHs[aoff0 + wb];     ah[1] = XHs[aoff1 + wb];
            ah[2] = XHs[aoff0 + wb + 4]; ah[3] = XHs[aoff1 + wb + 4];
            al[0] = XLs[aoff0 + wb];     al[1] = XLs[aoff1 + wb];
            al[2] = XLs[aoff0 + wb + 4]; al[3] = XLs[aoff1 + wb + 4];
            uint32_t bh0 = WHs[boff + wb], bh1 = WHs[boff + wb + 4];
            uint32_t bl0 = WLs[boff + wb], bl1 = WLs[boff + wb + 4];
            mma16(acc, ah, bh0, bh1);
            mma16(acc, ah, bl0, bl1);
            mma16(acc, al, bh0, bh1);
            if (DOWHH && nw == 0) {
                uint32_t vh0 = VHs[voff + wb], vh1 = VHs[voff + wb + 4];
                uint32_t vl0 = VLs[voff + wb], vl1 = VLs[voff + wb + 4];
                mma16(accW, ah, vh0, vh1);
                mma16(accW, ah, vl0, vl1);
                mma16(accW, al, vh0, vh1);
            }
        }
        __syncthreads();
        if (c + NSTAGE < nch) issue(c + NSTAGE, (c + NSTAGE) & (NSTAGE - 1));
    }

    const int orow = mT + r0;
    const int ocol = nT + nw * 8 + wc * 2;
    float2 bb = *(const float2*)(bias + ocol);
    float v0 = acc[0] + bb.x, v1 = acc[1] + bb.y;
    float v2 = acc[2] + bb.x, v3 = acc[3] + bb.y;
    if (RELU) {
        v0 = fmaxf(v0, 0.f); v1 = fmaxf(v1, 0.f);
        v2 = fmaxf(v2, 0.f); v3 = fmaxf(v3, 0.f);
    }
    uint32_t hw, lw;
    split_pack(v0, v1, hw, lw);
    __stcg((uint32_t*)&Yh[(size_t)orow * ldy + ocol], hw);
    __stcg((uint32_t*)&Yl[(size_t)orow * ldy + ocol], lw);
    split_pack(v2, v3, hw, lw);
    __stcg((uint32_t*)&Yh[(size_t)(orow + 8) * ldy + ocol], hw);
    __stcg((uint32_t*)&Yl[(size_t)(orow + 8) * ldy + ocol], lw);

    if (DOWHH && nw == 0) {
        const int wcol = whCol0 + wc * 2;
        __stcg((float2*)&Cout[(size_t)orow * LAT + wcol], make_float2(accW[0], accW[1]));
        __stcg((float2*)&Cout[(size_t)(orow + 8) * LAT + wcol], make_float2(accW[2], accW[3]));
    }
}

// ---------------------------------------------------------------------------
// Phase 2: 128 CTAs, 4 groups of 32, 5 barriers/step, dynamic smem (4 stages).
// ---------------------------------------------------------------------------
__global__ void __launch_bounds__(256, 1) phase2_kernel(
    const float* __restrict__ b1, const float* __restrict__ b2,
    const float* __restrict__ b3, const float* __restrict__ b4,
    const float* __restrict__ W5, const float* __restrict__ b5,
    const float* __restrict__ Wih,
    const float* __restrict__ bih, const float* __restrict__ bhh,
    const float* __restrict__ Z,
    float* __restrict__ PL,
    float* __restrict__ out)
{
    extern __shared__ __align__(16) uint32_t SW[];
    const uint32_t sbase = (uint32_t)__cvta_generic_to_shared(SW);
    const int bid = blockIdx.x, tid = threadIdx.x;
    const int g = bid >> 5, j = bid & 31;
    const int mT = g * 32, nT = j * 32;
    const int b = bid;
    unsigned target = 0;

    bf16* AH = (bf16*)(PL);
    bf16* AL = (bf16*)(PL + 65536);
    bf16* BH = (bf16*)(PL + 131072);
    bf16* BL = (bf16*)(PL + 196608);
    bf16* ZH = (bf16*)(PL + 262144);
    bf16* ZL = (bf16*)(PL + 278528);
    float* C = PL + 294912;

    const bf16 *W1H = g_WHB + OFF_W1,  *W1L = g_WLB + OFF_W1;
    const bf16 *W2H = g_WHB + OFF_W2,  *W2L = g_WLB + OFF_W2;
    const bf16 *W3H = g_WHB + OFF_W3,  *W3L = g_WLB + OFF_W3;
    const bf16 *W4H = g_WHB + OFF_W4,  *W4L = g_WLB + OFF_W4;
    const bf16 *VH  = g_WHB + OFF_WHH, *VL  = g_WLB + OFF_WHH;

    if (tid < 128) {
        float2 z2 = __ldcg((const float2*)(Z + (size_t)TSTEPS * ZSTRIDE + (size_t)b * LAT) + tid);
        uint32_t hw, lw;
        split_pack(z2.x, z2.y, hw, lw);
        __stcg((uint32_t*)(ZH + (size_t)b * LAT) + tid, hw);
        __stcg((uint32_t*)(ZL + (size_t)b * LAT) + tid, lw);
    }
    ggsync(g, target);

    for (int t = TSTEPS; t < HORIZON; t++) {
        mma_region<true, true>(SW, sbase, mT, nT, LAT,
                               ZH, ZL, LAT, W1H, W1L, LAT,
                               VH, VL, j * 8, b1, AH, AL, HID, C);
        ggsync(g, target);
        mma_region<true, false>(SW, sbase, mT, nT, HID,
                                AH, AL, HID, W2H, W2L, HID,
                                (const bf16*)0, (const bf16*)0, 0, b2, BH, BL, HID, (float*)0);
        ggsync(g, target);
        mma_region<true, false>(SW, sbase, mT, nT, HID,
                                BH, BL, HID, W3H, W3L, HID,
                                (const bf16*)0, (const bf16*)0, 0, b3, AH, AL, HID, (float*)0);
        ggsync(g, target);
        mma_region<true, false>(SW, sbase, mT, nT, HID,
                                AH, AL, HID, W4H, W4L, HID,
                                (const bf16*)0, (const bf16*)0, 0, b4, BH, BL, HID, (float*)0);
        ggsync(g, target);

        {
            float* FS = (float*)SW;
            const uint32_t* bhrow = (const uint32_t*)(BH + (size_t)b * HID);
            const uint32_t* blrow = (const uint32_t*)(BL + (size_t)b * HID);
            for (int i = tid; i < 512; i += 256) {
                uint32_t hwv = __ldcg(bhrow + i);
                uint32_t lwv = __ldcg(blrow + i);
                float2 u = comb2(hwv, lwv);
                FS[2*i]   = u.x;
                FS[2*i+1] = u.y;
            }
            __syncthreads();
            {
                const int n = tid >> 3, q = tid & 7;
                const float4* w5 = (const float4*)(W5 + (size_t)n * HID) + q * 32;
                const float4* xb = (const float4*)FS + q * 32;
                float s = 0.f;
#pragma unroll 8
                for (int k = 0; k < 32; k++) {
                    float4 wv = __ldg(w5 + k);
                    float4 xv = xb[k];
                    s += xv.x*wv.x + xv.y*wv.y + xv.z*wv.z + xv.w*wv.w;
                }
                FS[1024 + tid] = s;
            }
            __syncthreads();
            if (tid < OBS) {
                float yh = __ldg(b5 + tid);
#pragma unroll
                for (int q = 0; q < 8; q++) yh += FS[1024 + tid * 8 + q];
                __stcg(out + ((size_t)b * HORIZON + t) * OBS + tid, yh);
                FS[1280 + tid] = yh;
            }
            __syncthreads();
            if (t < HORIZON - 1) {
                const int n = tid;
                float acc = __ldcg(C + (size_t)b * LAT + n)
                          + __ldg(bih + n) + __ldg(bhh + n);
                const float4* wr = (const float4*)(Wih + (size_t)n * OBS);
#pragma unroll
                for (int k = 0; k < 8; k++) {
                    float4 wv = __ldg(wr + k);
                    acc += FS[1280+k*4+0]*wv.x + FS[1280+k*4+1]*wv.y
                         + FS[1280+k*4+2]*wv.z + FS[1280+k*4+3]*wv.w;
                }
                FS[1536 + n] = tanhf(acc);
                __syncthreads();
                if (tid < 128) {
                    float z0 = FS[1536 + 2*tid], z1 = FS[1536 + 2*tid + 1];
                    uint32_t hw, lw;
                    split_pack(z0, z1, hw, lw);
                    __stcg((uint32_t*)(ZH + (size_t)b * LAT) + tid, hw);
                    __stcg((uint32_t*)(ZL + (size_t)b * LAT) + tid, lw);
                }
            }
        }
        ggsync(g, target);
    }
}

// ---------------------------------------------------------------------------
// Launch
// ---------------------------------------------------------------------------
extern "C" void kernel_launch(void* const* d_in, const int* in_sizes, int n_in,
                              void* d_out, int out_size)
{
    const float* y   = (const float*)d_in[0];
    const float* Wih = (const float*)d_in[2];
    const float* Whh = (const float*)d_in[3];
    const float* bih = (const float*)d_in[4];
    const float* bhh = (const float*)d_in[5];
    const float* W1  = (const float*)d_in[6];
    const float* b1  = (const float*)d_in[7];
    const float* W2  = (const float*)d_in[8];
    const float* b2  = (const float*)d_in[9];
    const float* W3  = (const float*)d_in[10];
    const float* b3  = (const float*)d_in[11];
    const float* W4  = (const float*)d_in[12];
    const float* b4  = (const float*)d_in[13];
    const float* W5  = (const float*)d_in[14];
    const float* b5  = (const float*)d_in[15];
    float* out = (float*)d_out;

    float *Z, *A, *Bf;
    bf16 *WHB, *WLB, *ZPH, *ZPL;
    unsigned* gbar;
    cudaGetSymbolAddress((void**)&Z,    g_Z);
    cudaGetSymbolAddress((void**)&A,    g_A);
    cudaGetSymbolAddress((void**)&Bf,   g_B);
    cudaGetSymbolAddress((void**)&WHB,  g_WHB);
    cudaGetSymbolAddress((void**)&WLB,  g_WLB);
    cudaGetSymbolAddress((void**)&ZPH,  g_ZPH);
    cudaGetSymbolAddress((void**)&ZPL,  g_ZPL);
    cudaGetSymbolAddress((void**)&gbar, g_gbar);

    static int attr_done = 0;
    if (!attr_done) {
        cudaFuncSetAttribute(phase2_kernel,
                             cudaFuncAttributeMaxDynamicSharedMemorySize, P2_SMEM);
        attr_done = 1;
    }

    // weight bf16 hi/lo prepass
    splitw_bf16<<<(262144 + 255)/256, 256>>>(W1,  WHB + OFF_W1,  WLB + OFF_W1,  262144);
    splitw_bf16<<<(1048576 + 255)/256, 256>>>(W2, WHB + OFF_W2,  WLB + OFF_W2,  1048576);
    splitw_bf16<<<(1048576 + 255)/256, 256>>>(W3, WHB + OFF_W3,  WLB + OFF_W3,  1048576);
    splitw_bf16<<<(1048576 + 255)/256, 256>>>(W4, WHB + OFF_W4,  WLB + OFF_W4,  1048576);
    splitw_bf16<<<(65536 + 255)/256, 256>>>(Whh, WHB + OFF_WHH, WLB + OFF_WHH, 65536);

    // Phase 1a
    phase1a_kernel<<<BATCH, 256>>>(y, Wih, Whh, bih, bhh, Z);

    // split all teacher-forced z states into bf16 planes
    splitw_bf16<<<(TSTEPS * ZSTRIDE + 255)/256, 256>>>(Z, ZPH, ZPL, TSTEPS * ZSTRIDE);

    // Phase 1b: 2 chunks of 128 steps, bf16-pair MMA
    const int CHUNK = 128;
    const int MBIG  = CHUNK * BATCH;
    bf16* AH = (bf16*)A;
    bf16* AL = (bf16*)A + (size_t)MBIG * HID;
    bf16* BH = (bf16*)Bf;
    bf16* BL = (bf16*)Bf + (size_t)MBIG * HID;
    for (int c = 0; c < TSTEPS / CHUNK; c++) {
        const bf16* XzH = ZPH + (size_t)c * CHUNK * ZSTRIDE;
        const bf16* XzL = ZPL + (size_t)c * CHUNK * ZSTRIDE;
        gemm_mma_big<<<dim3(HID/64, MBIG/64), 256>>>(
            XzH, XzL, LAT, WHB + OFF_W1, WLB + OFF_W1, LAT, b1, AH, AL, HID, LAT);
        gemm_mma_big<<<dim3(HID/64, MBIG/64), 256>>>(
            AH, AL, HID, WHB + OFF_W2, WLB + OFF_W2, HID, b2, BH, BL, HID, HID);
        gemm_mma_big<<<dim3(HID/64, MBIG/64), 256>>>(
            BH, BL, HID, WHB + OFF_W3, WLB + OFF_W3, HID, b3, AH, AL, HID, HID);
        gemm_mma_big<<<dim3(HID/64, MBIG/64), 256>>>(
            AH, AL, HID, WHB + OFF_W4, WLB + OFF_W4, HID, b4, BH, BL, HID, HID);
        gemm_out_bf<<<dim3(1, MBIG/128), 256>>>(
            BH, BL, HID, W5, HID, b5, out, HID, c * CHUNK);
    }

    // Phase 2: reset group barriers, persistent rollout (4-stage pipeline)
    cudaMemsetAsync(gbar, 0, sizeof(unsigned) * 4 * 32);
    phase2_kernel<<<128, 256, P2_SMEM>>>(b1, b2, b3, b4, W5, b5, Wih, bih, bhh,
                                         Z, A, out);
}

// round 12
// speedup vs baseline: 2.0690x; 1.1441x over previous
#include <cuda_runtime.h>
#include <cuda_bf16.h>
#include <math.h>
#include <stdint.h>

#define BATCH   128
#define TSTEPS  256
#define HORIZON 512
#define OBS     32
#define LAT     256
#define HID     1024
#define ZSTRIDE (BATCH * LAT)

typedef __nv_bfloat16 bf16;

#define STAGE_W 5184
#define NSTAGE  4
#define P2_SMEM (NSTAGE * STAGE_W * 4)

// ---------------------------------------------------------------------------
// Scratch
// ---------------------------------------------------------------------------
__device__ float g_Z[(size_t)(HORIZON + 1) * ZSTRIDE];   // slots 0..256 used; tail = phase2 scratch
__device__ float g_A[(size_t)128 * BATCH * HID];
__device__ float g_B[(size_t)128 * BATCH * HID];
__device__ bf16  g_ZPH[(size_t)TSTEPS * ZSTRIDE];
__device__ bf16  g_ZPL[(size_t)TSTEPS * ZSTRIDE];
__device__ bf16  g_WHB[3473408];
__device__ bf16  g_WLB[3473408];
__device__ unsigned g_gbar[4 * 32];

#define OFF_W1  0
#define OFF_W2  262144
#define OFF_W3  1310720
#define OFF_W4  2359296
#define OFF_WHH 3407872
#define NW_TOT  3473408

// phase-2 scratch carve (float offsets inside g_Z tail)
#define P2_BASE (320 * ZSTRIDE)
#define C_AH    0
#define C_AL    65536
#define C_BH    131072
#define C_BL    196608
#define C_ZH    262144
#define C_ZL    278528
#define C_C     294912
#define C_YP    327680    // yhpart: [32 j][128 b][32 s] fp32 = 131072 floats

// ---------------------------------------------------------------------------
// helpers
// ---------------------------------------------------------------------------
__device__ __forceinline__ void mma16(float* d, const uint32_t* a, uint32_t b0, uint32_t b1) {
    asm volatile(
        "mma.sync.aligned.m16n8k16.row.col.f32.bf16.bf16.f32 "
        "{%0,%1,%2,%3},{%4,%5,%6,%7},{%8,%9},{%0,%1,%2,%3};"
        : "+f"(d[0]), "+f"(d[1]), "+f"(d[2]), "+f"(d[3])
        : "r"(a[0]), "r"(a[1]), "r"(a[2]), "r"(a[3]), "r"(b0), "r"(b1));
}
__device__ __forceinline__ void cpa16(uint32_t dst, const void* src) {
    asm volatile("cp.async.cg.shared.global [%0], [%1], 16;" :: "r"(dst), "l"(src));
}
__device__ __forceinline__ void wait_ahead(int rem) {
    if (rem >= 3)      asm volatile("cp.async.wait_group 3;" ::: "memory");
    else if (rem == 2) asm volatile("cp.async.wait_group 2;" ::: "memory");
    else if (rem == 1) asm volatile("cp.async.wait_group 1;" ::: "memory");
    else               asm volatile("cp.async.wait_group 0;" ::: "memory");
}
__device__ __forceinline__ void split_pack(float v0, float v1, uint32_t& hw, uint32_t& lw) {
    bf16 h0 = __float2bfloat16(v0);
    bf16 h1 = __float2bfloat16(v1);
    bf16 l0 = __float2bfloat16(v0 - __bfloat162float(h0));
    bf16 l1 = __float2bfloat16(v1 - __bfloat162float(h1));
    hw = ((uint32_t)__bfloat16_as_ushort(h1) << 16) | __bfloat16_as_ushort(h0);
    lw = ((uint32_t)__bfloat16_as_ushort(l1) << 16) | __bfloat16_as_ushort(l0);
}
__device__ __forceinline__ float2 comb2(uint32_t h, uint32_t l) {
    float2 r;
    r.x = __bfloat162float(__ushort_as_bfloat16((unsigned short)(h & 0xffff)))
        + __bfloat162float(__ushort_as_bfloat16((unsigned short)(l & 0xffff)));
    r.y = __bfloat162float(__ushort_as_bfloat16((unsigned short)(h >> 16)))
        + __bfloat162float(__ushort_as_bfloat16((unsigned short)(l >> 16)));
    return r;
}

__device__ __forceinline__ void ggsync(int g, unsigned& target) {
    target += 32;
    __syncthreads();
    __threadfence();
    if (threadIdx.x == 0) {
        atomicAdd(&g_gbar[g * 32], 1u);
        while (*((volatile unsigned*)&g_gbar[g * 32]) < target) {}
        __threadfence();
    }
    __syncthreads();
}

// fused weight hi/lo split (all 5 matrices, one launch)
__global__ void splitw_all(const float* __restrict__ W1, const float* __restrict__ W2,
                           const float* __restrict__ W3, const float* __restrict__ W4,
                           const float* __restrict__ Whh)
{
    int i = blockIdx.x * 256 + threadIdx.x;
    if (i >= NW_TOT) return;
    const float* src; int off;
    if (i < OFF_W2)       { src = W1;  off = OFF_W1; }
    else if (i < OFF_W3)  { src = W2;  off = OFF_W2; }
    else if (i < OFF_W4)  { src = W3;  off = OFF_W3; }
    else if (i < OFF_WHH) { src = W4;  off = OFF_W4; }
    else                  { src = Whh; off = OFF_WHH; }
    float v = src[i - off];
    bf16 h = __float2bfloat16(v);
    g_WHB[i] = h;
    g_WLB[i] = __float2bfloat16(v - __bfloat162float(h));
}

// generic hi/lo split (z states)
__global__ void splitw_bf16(const float* __restrict__ src,
                            bf16* __restrict__ hi, bf16* __restrict__ lo, int n)
{
    int i = blockIdx.x * 256 + threadIdx.x;
    if (i < n) {
        float v = src[i];
        bf16 h = __float2bfloat16(v);
        hi[i] = h;
        lo[i] = __float2bfloat16(v - __bfloat162float(h));
    }
}

// ---------------------------------------------------------------------------
// Phase 1a: barrier-free recurrence + gbar zeroing
// ---------------------------------------------------------------------------
__global__ void __launch_bounds__(256) phase1a_kernel(
    const float* __restrict__ y,
    const float* __restrict__ Wih, const float* __restrict__ Whh,
    const float* __restrict__ bih, const float* __restrict__ bhh,
    float* __restrict__ Z)
{
    const int b = blockIdx.x, tid = threadIdx.x;
    __shared__ float sz[LAT];
    __shared__ float sy[OBS];

    if (b == 0 && tid < 128) g_gbar[tid] = 0u;

    sz[tid] = 0.0f;
    __stcg(Z + (size_t)b * LAT + tid, 0.0f);
    float bsum = __ldg(bih + tid) + __ldg(bhh + tid);

    float4 wi[8];
    const float4* wip = (const float4*)(Wih + (size_t)tid * OBS);
#pragma unroll
    for (int k = 0; k < 8; k++) wi[k] = __ldg(wip + k);
    const float4* wh = (const float4*)(Whh + (size_t)tid * LAT);
    __syncthreads();

    for (int t = 0; t < TSTEPS; t++) {
        if (tid < OBS) sy[tid] = __ldg(y + ((size_t)b * TSTEPS + t) * OBS + tid);
        __syncthreads();
        float acc = bsum;
#pragma unroll
        for (int k = 0; k < 8; k++) {
            float4 w = wi[k];
            acc += sy[k*4+0]*w.x + sy[k*4+1]*w.y + sy[k*4+2]*w.z + sy[k*4+3]*w.w;
        }
#pragma unroll 8
        for (int k = 0; k < 64; k++) {
            float4 w = __ldg(wh + k);
            acc += sz[k*4+0]*w.x + sz[k*4+1]*w.y + sz[k*4+2]*w.z + sz[k*4+3]*w.w;
        }
        float zn = tanhf(acc);
        __syncthreads();
        sz[tid] = zn;
        __stcg(Z + ((size_t)t + 1) * ZSTRIDE + (size_t)b * LAT + tid, zn);
    }
}

// ---------------------------------------------------------------------------
// Phase 1b bf16-pair MMA GEMM (unchanged)
// ---------------------------------------------------------------------------
__global__ void __launch_bounds__(256, 2) gemm_mma_big(
    const bf16* __restrict__ Xh, const bf16* __restrict__ Xl, int ldx,
    const bf16* __restrict__ Wh, const bf16* __restrict__ Wl, int ldw,
    const float* __restrict__ bias,
    bf16* __restrict__ Yh, bf16* __restrict__ Yl, int ldy, int K)
{
    __shared__ __align__(16) uint32_t SW[2 * 5120];
    const uint32_t sbase = (uint32_t)__cvta_generic_to_shared(SW);
    const int tid = threadIdx.x, lane = tid & 31, wid = tid >> 5;
    const int mw = wid >> 2, nw = wid & 3;
    const int mB = blockIdx.y * 64, nB = blockIdx.x * 64;
    const int nch = K >> 5;

    auto issue = [&](int c, int s) {
        const int k0 = c << 5;
        const uint32_t base = (uint32_t)s * 5120u;
        const int row = tid >> 2, sg = tid & 3;
#pragma unroll
        for (int p = 0; p < 4; p++) {
            const uint32_t dw = base + (uint32_t)p * 1280u + row * 20u + sg * 4u;
            const bf16* src;
            if (p == 0)      src = Xh + (size_t)(mB + row) * ldx + k0 + sg * 8;
            else if (p == 1) src = Xl + (size_t)(mB + row) * ldx + k0 + sg * 8;
            else if (p == 2) src = Wh + (size_t)(nB + row) * ldw + k0 + sg * 8;
            else             src = Wl + (size_t)(nB + row) * ldw + k0 + sg * 8;
            cpa16(sbase + dw * 4u, src);
        }
        asm volatile("cp.async.commit_group;" ::: "memory");
    };

    float acc[2][2][4];
#pragma unroll
    for (int f = 0; f < 2; f++)
#pragma unroll
        for (int g = 0; g < 2; g++)
#pragma unroll
            for (int i = 0; i < 4; i++) acc[f][g][i] = 0.0f;

    issue(0, 0);
    if (nch > 1) issue(1, 1);

    const int arow = lane >> 2, acol = lane & 3;

    for (int c = 0; c < nch; c++) {
        if (c == nch - 1) asm volatile("cp.async.wait_group 0;" ::: "memory");
        else              asm volatile("cp.async.wait_group 1;" ::: "memory");
        __syncthreads();
        const uint32_t* S   = SW + (c & 1) * 5120;
        const uint32_t* XHs = S;
        const uint32_t* XLs = S + 1280;
        const uint32_t* WHs = S + 2560;
        const uint32_t* WLs = S + 3840;
#pragma unroll
        for (int wb = 0; wb < 16; wb += 8) {
            uint32_t bh[2][2], bl[2][2];
#pragma unroll
            for (int g = 0; g < 2; g++) {
                int boff = (nw * 16 + g * 8 + arow) * 20 + acol + wb;
                bh[g][0] = WHs[boff]; bh[g][1] = WHs[boff + 4];
                bl[g][0] = WLs[boff]; bl[g][1] = WLs[boff + 4];
            }
#pragma unroll
            for (int f = 0; f < 2; f++) {
                int r = mw * 32 + f * 16 + arow;
                int aoff  = r * 20 + acol + wb;
                int aoff8 = (r + 8) * 20 + acol + wb;
                uint32_t ah[4] = {XHs[aoff], XHs[aoff8], XHs[aoff + 4], XHs[aoff8 + 4]};
                uint32_t al[4] = {XLs[aoff], XLs[aoff8], XLs[aoff + 4], XLs[aoff8 + 4]};
#pragma unroll
                for (int g = 0; g < 2; g++) {
                    mma16(acc[f][g], ah, bh[g][0], bh[g][1]);
                    mma16(acc[f][g], ah, bl[g][0], bl[g][1]);
                    mma16(acc[f][g], al, bh[g][0], bh[g][1]);
                }
            }
        }
        __syncthreads();
        if (c + 2 < nch) issue(c + 2, c & 1);
    }

#pragma unroll
    for (int f = 0; f < 2; f++) {
#pragma unroll
        for (int g = 0; g < 2; g++) {
            const int r0 = mB + mw * 32 + f * 16 + arow;
            const int col = nB + nw * 16 + g * 8 + acol * 2;
            float2 bb = *(const float2*)(bias + col);
            float v0 = fmaxf(acc[f][g][0] + bb.x, 0.f);
            float v1 = fmaxf(acc[f][g][1] + bb.y, 0.f);
            float v2 = fmaxf(acc[f][g][2] + bb.x, 0.f);
            float v3 = fmaxf(acc[f][g][3] + bb.y, 0.f);
            uint32_t hw, lw;
            split_pack(v0, v1, hw, lw);
            __stcg((uint32_t*)&Yh[(size_t)r0 * ldy + col], hw);
            __stcg((uint32_t*)&Yl[(size_t)r0 * ldy + col], lw);
            split_pack(v2, v3, hw, lw);
            __stcg((uint32_t*)&Yh[(size_t)(r0 + 8) * ldy + col], hw);
            __stcg((uint32_t*)&Yl[(size_t)(r0 + 8) * ldy + col], lw);
        }
    }
}

// ---------------------------------------------------------------------------
// Phase 1b output layer (unchanged)
// ---------------------------------------------------------------------------
__global__ void __launch_bounds__(256) gemm_out_bf(
    const bf16* __restrict__ Xh, const bf16* __restrict__ Xl, int ldx,
    const float* __restrict__ W, int ldw,
    const float* __restrict__ bias,
    float* __restrict__ out, int K, int t0)
{
    __shared__ __align__(16) float sX[16 * 132];
    __shared__ __align__(16) float sW[16 * 36];
    const int tid = threadIdx.x;
    const int ty = tid >> 4, tx = tid & 15;
    const int mB = blockIdx.y * 128;
    const int xr = tid >> 2, xc = tid & 3;

    const bf16* XpH0 = Xh + (size_t)(mB + xr) * ldx + xc * 4;
    const bf16* XpL0 = Xl + (size_t)(mB + xr) * ldx + xc * 4;
    const bf16* XpH1 = XpH0 + (size_t)64 * ldx;
    const bf16* XpL1 = XpL0 + (size_t)64 * ldx;
    const bool wp = tid < 128;
    const float* Wp = W + (size_t)xr * ldw + xc * 4;

    uint2 xh0 = __ldg((const uint2*)XpH0);
    uint2 xl0 = __ldg((const uint2*)XpL0);
    uint2 xh1 = __ldg((const uint2*)XpH1);
    uint2 xl1 = __ldg((const uint2*)XpL1);
    float4 wv = make_float4(0,0,0,0);
    if (wp) wv = __ldg((const float4*)Wp);

    float acc[8][2];
#pragma unroll
    for (int i = 0; i < 8; i++) { acc[i][0] = 0.f; acc[i][1] = 0.f; }

    for (int k0 = 0;;) {
        {
            float2 a = comb2(xh0.x, xl0.x), b = comb2(xh0.y, xl0.y);
            sX[(xc*4+0)*132 + xr] = a.x; sX[(xc*4+1)*132 + xr] = a.y;
            sX[(xc*4+2)*132 + xr] = b.x; sX[(xc*4+3)*132 + xr] = b.y;
            float2 c = comb2(xh1.x, xl1.x), d = comb2(xh1.y, xl1.y);
            sX[(xc*4+0)*132 + xr+64] = c.x; sX[(xc*4+1)*132 + xr+64] = c.y;
            sX[(xc*4+2)*132 + xr+64] = d.x; sX[(xc*4+3)*132 + xr+64] = d.y;
        }
        if (wp) {
            sW[(xc*4+0)*36 + xr] = wv.x; sW[(xc*4+1)*36 + xr] = wv.y;
            sW[(xc*4+2)*36 + xr] = wv.z; sW[(xc*4+3)*36 + xr] = wv.w;
        }
        __syncthreads();
        const int k1 = k0 + 16;
        if (k1 < K) {
            xh0 = __ldg((const uint2*)(XpH0 + k1));
            xl0 = __ldg((const uint2*)(XpL0 + k1));
            xh1 = __ldg((const uint2*)(XpH1 + k1));
            xl1 = __ldg((const uint2*)(XpL1 + k1));
            if (wp) wv = __ldg((const float4*)(Wp + k1));
        }
#pragma unroll
        for (int kk = 0; kk < 16; kk++) {
            float4 a0 = *(const float4*)&sX[kk*132 + ty*8];
            float4 a1 = *(const float4*)&sX[kk*132 + ty*8 + 4];
            float2 b  = *(const float2*)&sW[kk*36 + tx*2];
            acc[0][0]+=a0.x*b.x; acc[0][1]+=a0.x*b.y;
            acc[1][0]+=a0.y*b.x; acc[1][1]+=a0.y*b.y;
            acc[2][0]+=a0.z*b.x; acc[2][1]+=a0.z*b.y;
            acc[3][0]+=a0.w*b.x; acc[3][1]+=a0.w*b.y;
            acc[4][0]+=a1.x*b.x; acc[4][1]+=a1.x*b.y;
            acc[5][0]+=a1.y*b.x; acc[5][1]+=a1.y*b.y;
            acc[6][0]+=a1.z*b.x; acc[6][1]+=a1.z*b.y;
            acc[7][0]+=a1.w*b.x; acc[7][1]+=a1.w*b.y;
        }
        __syncthreads();
        if (k1 >= K) break;
        k0 = k1;
    }

    float2 bb = *(const float2*)(bias + tx * 2);
#pragma unroll
    for (int i = 0; i < 8; i++) {
        int r = mB + ty * 8 + i;
        int b = r & (BATCH - 1);
        int t = t0 + (r >> 7);
        float2 v = make_float2(acc[i][0] + bb.x, acc[i][1] + bb.y);
        *(float2*)(out + ((size_t)b * HORIZON + t) * OBS + tx * 2) = v;
    }
}

// ---------------------------------------------------------------------------
// Phase-2 region: 32x32 tile, 3 independent accumulators, 4-stage pipeline.
// DOL5: fold L5 partial (h4 strip @ W5 strip) into this region; no plane store.
// ---------------------------------------------------------------------------
template<bool RELU, bool DOWHH, bool DOL5>
__device__ void mma_region(
    uint32_t* SW, uint32_t sbase,
    int mT, int nT, int K,
    const bf16* __restrict__ Xh, const bf16* __restrict__ Xl, int ldx,
    const bf16* __restrict__ Wh, const bf16* __restrict__ Wl, int ldw,
    const bf16* __restrict__ Vh, const bf16* __restrict__ Vl, int whCol0,
    const float* __restrict__ bias,
    bf16* __restrict__ Yh, bf16* __restrict__ Yl, int ldy,
    float* __restrict__ Cout,
    const float* __restrict__ W5, float* __restrict__ yhpart, int jIdx)
{
    const int tid = threadIdx.x, lane = tid & 31, wid = tid >> 5;
    const int mw = wid >> 2, nw = wid & 3;
    const int nch = K >> 6;

    auto issue = [&](int c, int s) {
        const int k0 = c << 6;
        const uint32_t base = (uint32_t)s * (uint32_t)STAGE_W;
#pragma unroll
        for (int ii = 0; ii < 4; ii++) {
            const int o = tid + ii * 256;
            const int p = o >> 8, q = o & 255, row = q >> 3, sg = q & 7;
            const uint32_t dw = base + (uint32_t)p * 1152u + row * 36u + sg * 4u;
            const bf16* src;
            if (p == 0)      src = Xh + (size_t)(mT + row) * ldx + k0 + sg * 8;
            else if (p == 1) src = Xl + (size_t)(mT + row) * ldx + k0 + sg * 8;
            else if (p == 2) src = Wh + (size_t)(nT + row) * ldw + k0 + sg * 8;
            else             src = Wl + (size_t)(nT + row) * ldw + k0 + sg * 8;
            cpa16(sbase + dw * 4u, src);
        }
        if (DOWHH && tid < 128) {
            const int p = tid >> 6, q = tid & 63, row = q >> 3, sg = q & 7;
            const uint32_t dw = base + 4608u + (uint32_t)p * 288u + row * 36u + sg * 4u;
            const bf16* src = (p ? Vl : Vh) + (size_t)(whCol0 + row) * 256 + k0 + sg * 8;
            cpa16(sbase + dw * 4u, src);
        }
        asm volatile("cp.async.commit_group;" ::: "memory");
    };

    float ahh[4] = {0,0,0,0}, ahl[4] = {0,0,0,0}, alh[4] = {0,0,0,0};
    float whh[4] = {0,0,0,0}, whl[4] = {0,0,0,0}, wlh[4] = {0,0,0,0};

#pragma unroll
    for (int c0 = 0; c0 < NSTAGE; c0++)
        if (c0 < nch) issue(c0, c0);

    const int r0 = mw * 16 + (lane >> 2);
    const int wc = lane & 3;
    const int aoff0 = r0 * 36 + wc;
    const int aoff1 = (r0 + 8) * 36 + wc;
    const int boff = (nw * 8 + (lane >> 2)) * 36 + wc;
    const int voff = (lane >> 2) * 36 + wc;

    for (int c = 0; c < nch; c++) {
        wait_ahead(nch - 1 - c);
        __syncthreads();
        const uint32_t* S   = SW + (c & (NSTAGE - 1)) * STAGE_W;
        const uint32_t* XHs = S;
        const uint32_t* XLs = S + 1152;
        const uint32_t* WHs = S + 2304;
        const uint32_t* WLs = S + 3456;
        const uint32_t* VHs = S + 4608;
        const uint32_t* VLs = S + 4896;
#pragma unroll
        for (int wb = 0; wb < 32; wb += 8) {
            uint32_t ah[4], al[4];
            ah[0] = XHs[aoff0 + wb];     ah[1] = XHs[aoff1 + wb];
            ah[2] = XHs[aoff0 + wb + 4]; ah[3] = XHs[aoff1 + wb + 4];
            al[0] = XLs[aoff0 + wb];     al[1] = XLs[aoff1 + wb];
            al[2] = XLs[aoff0 + wb + 4]; al[3] = XLs[aoff1 + wb + 4];
            uint32_t bh0 = WHs[boff + wb], bh1 = WHs[boff + wb + 4];
            uint32_t bl0 = WLs[boff + wb], bl1 = WLs[boff + wb + 4];
            mma16(ahh, ah, bh0, bh1);
            mma16(ahl, ah, bl0, bl1);
            mma16(alh, al, bh0, bh1);
            if (DOWHH && nw == 0) {
                uint32_t vh0 = VHs[voff + wb], vh1 = VHs[voff + wb + 4];
                uint32_t vl0 = VLs[voff + wb], vl1 = VLs[voff + wb + 4];
                mma16(whh, ah, vh0, vh1);
                mma16(whl, ah, vl0, vl1);
                mma16(wlh, al, vh0, vh1);
            }
        }
        __syncthreads();
        if (c + NSTAGE < nch) issue(c + NSTAGE, (c + NSTAGE) & (NSTAGE - 1));
    }

    const int orow = mT + r0;
    const int ocol_l = nw * 8 + wc * 2;          // local col 0..31
    const int ocol = nT + ocol_l;
    float2 bb = *(const float2*)(bias + ocol);
    float v0 = ahh[0] + ahl[0] + alh[0] + bb.x;
    float v1 = ahh[1] + ahl[1] + alh[1] + bb.y;
    float v2 = ahh[2] + ahl[2] + alh[2] + bb.x;
    float v3 = ahh[3] + ahl[3] + alh[3] + bb.y;
    if (RELU) {
        v0 = fmaxf(v0, 0.f); v1 = fmaxf(v1, 0.f);
        v2 = fmaxf(v2, 0.f); v3 = fmaxf(v3, 0.f);
    }

    if (DOL5) {
        // stage h4 strip (32 x 32) in smem, compute yh partial against W5 strip
        float* sh4 = (float*)SW;                 // 32 x 33
        sh4[r0 * 33 + ocol_l]           = v0;
        sh4[r0 * 33 + ocol_l + 1]       = v1;
        sh4[(r0 + 8) * 33 + ocol_l]     = v2;
        sh4[(r0 + 8) * 33 + ocol_l + 1] = v3;
        __syncthreads();
        const float* w5r = W5 + (size_t)lane * HID + nT;   // W5[s][nT..nT+31]
        float w5f[32];
#pragma unroll
        for (int q = 0; q < 8; q++) {
            float4 w = __ldg((const float4*)(w5r + q * 4));
            w5f[q*4+0] = w.x; w5f[q*4+1] = w.y; w5f[q*4+2] = w.z; w5f[q*4+3] = w.w;
        }
#pragma unroll
        for (int i = 0; i < 4; i++) {
            const int r = wid * 4 + i;
            const float* hr = sh4 + r * 33;
            float s = 0.f;
#pragma unroll
            for (int n = 0; n < 32; n++) s += hr[n] * w5f[n];
            __stcg(yhpart + (size_t)jIdx * (BATCH * 32) + (mT + r) * 32 + lane, s);
        }
    } else {
        uint32_t hw, lw;
        split_pack(v0, v1, hw, lw);
        __stcg((uint32_t*)&Yh[(size_t)orow * ldy + ocol], hw);
        __stcg((uint32_t*)&Yl[(size_t)orow * ldy + ocol], lw);
        split_pack(v2, v3, hw, lw);
        __stcg((uint32_t*)&Yh[(size_t)(orow + 8) * ldy + ocol], hw);
        __stcg((uint32_t*)&Yl[(size_t)(orow + 8) * ldy + ocol], lw);
    }

    if (DOWHH && nw == 0) {
        const int wcol = whCol0 + wc * 2;
        __stcg((float2*)&Cout[(size_t)orow * LAT + wcol],
               make_float2(whh[0]+whl[0]+wlh[0], whh[1]+whl[1]+wlh[1]));
        __stcg((float2*)&Cout[(size_t)(orow + 8) * LAT + wcol],
               make_float2(whh[2]+whl[2]+wlh[2], whh[3]+whl[3]+wlh[3]));
    }
}

// ---------------------------------------------------------------------------
// Phase 2: 128 CTAs, 4 groups of 32, 5 barriers/step.
// ---------------------------------------------------------------------------
__global__ void __launch_bounds__(256, 1) phase2_kernel(
    const float* __restrict__ b1, const float* __restrict__ b2,
    const float* __restrict__ b3, const float* __restrict__ b4,
    const float* __restrict__ W5, const float* __restrict__ b5,
    const float* __restrict__ Wih,
    const float* __restrict__ bih, const float* __restrict__ bhh,
    const float* __restrict__ Z,
    float* __restrict__ PL,
    float* __restrict__ out)
{
    extern __shared__ __align__(16) uint32_t SW[];
    const uint32_t sbase = (uint32_t)__cvta_generic_to_shared(SW);
    const int bid = blockIdx.x, tid = threadIdx.x;
    const int g = bid >> 5, j = bid & 31;
    const int mT = g * 32, nT = j * 32;
    const int b = bid;
    unsigned target = 0;

    bf16* AH = (bf16*)(PL + C_AH);
    bf16* AL = (bf16*)(PL + C_AL);
    bf16* BH = (bf16*)(PL + C_BH);
    bf16* BL = (bf16*)(PL + C_BL);
    bf16* ZH = (bf16*)(PL + C_ZH);
    bf16* ZL = (bf16*)(PL + C_ZL);
    float* C  = PL + C_C;
    float* YP = PL + C_YP;

    const bf16 *W1H = g_WHB + OFF_W1,  *W1L = g_WLB + OFF_W1;
    const bf16 *W2H = g_WHB + OFF_W2,  *W2L = g_WLB + OFF_W2;
    const bf16 *W3H = g_WHB + OFF_W3,  *W3L = g_WLB + OFF_W3;
    const bf16 *W4H = g_WHB + OFF_W4,  *W4L = g_WLB + OFF_W4;
    const bf16 *VH  = g_WHB + OFF_WHH, *VL  = g_WLB + OFF_WHH;

    if (tid < 128) {
        float2 z2 = __ldcg((const float2*)(Z + (size_t)TSTEPS * ZSTRIDE + (size_t)b * LAT) + tid);
        uint32_t hw, lw;
        split_pack(z2.x, z2.y, hw, lw);
        __stcg((uint32_t*)(ZH + (size_t)b * LAT) + tid, hw);
        __stcg((uint32_t*)(ZL + (size_t)b * LAT) + tid, lw);
    }
    ggsync(g, target);

    for (int t = TSTEPS; t < HORIZON; t++) {
        mma_region<true, true, false>(SW, sbase, mT, nT, LAT,
                               ZH, ZL, LAT, W1H, W1L, LAT,
                               VH, VL, j * 8, b1, AH, AL, HID, C,
                               (const float*)0, (float*)0, 0);
        ggsync(g, target);
        mma_region<true, false, false>(SW, sbase, mT, nT, HID,
                                AH, AL, HID, W2H, W2L, HID,
                                (const bf16*)0, (const bf16*)0, 0, b2, BH, BL, HID, (float*)0,
                                (const float*)0, (float*)0, 0);
        ggsync(g, target);
        mma_region<true, false, false>(SW, sbase, mT, nT, HID,
                                BH, BL, HID, W3H, W3L, HID,
                                (const bf16*)0, (const bf16*)0, 0, b3, AH, AL, HID, (float*)0,
                                (const float*)0, (float*)0, 0);
        ggsync(g, target);
        // R4: L4 + fused L5 partial (no plane store)
        mma_region<true, false, true>(SW, sbase, mT, nT, HID,
                                AH, AL, HID, W4H, W4L, HID,
                                (const bf16*)0, (const bf16*)0, 0, b4,
                                (bf16*)0, (bf16*)0, HID, (float*)0,
                                W5, YP, j);
        ggsync(g, target);

        // R5: combine yh partials -> out; cell finish
        {
            float* FS = (float*)SW;
            if (tid < OBS) {
                float s = __ldg(b5 + tid);
                const float* yp = YP + (size_t)b * 32 + tid;
#pragma unroll
                for (int jj = 0; jj < 32; jj++)
                    s += __ldcg(yp + (size_t)jj * (BATCH * 32));
                __stcg(out + ((size_t)b * HORIZON + t) * OBS + tid, s);
                FS[tid] = s;
            }
            __syncthreads();
            if (t < HORIZON - 1) {
                const int n = tid;
                float acc = __ldcg(C + (size_t)b * LAT + n)
                          + __ldg(bih + n) + __ldg(bhh + n);
                const float4* wr = (const float4*)(Wih + (size_t)n * OBS);
#pragma unroll
                for (int k = 0; k < 8; k++) {
                    float4 wv = __ldg(wr + k);
                    acc += FS[k*4+0]*wv.x + FS[k*4+1]*wv.y
                         + FS[k*4+2]*wv.z + FS[k*4+3]*wv.w;
                }
                FS[64 + n] = tanhf(acc);
                __syncthreads();
                if (tid < 128) {
                    float z0 = FS[64 + 2*tid], z1 = FS[64 + 2*tid + 1];
                    uint32_t hw, lw;
                    split_pack(z0, z1, hw, lw);
                    __stcg((uint32_t*)(ZH + (size_t)b * LAT) + tid, hw);
                    __stcg((uint32_t*)(ZL + (size_t)b * LAT) + tid, lw);
                }
            }
        }
        ggsync(g, target);
    }
}

// ---------------------------------------------------------------------------
// Launch.  Order chosen so phase2_kernel is OUR launch index 3 (ncu -s 5
// lands there given the harness's two preceding launches).
// ---------------------------------------------------------------------------
extern "C" void kernel_launch(void* const* d_in, const int* in_sizes, int n_in,
                              void* d_out, int out_size)
{
    const float* y   = (const float*)d_in[0];
    const float* Wih = (const float*)d_in[2];
    const float* Whh = (const float*)d_in[3];
    const float* bih = (const float*)d_in[4];
    const float* bhh = (const float*)d_in[5];
    const float* W1  = (const float*)d_in[6];
    const float* b1  = (const float*)d_in[7];
    const float* W2  = (const float*)d_in[8];
    const float* b2  = (const float*)d_in[9];
    const float* W3  = (const float*)d_in[10];
    const float* b3  = (const float*)d_in[11];
    const float* W4  = (const float*)d_in[12];
    const float* b4  = (const float*)d_in[13];
    const float* W5  = (const float*)d_in[14];
    const float* b5  = (const float*)d_in[15];
    float* out = (float*)d_out;

    float *Z, *A, *Bf;
    bf16 *WHB, *WLB, *ZPH, *ZPL;
    cudaGetSymbolAddress((void**)&Z,    g_Z);
    cudaGetSymbolAddress((void**)&A,    g_A);
    cudaGetSymbolAddress((void**)&Bf,   g_B);
    cudaGetSymbolAddress((void**)&WHB,  g_WHB);
    cudaGetSymbolAddress((void**)&WLB,  g_WLB);
    cudaGetSymbolAddress((void**)&ZPH,  g_ZPH);
    cudaGetSymbolAddress((void**)&ZPL,  g_ZPL);

    static int attr_done = 0;
    if (!attr_done) {
        cudaFuncSetAttribute(phase2_kernel,
                             cudaFuncAttributeMaxDynamicSharedMemorySize, P2_SMEM);
        attr_done = 1;
    }

    // [0] fused weight hi/lo split
    splitw_all<<<(NW_TOT + 255)/256, 256>>>(W1, W2, W3, W4, Whh);

    // [1] phase 1a (also zeroes group barriers)
    phase1a_kernel<<<BATCH, 256>>>(y, Wih, Whh, bih, bhh, Z);

    // [2] split teacher-forced z states into bf16 planes
    splitw_bf16<<<(TSTEPS * ZSTRIDE + 255)/256, 256>>>(Z, ZPH, ZPL, TSTEPS * ZSTRIDE);

    // [3] phase 2 (persistent AR rollout) — profiled launch
    phase2_kernel<<<128, 256, P2_SMEM>>>(b1, b2, b3, b4, W5, b5, Wih, bih, bhh,
                                         Z, Z + (size_t)P2_BASE, out);

    // [4..13] phase 1b: 2 chunks of 128 steps, bf16-pair MMA
    const int CHUNK = 128;
    const int MBIG  = CHUNK * BATCH;
    bf16* AH = (bf16*)A;
    bf16* AL = (bf16*)A + (size_t)MBIG * HID;
    bf16* BH = (bf16*)Bf;
    bf16* BL = (bf16*)Bf + (size_t)MBIG * HID;
    for (int c = 0; c < TSTEPS / CHUNK; c++) {
        const bf16* XzH = ZPH + (size_t)c * CHUNK * ZSTRIDE;
        const bf16* XzL = ZPL + (size_t)c * CHUNK * ZSTRIDE;
        gemm_mma_big<<<dim3(HID/64, MBIG/64), 256>>>(
            XzH, XzL, LAT, WHB + OFF_W1, WLB + OFF_W1, LAT, b1, AH, AL, HID, LAT);
        gemm_mma_big<<<dim3(HID/64, MBIG/64), 256>>>(
            AH, AL, HID, WHB + OFF_W2, WLB + OFF_W2, HID, b2, BH, BL, HID, HID);
        gemm_mma_big<<<dim3(HID/64, MBIG/64), 256>>>(
            BH, BL, HID, WHB + OFF_W3, WLB + OFF_W3, HID, b3, AH, AL, HID, HID);
        gemm_mma_big<<<dim3(HID/64, MBIG/64), 256>>>(
            AH, AL, HID, WHB + OFF_W4, WLB + OFF_W4, HID, b4, BH, BL, HID, HID);
        gemm_out_bf<<<dim3(1, MBIG/128), 256>>>(
            BH, BL, HID, W5, HID, b5, out, HID, c * CHUNK);
    }
}

// round 13
// speedup vs baseline: 2.1050x; 1.0174x over previous
#include <cuda_runtime.h>
#include <cuda_bf16.h>
#include <math.h>
#include <stdint.h>

#define BATCH   128
#define TSTEPS  256
#define HORIZON 512
#define OBS     32
#define LAT     256
#define HID     1024
#define ZSTRIDE (BATCH * LAT)

typedef __nv_bfloat16 bf16;

#define STAGE_W 5184
#define NSTAGE  4
#define P2_SMEM (NSTAGE * STAGE_W * 4)

#define S1B_W   10240          // 1b stage words: XH 0, XL 2560, WH 5120, WL 7680
#define NST1B   3
#define SMEM1B  (NST1B * S1B_W * 4)

// ---------------------------------------------------------------------------
// Scratch
// ---------------------------------------------------------------------------
__device__ float g_Z[(size_t)(HORIZON + 1) * ZSTRIDE];
__device__ float g_A[(size_t)128 * BATCH * HID];
__device__ float g_B[(size_t)128 * BATCH * HID];
__device__ bf16  g_ZPH[(size_t)TSTEPS * ZSTRIDE];
__device__ bf16  g_ZPL[(size_t)TSTEPS * ZSTRIDE];
__device__ bf16  g_WHB[3473408];
__device__ bf16  g_WLB[3473408];
__device__ unsigned g_gbar[4 * 32];

#define OFF_W1  0
#define OFF_W2  262144
#define OFF_W3  1310720
#define OFF_W4  2359296
#define OFF_WHH 3407872
#define NW_TOT  3473408

// phase-2 scratch carve (float offsets inside g_Z tail)
#define P2_BASE (320 * ZSTRIDE)
#define C_AH    0
#define C_AL    65536
#define C_BH    131072
#define C_BL    196608
#define C_ZH    262144
#define C_ZL    278528
#define C_C     294912
#define C_YP    327680

// ---------------------------------------------------------------------------
// helpers
// ---------------------------------------------------------------------------
__device__ __forceinline__ void mma16(float* d, const uint32_t* a, uint32_t b0, uint32_t b1) {
    asm volatile(
        "mma.sync.aligned.m16n8k16.row.col.f32.bf16.bf16.f32 "
        "{%0,%1,%2,%3},{%4,%5,%6,%7},{%8,%9},{%0,%1,%2,%3};"
        : "+f"(d[0]), "+f"(d[1]), "+f"(d[2]), "+f"(d[3])
        : "r"(a[0]), "r"(a[1]), "r"(a[2]), "r"(a[3]), "r"(b0), "r"(b1));
}
__device__ __forceinline__ void cpa16(uint32_t dst, const void* src) {
    asm volatile("cp.async.cg.shared.global [%0], [%1], 16;" :: "r"(dst), "l"(src));
}
__device__ __forceinline__ void wait_ahead(int rem) {
    if (rem >= 3)      asm volatile("cp.async.wait_group 3;" ::: "memory");
    else if (rem == 2) asm volatile("cp.async.wait_group 2;" ::: "memory");
    else if (rem == 1) asm volatile("cp.async.wait_group 1;" ::: "memory");
    else               asm volatile("cp.async.wait_group 0;" ::: "memory");
}
__device__ __forceinline__ void wait_1b(int rem) {
    if (rem >= 2)      asm volatile("cp.async.wait_group 2;" ::: "memory");
    else if (rem == 1) asm volatile("cp.async.wait_group 1;" ::: "memory");
    else               asm volatile("cp.async.wait_group 0;" ::: "memory");
}
__device__ __forceinline__ void split_pack(float v0, float v1, uint32_t& hw, uint32_t& lw) {
    bf16 h0 = __float2bfloat16(v0);
    bf16 h1 = __float2bfloat16(v1);
    bf16 l0 = __float2bfloat16(v0 - __bfloat162float(h0));
    bf16 l1 = __float2bfloat16(v1 - __bfloat162float(h1));
    hw = ((uint32_t)__bfloat16_as_ushort(h1) << 16) | __bfloat16_as_ushort(h0);
    lw = ((uint32_t)__bfloat16_as_ushort(l1) << 16) | __bfloat16_as_ushort(l0);
}
__device__ __forceinline__ float2 comb2(uint32_t h, uint32_t l) {
    float2 r;
    r.x = __bfloat162float(__ushort_as_bfloat16((unsigned short)(h & 0xffff)))
        + __bfloat162float(__ushort_as_bfloat16((unsigned short)(l & 0xffff)));
    r.y = __bfloat162float(__ushort_as_bfloat16((unsigned short)(h >> 16)))
        + __bfloat162float(__ushort_as_bfloat16((unsigned short)(l >> 16)));
    return r;
}

__device__ __forceinline__ void ggsync(int g, unsigned& target) {
    target += 32;
    __syncthreads();
    __threadfence();
    if (threadIdx.x == 0) {
        atomicAdd(&g_gbar[g * 32], 1u);
        while (*((volatile unsigned*)&g_gbar[g * 32]) < target) {}
        __threadfence();
    }
    __syncthreads();
}

__global__ void splitw_all(const float* __restrict__ W1, const float* __restrict__ W2,
                           const float* __restrict__ W3, const float* __restrict__ W4,
                           const float* __restrict__ Whh)
{
    int i = blockIdx.x * 256 + threadIdx.x;
    if (i >= NW_TOT) return;
    const float* src; int off;
    if (i < OFF_W2)       { src = W1;  off = OFF_W1; }
    else if (i < OFF_W3)  { src = W2;  off = OFF_W2; }
    else if (i < OFF_W4)  { src = W3;  off = OFF_W3; }
    else if (i < OFF_WHH) { src = W4;  off = OFF_W4; }
    else                  { src = Whh; off = OFF_WHH; }
    float v = src[i - off];
    bf16 h = __float2bfloat16(v);
    g_WHB[i] = h;
    g_WLB[i] = __float2bfloat16(v - __bfloat162float(h));
}

__global__ void splitw_bf16(const float* __restrict__ src,
                            bf16* __restrict__ hi, bf16* __restrict__ lo, int n)
{
    int i = blockIdx.x * 256 + threadIdx.x;
    if (i < n) {
        float v = src[i];
        bf16 h = __float2bfloat16(v);
        hi[i] = h;
        lo[i] = __float2bfloat16(v - __bfloat162float(h));
    }
}

// ---------------------------------------------------------------------------
// Phase 1a (unchanged; zeroes group barriers)
// ---------------------------------------------------------------------------
__global__ void __launch_bounds__(256) phase1a_kernel(
    const float* __restrict__ y,
    const float* __restrict__ Wih, const float* __restrict__ Whh,
    const float* __restrict__ bih, const float* __restrict__ bhh,
    float* __restrict__ Z)
{
    const int b = blockIdx.x, tid = threadIdx.x;
    __shared__ float sz[LAT];
    __shared__ float sy[OBS];

    if (b == 0 && tid < 128) g_gbar[tid] = 0u;

    sz[tid] = 0.0f;
    __stcg(Z + (size_t)b * LAT + tid, 0.0f);
    float bsum = __ldg(bih + tid) + __ldg(bhh + tid);

    float4 wi[8];
    const float4* wip = (const float4*)(Wih + (size_t)tid * OBS);
#pragma unroll
    for (int k = 0; k < 8; k++) wi[k] = __ldg(wip + k);
    const float4* wh = (const float4*)(Whh + (size_t)tid * LAT);
    __syncthreads();

    for (int t = 0; t < TSTEPS; t++) {
        if (tid < OBS) sy[tid] = __ldg(y + ((size_t)b * TSTEPS + t) * OBS + tid);
        __syncthreads();
        float acc = bsum;
#pragma unroll
        for (int k = 0; k < 8; k++) {
            float4 w = wi[k];
            acc += sy[k*4+0]*w.x + sy[k*4+1]*w.y + sy[k*4+2]*w.z + sy[k*4+3]*w.w;
        }
#pragma unroll 8
        for (int k = 0; k < 64; k++) {
            float4 w = __ldg(wh + k);
            acc += sz[k*4+0]*w.x + sz[k*4+1]*w.y + sz[k*4+2]*w.z + sz[k*4+3]*w.w;
        }
        float zn = tanhf(acc);
        __syncthreads();
        sz[tid] = zn;
        __stcg(Z + ((size_t)t + 1) * ZSTRIDE + (size_t)b * LAT + tid, zn);
    }
}

// ---------------------------------------------------------------------------
// Phase 1b bf16-pair MMA GEMM: 128x128 tile, 3-stage cp.async, dynamic smem.
// 8 warps = 2m x 4n; warp tile 64m x 32n (f=4, g=4).
// ---------------------------------------------------------------------------
__global__ void __launch_bounds__(256) gemm_mma_128(
    const bf16* __restrict__ Xh, const bf16* __restrict__ Xl, int ldx,
    const bf16* __restrict__ Wh, const bf16* __restrict__ Wl, int ldw,
    const float* __restrict__ bias,
    bf16* __restrict__ Yh, bf16* __restrict__ Yl, int ldy, int K)
{
    extern __shared__ __align__(16) uint32_t SW[];
    const uint32_t sbase = (uint32_t)__cvta_generic_to_shared(SW);
    const int tid = threadIdx.x, lane = tid & 31, wid = tid >> 5;
    const int mw = wid >> 2, nw = wid & 3;
    const int mB = blockIdx.y * 128, nB = blockIdx.x * 128;
    const int nch = K >> 5;

    auto issue = [&](int c, int s) {
        const int k0 = c << 5;
        const uint32_t base = (uint32_t)s * (uint32_t)S1B_W;
#pragma unroll
        for (int ii = 0; ii < 8; ii++) {
            const int o = tid + ii * 256;
            const int p = o >> 9, q = o & 511, row = q >> 2, sg = q & 3;
            const uint32_t dw = base + (uint32_t)p * 2560u + row * 20u + sg * 4u;
            const bf16* src;
            if (p == 0)      src = Xh + (size_t)(mB + row) * ldx + k0 + sg * 8;
            else if (p == 1) src = Xl + (size_t)(mB + row) * ldx + k0 + sg * 8;
            else if (p == 2) src = Wh + (size_t)(nB + row) * ldw + k0 + sg * 8;
            else             src = Wl + (size_t)(nB + row) * ldw + k0 + sg * 8;
            cpa16(sbase + dw * 4u, src);
        }
        asm volatile("cp.async.commit_group;" ::: "memory");
    };

    float acc[4][4][4];
#pragma unroll
    for (int f = 0; f < 4; f++)
#pragma unroll
        for (int g = 0; g < 4; g++)
#pragma unroll
            for (int i = 0; i < 4; i++) acc[f][g][i] = 0.0f;

#pragma unroll
    for (int c0 = 0; c0 < NST1B; c0++)
        if (c0 < nch) issue(c0, c0);

    const int arow = lane >> 2, acol = lane & 3;
    int stage = 0;

    for (int c = 0; c < nch; c++) {
        wait_1b(nch - 1 - c);
        __syncthreads();
        const uint32_t* S   = SW + stage * S1B_W;
        const uint32_t* XHs = S;
        const uint32_t* XLs = S + 2560;
        const uint32_t* WHs = S + 5120;
        const uint32_t* WLs = S + 7680;
#pragma unroll
        for (int wb = 0; wb < 16; wb += 8) {
            uint32_t bh[4][2], bl[4][2];
#pragma unroll
            for (int g = 0; g < 4; g++) {
                int boff = (nw * 32 + g * 8 + arow) * 20 + acol + wb;
                bh[g][0] = WHs[boff]; bh[g][1] = WHs[boff + 4];
                bl[g][0] = WLs[boff]; bl[g][1] = WLs[boff + 4];
            }
#pragma unroll
            for (int f = 0; f < 4; f++) {
                int r = mw * 64 + f * 16 + arow;
                int aoff  = r * 20 + acol + wb;
                int aoff8 = (r + 8) * 20 + acol + wb;
                uint32_t ah[4] = {XHs[aoff], XHs[aoff8], XHs[aoff + 4], XHs[aoff8 + 4]};
                uint32_t al[4] = {XLs[aoff], XLs[aoff8], XLs[aoff + 4], XLs[aoff8 + 4]};
#pragma unroll
                for (int g = 0; g < 4; g++) {
                    mma16(acc[f][g], ah, bh[g][0], bh[g][1]);
                    mma16(acc[f][g], ah, bl[g][0], bl[g][1]);
                    mma16(acc[f][g], al, bh[g][0], bh[g][1]);
                }
            }
        }
        __syncthreads();
        if (c + NST1B < nch) {
            issue(c + NST1B, stage);
        }
        stage = (stage == NST1B - 1) ? 0 : stage + 1;
    }

#pragma unroll
    for (int f = 0; f < 4; f++) {
#pragma unroll
        for (int g = 0; g < 4; g++) {
            const int r0 = mB + mw * 64 + f * 16 + arow;
            const int col = nB + nw * 32 + g * 8 + acol * 2;
            float2 bb = *(const float2*)(bias + col);
            float v0 = fmaxf(acc[f][g][0] + bb.x, 0.f);
            float v1 = fmaxf(acc[f][g][1] + bb.y, 0.f);
            float v2 = fmaxf(acc[f][g][2] + bb.x, 0.f);
            float v3 = fmaxf(acc[f][g][3] + bb.y, 0.f);
            uint32_t hw, lw;
            split_pack(v0, v1, hw, lw);
            __stcg((uint32_t*)&Yh[(size_t)r0 * ldy + col], hw);
            __stcg((uint32_t*)&Yl[(size_t)r0 * ldy + col], lw);
            split_pack(v2, v3, hw, lw);
            __stcg((uint32_t*)&Yh[(size_t)(r0 + 8) * ldy + col], hw);
            __stcg((uint32_t*)&Yl[(size_t)(r0 + 8) * ldy + col], lw);
        }
    }
}

// ---------------------------------------------------------------------------
// Phase 1b output layer (unchanged)
// ---------------------------------------------------------------------------
__global__ void __launch_bounds__(256) gemm_out_bf(
    const bf16* __restrict__ Xh, const bf16* __restrict__ Xl, int ldx,
    const float* __restrict__ W, int ldw,
    const float* __restrict__ bias,
    float* __restrict__ out, int K, int t0)
{
    __shared__ __align__(16) float sX[16 * 132];
    __shared__ __align__(16) float sW[16 * 36];
    const int tid = threadIdx.x;
    const int ty = tid >> 4, tx = tid & 15;
    const int mB = blockIdx.y * 128;
    const int xr = tid >> 2, xc = tid & 3;

    const bf16* XpH0 = Xh + (size_t)(mB + xr) * ldx + xc * 4;
    const bf16* XpL0 = Xl + (size_t)(mB + xr) * ldx + xc * 4;
    const bf16* XpH1 = XpH0 + (size_t)64 * ldx;
    const bf16* XpL1 = XpL0 + (size_t)64 * ldx;
    const bool wp = tid < 128;
    const float* Wp = W + (size_t)xr * ldw + xc * 4;

    uint2 xh0 = __ldg((const uint2*)XpH0);
    uint2 xl0 = __ldg((const uint2*)XpL0);
    uint2 xh1 = __ldg((const uint2*)XpH1);
    uint2 xl1 = __ldg((const uint2*)XpL1);
    float4 wv = make_float4(0,0,0,0);
    if (wp) wv = __ldg((const float4*)Wp);

    float acc[8][2];
#pragma unroll
    for (int i = 0; i < 8; i++) { acc[i][0] = 0.f; acc[i][1] = 0.f; }

    for (int k0 = 0;;) {
        {
            float2 a = comb2(xh0.x, xl0.x), b = comb2(xh0.y, xl0.y);
            sX[(xc*4+0)*132 + xr] = a.x; sX[(xc*4+1)*132 + xr] = a.y;
            sX[(xc*4+2)*132 + xr] = b.x; sX[(xc*4+3)*132 + xr] = b.y;
            float2 c = comb2(xh1.x, xl1.x), d = comb2(xh1.y, xl1.y);
            sX[(xc*4+0)*132 + xr+64] = c.x; sX[(xc*4+1)*132 + xr+64] = c.y;
            sX[(xc*4+2)*132 + xr+64] = d.x; sX[(xc*4+3)*132 + xr+64] = d.y;
        }
        if (wp) {
            sW[(xc*4+0)*36 + xr] = wv.x; sW[(xc*4+1)*36 + xr] = wv.y;
            sW[(xc*4+2)*36 + xr] = wv.z; sW[(xc*4+3)*36 + xr] = wv.w;
        }
        __syncthreads();
        const int k1 = k0 + 16;
        if (k1 < K) {
            xh0 = __ldg((const uint2*)(XpH0 + k1));
            xl0 = __ldg((const uint2*)(XpL0 + k1));
            xh1 = __ldg((const uint2*)(XpH1 + k1));
            xl1 = __ldg((const uint2*)(XpL1 + k1));
            if (wp) wv = __ldg((const float4*)(Wp + k1));
        }
#pragma unroll
        for (int kk = 0; kk < 16; kk++) {
            float4 a0 = *(const float4*)&sX[kk*132 + ty*8];
            float4 a1 = *(const float4*)&sX[kk*132 + ty*8 + 4];
            float2 b  = *(const float2*)&sW[kk*36 + tx*2];
            acc[0][0]+=a0.x*b.x; acc[0][1]+=a0.x*b.y;
            acc[1][0]+=a0.y*b.x; acc[1][1]+=a0.y*b.y;
            acc[2][0]+=a0.z*b.x; acc[2][1]+=a0.z*b.y;
            acc[3][0]+=a0.w*b.x; acc[3][1]+=a0.w*b.y;
            acc[4][0]+=a1.x*b.x; acc[4][1]+=a1.x*b.y;
            acc[5][0]+=a1.y*b.x; acc[5][1]+=a1.y*b.y;
            acc[6][0]+=a1.z*b.x; acc[6][1]+=a1.z*b.y;
            acc[7][0]+=a1.w*b.x; acc[7][1]+=a1.w*b.y;
        }
        __syncthreads();
        if (k1 >= K) break;
        k0 = k1;
    }

    float2 bb = *(const float2*)(bias + tx * 2);
#pragma unroll
    for (int i = 0; i < 8; i++) {
        int r = mB + ty * 8 + i;
        int b = r & (BATCH - 1);
        int t = t0 + (r >> 7);
        float2 v = make_float2(acc[i][0] + bb.x, acc[i][1] + bb.y);
        *(float2*)(out + ((size_t)b * HORIZON + t) * OBS + tx * 2) = v;
    }
}

// ---------------------------------------------------------------------------
// Phase-2: W prologue, issued BEFORE the barrier that precedes a region.
// Loads W (and V for DOWHH) parts of stages 0..3; always 4 commit groups.
// ---------------------------------------------------------------------------
template<bool DOV>
__device__ __forceinline__ void prologueW(
    uint32_t sbase, int nT, int K,
    const bf16* __restrict__ Wh, const bf16* __restrict__ Wl, int ldw,
    const bf16* __restrict__ Vh, const bf16* __restrict__ Vl, int whCol0)
{
    const int tid = threadIdx.x;
    const int nch = K >> 6;
#pragma unroll
    for (int s = 0; s < NSTAGE; s++) {
        if (s < nch) {
            const int k0 = s << 6;
            const uint32_t base = (uint32_t)s * (uint32_t)STAGE_W;
#pragma unroll
            for (int ii = 0; ii < 2; ii++) {
                const int o = tid + ii * 256;
                const int p = o >> 8, q = o & 255, row = q >> 3, sg = q & 7;
                const uint32_t dw = base + 2304u + (uint32_t)p * 1152u + row * 36u + sg * 4u;
                const bf16* src = (p ? Wl : Wh) + (size_t)(nT + row) * ldw + k0 + sg * 8;
                cpa16(sbase + dw * 4u, src);
            }
            if (DOV && tid < 128) {
                const int p = tid >> 6, q = tid & 63, row = q >> 3, sg = q & 7;
                const uint32_t dw = base + 4608u + (uint32_t)p * 288u + row * 36u + sg * 4u;
                const bf16* src = (p ? Vl : Vh) + (size_t)(whCol0 + row) * 256 + k0 + sg * 8;
                cpa16(sbase + dw * 4u, src);
            }
        }
        asm volatile("cp.async.commit_group;" ::: "memory");
    }
}

// ---------------------------------------------------------------------------
// Phase-2 region: X prologue (4 groups) + combined steady-state.
// W (and V) for stages 0..3 must have been pre-issued via prologueW.
// ---------------------------------------------------------------------------
template<bool RELU, bool DOWHH, bool DOL5>
__device__ void mma_region(
    uint32_t* SW, uint32_t sbase,
    int mT, int nT, int K,
    const bf16* __restrict__ Xh, const bf16* __restrict__ Xl, int ldx,
    const bf16* __restrict__ Wh, const bf16* __restrict__ Wl, int ldw,
    const float* __restrict__ bias,
    bf16* __restrict__ Yh, bf16* __restrict__ Yl, int ldy,
    float* __restrict__ Cout, int whCol0,
    const float* __restrict__ W5, float* __restrict__ yhpart, int jIdx)
{
    const int tid = threadIdx.x, lane = tid & 31, wid = tid >> 5;
    const int mw = wid >> 2, nw = wid & 3;
    const int nch = K >> 6;

    // X prologue: 4 commit groups (X planes only)
#pragma unroll
    for (int s = 0; s < NSTAGE; s++) {
        if (s < nch) {
            const int k0 = s << 6;
            const uint32_t base = (uint32_t)s * (uint32_t)STAGE_W;
#pragma unroll
            for (int ii = 0; ii < 2; ii++) {
                const int o = tid + ii * 256;
                const int p = o >> 8, q = o & 255, row = q >> 3, sg = q & 7;
                const uint32_t dw = base + (uint32_t)p * 1152u + row * 36u + sg * 4u;
                const bf16* src = (p ? Xl : Xh) + (size_t)(mT + row) * ldx + k0 + sg * 8;
                cpa16(sbase + dw * 4u, src);
            }
        }
        asm volatile("cp.async.commit_group;" ::: "memory");
    }

    // combined steady-state issue (X + W)
    auto issueC = [&](int c, int s) {
        const int k0 = c << 6;
        const uint32_t base = (uint32_t)s * (uint32_t)STAGE_W;
#pragma unroll
        for (int ii = 0; ii < 4; ii++) {
            const int o = tid + ii * 256;
            const int p = o >> 8, q = o & 255, row = q >> 3, sg = q & 7;
            const uint32_t dw = base + (uint32_t)p * 1152u + row * 36u + sg * 4u;
            const bf16* src;
            if (p == 0)      src = Xh + (size_t)(mT + row) * ldx + k0 + sg * 8;
            else if (p == 1) src = Xl + (size_t)(mT + row) * ldx + k0 + sg * 8;
            else if (p == 2) src = Wh + (size_t)(nT + row) * ldw + k0 + sg * 8;
            else             src = Wl + (size_t)(nT + row) * ldw + k0 + sg * 8;
            cpa16(sbase + dw * 4u, src);
        }
        asm volatile("cp.async.commit_group;" ::: "memory");
    };

    float ahh[4] = {0,0,0,0}, ahl[4] = {0,0,0,0}, alh[4] = {0,0,0,0};
    float whh[4] = {0,0,0,0}, whl[4] = {0,0,0,0}, wlh[4] = {0,0,0,0};

    const int r0 = mw * 16 + (lane >> 2);
    const int wc = lane & 3;
    const int aoff0 = r0 * 36 + wc;
    const int aoff1 = (r0 + 8) * 36 + wc;
    const int boff = (nw * 8 + (lane >> 2)) * 36 + wc;
    const int voff = (lane >> 2) * 36 + wc;

    for (int c = 0; c < nch; c++) {
        wait_ahead(nch - 1 - c);
        __syncthreads();
        const uint32_t* S   = SW + (c & (NSTAGE - 1)) * STAGE_W;
        const uint32_t* XHs = S;
        const uint32_t* XLs = S + 1152;
        const uint32_t* WHs = S + 2304;
        const uint32_t* WLs = S + 3456;
        const uint32_t* VHs = S + 4608;
        const uint32_t* VLs = S + 4896;
#pragma unroll
        for (int wb = 0; wb < 32; wb += 8) {
            uint32_t ah[4], al[4];
            ah[0] = XHs[aoff0 + wb];     ah[1] = XHs[aoff1 + wb];
            ah[2] = XHs[aoff0 + wb + 4]; ah[3] = XHs[aoff1 + wb + 4];
            al[0] = XLs[aoff0 + wb];     al[1] = XLs[aoff1 + wb];
            al[2] = XLs[aoff0 + wb + 4]; al[3] = XLs[aoff1 + wb + 4];
            uint32_t bh0 = WHs[boff + wb], bh1 = WHs[boff + wb + 4];
            uint32_t bl0 = WLs[boff + wb], bl1 = WLs[boff + wb + 4];
            mma16(ahh, ah, bh0, bh1);
            mma16(ahl, ah, bl0, bl1);
            mma16(alh, al, bh0, bh1);
            if (DOWHH && nw == 0) {
                uint32_t vh0 = VHs[voff + wb], vh1 = VHs[voff + wb + 4];
                uint32_t vl0 = VLs[voff + wb], vl1 = VLs[voff + wb + 4];
                mma16(whh, ah, vh0, vh1);
                mma16(whl, ah, vl0, vl1);
                mma16(wlh, al, vh0, vh1);
            }
        }
        __syncthreads();
        if (c + NSTAGE < nch) issueC(c + NSTAGE, (c + NSTAGE) & (NSTAGE - 1));
    }

    const int orow = mT + r0;
    const int ocol_l = nw * 8 + wc * 2;
    const int ocol = nT + ocol_l;
    float2 bb = *(const float2*)(bias + ocol);
    float v0 = ahh[0] + ahl[0] + alh[0] + bb.x;
    float v1 = ahh[1] + ahl[1] + alh[1] + bb.y;
    float v2 = ahh[2] + ahl[2] + alh[2] + bb.x;
    float v3 = ahh[3] + ahl[3] + alh[3] + bb.y;
    if (RELU) {
        v0 = fmaxf(v0, 0.f); v1 = fmaxf(v1, 0.f);
        v2 = fmaxf(v2, 0.f); v3 = fmaxf(v3, 0.f);
    }

    if (DOL5) {
        float* sh4 = (float*)SW;
        sh4[r0 * 33 + ocol_l]           = v0;
        sh4[r0 * 33 + ocol_l + 1]       = v1;
        sh4[(r0 + 8) * 33 + ocol_l]     = v2;
        sh4[(r0 + 8) * 33 + ocol_l + 1] = v3;
        __syncthreads();
        const float* w5r = W5 + (size_t)lane * HID + nT;
        float w5f[32];
#pragma unroll
        for (int q = 0; q < 8; q++) {
            float4 w = __ldg((const float4*)(w5r + q * 4));
            w5f[q*4+0] = w.x; w5f[q*4+1] = w.y; w5f[q*4+2] = w.z; w5f[q*4+3] = w.w;
        }
#pragma unroll
        for (int i = 0; i < 4; i++) {
            const int r = wid * 4 + i;
            const float* hr = sh4 + r * 33;
            float s = 0.f;
#pragma unroll
            for (int n = 0; n < 32; n++) s += hr[n] * w5f[n];
            __stcg(yhpart + (size_t)jIdx * (BATCH * 32) + (mT + r) * 32 + lane, s);
        }
    } else {
        uint32_t hw, lw;
        split_pack(v0, v1, hw, lw);
        __stcg((uint32_t*)&Yh[(size_t)orow * ldy + ocol], hw);
        __stcg((uint32_t*)&Yl[(size_t)orow * ldy + ocol], lw);
        split_pack(v2, v3, hw, lw);
        __stcg((uint32_t*)&Yh[(size_t)(orow + 8) * ldy + ocol], hw);
        __stcg((uint32_t*)&Yl[(size_t)(orow + 8) * ldy + ocol], lw);
    }

    if (DOWHH && nw == 0) {
        const int wcol = whCol0 + wc * 2;
        __stcg((float2*)&Cout[(size_t)orow * LAT + wcol],
               make_float2(whh[0]+whl[0]+wlh[0], whh[1]+whl[1]+wlh[1]));
        __stcg((float2*)&Cout[(size_t)(orow + 8) * LAT + wcol],
               make_float2(whh[2]+whl[2]+wlh[2], whh[3]+whl[3]+wlh[3]));
    }
}

// ---------------------------------------------------------------------------
// Phase 2: 128 CTAs, 4 groups of 32, 5 barriers/step, W prefetched over them.
// ---------------------------------------------------------------------------
__global__ void __launch_bounds__(256, 1) phase2_kernel(
    const float* __restrict__ b1, const float* __restrict__ b2,
    const float* __restrict__ b3, const float* __restrict__ b4,
    const float* __restrict__ W5, const float* __restrict__ b5,
    const float* __restrict__ Wih,
    const float* __restrict__ bih, const float* __restrict__ bhh,
    const float* __restrict__ Z,
    float* __restrict__ PL,
    float* __restrict__ out)
{
    extern __shared__ __align__(16) uint32_t SW[];
    const uint32_t sbase = (uint32_t)__cvta_generic_to_shared(SW);
    const int bid = blockIdx.x, tid = threadIdx.x;
    const int g = bid >> 5, j = bid & 31;
    const int mT = g * 32, nT = j * 32;
    const int b = bid;
    unsigned target = 0;

    bf16* AH = (bf16*)(PL + C_AH);
    bf16* AL = (bf16*)(PL + C_AL);
    bf16* BH = (bf16*)(PL + C_BH);
    bf16* BL = (bf16*)(PL + C_BL);
    bf16* ZH = (bf16*)(PL + C_ZH);
    bf16* ZL = (bf16*)(PL + C_ZL);
    float* C  = PL + C_C;
    float* YP = PL + C_YP;

    const bf16 *W1H = g_WHB + OFF_W1,  *W1L = g_WLB + OFF_W1;
    const bf16 *W2H = g_WHB + OFF_W2,  *W2L = g_WLB + OFF_W2;
    const bf16 *W3H = g_WHB + OFF_W3,  *W3L = g_WLB + OFF_W3;
    const bf16 *W4H = g_WHB + OFF_W4,  *W4L = g_WLB + OFF_W4;
    const bf16 *VH  = g_WHB + OFF_WHH, *VL  = g_WLB + OFF_WHH;

    if (tid < 128) {
        float2 z2 = __ldcg((const float2*)(Z + (size_t)TSTEPS * ZSTRIDE + (size_t)b * LAT) + tid);
        uint32_t hw, lw;
        split_pack(z2.x, z2.y, hw, lw);
        __stcg((uint32_t*)(ZH + (size_t)b * LAT) + tid, hw);
        __stcg((uint32_t*)(ZL + (size_t)b * LAT) + tid, lw);
    }
    // prefetch R1 weights + Whh strip before the init barrier
    prologueW<true>(sbase, nT, LAT, W1H, W1L, LAT, VH, VL, j * 8);
    ggsync(g, target);

    for (int t = TSTEPS; t < HORIZON; t++) {
        mma_region<true, true, false>(SW, sbase, mT, nT, LAT,
                               ZH, ZL, LAT, W1H, W1L, LAT,
                               b1, AH, AL, HID, C, j * 8,
                               (const float*)0, (float*)0, 0);
        prologueW<false>(sbase, nT, HID, W2H, W2L, HID, (const bf16*)0, (const bf16*)0, 0);
        ggsync(g, target);
        mma_region<true, false, false>(SW, sbase, mT, nT, HID,
                                AH, AL, HID, W2H, W2L, HID,
                                b2, BH, BL, HID, (float*)0, 0,
                                (const float*)0, (float*)0, 0);
        prologueW<false>(sbase, nT, HID, W3H, W3L, HID, (const bf16*)0, (const bf16*)0, 0);
        ggsync(g, target);
        mma_region<true, false, false>(SW, sbase, mT, nT, HID,
                                BH, BL, HID, W3H, W3L, HID,
                                b3, AH, AL, HID, (float*)0, 0,
                                (const float*)0, (float*)0, 0);
        prologueW<false>(sbase, nT, HID, W4H, W4L, HID, (const bf16*)0, (const bf16*)0, 0);
        ggsync(g, target);
        mma_region<true, false, true>(SW, sbase, mT, nT, HID,
                                AH, AL, HID, W4H, W4L, HID,
                                b4, (bf16*)0, (bf16*)0, HID, (float*)0, 0,
                                W5, YP, j);
        ggsync(g, target);

        // R5: combine yh partials -> out; cell finish
        {
            float* FS = (float*)SW;
            if (tid < OBS) {
                float s = __ldg(b5 + tid);
                const float* yp = YP + (size_t)b * 32 + tid;
#pragma unroll
                for (int jj = 0; jj < 32; jj++)
                    s += __ldcg(yp + (size_t)jj * (BATCH * 32));
                __stcg(out + ((size_t)b * HORIZON + t) * OBS + tid, s);
                FS[tid] = s;
            }
            __syncthreads();
            if (t < HORIZON - 1) {
                const int n = tid;
                float acc = __ldcg(C + (size_t)b * LAT + n)
                          + __ldg(bih + n) + __ldg(bhh + n);
                const float4* wr = (const float4*)(Wih + (size_t)n * OBS);
#pragma unroll
                for (int k = 0; k < 8; k++) {
                    float4 wv = __ldg(wr + k);
                    acc += FS[k*4+0]*wv.x + FS[k*4+1]*wv.y
                         + FS[k*4+2]*wv.z + FS[k*4+3]*wv.w;
                }
                FS[64 + n] = tanhf(acc);
                __syncthreads();
                if (tid < 128) {
                    float z0 = FS[64 + 2*tid], z1 = FS[64 + 2*tid + 1];
                    uint32_t hw, lw;
                    split_pack(z0, z1, hw, lw);
                    __stcg((uint32_t*)(ZH + (size_t)b * LAT) + tid, hw);
                    __stcg((uint32_t*)(ZL + (size_t)b * LAT) + tid, lw);
                }
                __syncthreads();
                // prefetch next step's R1 weights across the final barrier
                prologueW<true>(sbase, nT, LAT, W1H, W1L, LAT, VH, VL, j * 8);
            }
        }
        ggsync(g, target);
    }
}

// ---------------------------------------------------------------------------
// Launch (phase2 at our launch index 3 for ncu)
// ---------------------------------------------------------------------------
extern "C" void kernel_launch(void* const* d_in, const int* in_sizes, int n_in,
                              void* d_out, int out_size)
{
    const float* y   = (const float*)d_in[0];
    const float* Wih = (const float*)d_in[2];
    const float* Whh = (const float*)d_in[3];
    const float* bih = (const float*)d_in[4];
    const float* bhh = (const float*)d_in[5];
    const float* W1  = (const float*)d_in[6];
    const float* b1  = (const float*)d_in[7];
    const float* W2  = (const float*)d_in[8];
    const float* b2  = (const float*)d_in[9];
    const float* W3  = (const float*)d_in[10];
    const float* b3  = (const float*)d_in[11];
    const float* W4  = (const float*)d_in[12];
    const float* b4  = (const float*)d_in[13];
    const float* W5  = (const float*)d_in[14];
    const float* b5  = (const float*)d_in[15];
    float* out = (float*)d_out;

    float *Z, *A, *Bf;
    bf16 *WHB, *WLB, *ZPH, *ZPL;
    cudaGetSymbolAddress((void**)&Z,    g_Z);
    cudaGetSymbolAddress((void**)&A,    g_A);
    cudaGetSymbolAddress((void**)&Bf,   g_B);
    cudaGetSymbolAddress((void**)&WHB,  g_WHB);
    cudaGetSymbolAddress((void**)&WLB,  g_WLB);
    cudaGetSymbolAddress((void**)&ZPH,  g_ZPH);
    cudaGetSymbolAddress((void**)&ZPL,  g_ZPL);

    static int attr_done = 0;
    if (!attr_done) {
        cudaFuncSetAttribute(phase2_kernel,
                             cudaFuncAttributeMaxDynamicSharedMemorySize, P2_SMEM);
        cudaFuncSetAttribute(gemm_mma_128,
                             cudaFuncAttributeMaxDynamicSharedMemorySize, SMEM1B);
        attr_done = 1;
    }

    // [0] fused weight hi/lo split
    splitw_all<<<(NW_TOT + 255)/256, 256>>>(W1, W2, W3, W4, Whh);

    // [1] phase 1a (also zeroes group barriers)
    phase1a_kernel<<<BATCH, 256>>>(y, Wih, Whh, bih, bhh, Z);

    // [2] split teacher-forced z states into bf16 planes
    splitw_bf16<<<(TSTEPS * ZSTRIDE + 255)/256, 256>>>(Z, ZPH, ZPL, TSTEPS * ZSTRIDE);

    // [3] phase 2 (persistent AR rollout) — profiled launch
    phase2_kernel<<<128, 256, P2_SMEM>>>(b1, b2, b3, b4, W5, b5, Wih, bih, bhh,
                                         Z, Z + (size_t)P2_BASE, out);

    // [4..13] phase 1b: 2 chunks of 128 steps, bf16-pair MMA (128x128 tiles)
    const int CHUNK = 128;
    const int MBIG  = CHUNK * BATCH;
    bf16* AH = (bf16*)A;
    bf16* AL = (bf16*)A + (size_t)MBIG * HID;
    bf16* BH = (bf16*)Bf;
    bf16* BL = (bf16*)Bf + (size_t)MBIG * HID;
    for (int c = 0; c < TSTEPS / CHUNK; c++) {
        const bf16* XzH = ZPH + (size_t)c * CHUNK * ZSTRIDE;
        const bf16* XzL = ZPL + (size_t)c * CHUNK * ZSTRIDE;
        gemm_mma_128<<<dim3(HID/128, MBIG/128), 256, SMEM1B>>>(
            XzH, XzL, LAT, WHB + OFF_W1, WLB + OFF_W1, LAT, b1, AH, AL, HID, LAT);
        gemm_mma_128<<<dim3(HID/128, MBIG/128), 256, SMEM1B>>>(
            AH, AL, HID, WHB + OFF_W2, WLB + OFF_W2, HID, b2, BH, BL, HID, HID);
        gemm_mma_128<<<dim3(HID/128, MBIG/128), 256, SMEM1B>>>(
            BH, BL, HID, WHB + OFF_W3, WLB + OFF_W3, HID, b3, AH, AL, HID, HID);
        gemm_mma_128<<<dim3(HID/128, MBIG/128), 256, SMEM1B>>>(
            AH, AL, HID, WHB + OFF_W4, WLB + OFF_W4, HID, b4, BH, BL, HID, HID);
        gemm_out_bf<<<dim3(1, MBIG/128), 256>>>(
            BH, BL, HID, W5, HID, b5, out, HID, c * CHUNK);
    }
}

// round 14
// speedup vs baseline: 2.1706x; 1.0311x over previous
#include <cuda_runtime.h>
#include <cuda_bf16.h>
#include <math.h>
#include <stdint.h>

#define BATCH   128
#define TSTEPS  256
#define HORIZON 512
#define OBS     32
#define LAT     256
#define HID     1024
#define ZSTRIDE (BATCH * LAT)

typedef __nv_bfloat16 bf16;

#define STAGE_W 5184
#define NSTAGE  4
#define P2_SMEM (NSTAGE * STAGE_W * 4)

#define S1B_W   10240
#define NST1B   3
#define SMEM1B  (NST1B * S1B_W * 4)

// ---------------------------------------------------------------------------
// Scratch
// ---------------------------------------------------------------------------
__device__ float g_Z[(size_t)(HORIZON + 1) * ZSTRIDE];
__device__ float g_A[(size_t)128 * BATCH * HID];
__device__ float g_B[(size_t)128 * BATCH * HID];
__device__ bf16  g_ZPH[(size_t)TSTEPS * ZSTRIDE];
__device__ bf16  g_ZPL[(size_t)TSTEPS * ZSTRIDE];
__device__ bf16  g_WHB[3473408];
__device__ bf16  g_WLB[3473408];
__device__ unsigned g_gbar[4 * 32];

#define OFF_W1  0
#define OFF_W2  262144
#define OFF_W3  1310720
#define OFF_W4  2359296
#define OFF_WHH 3407872
#define NW_TOT  3473408

#define P2_BASE (320 * ZSTRIDE)
#define C_AH    0
#define C_AL    65536
#define C_BH    131072
#define C_BL    196608
#define C_ZH    262144
#define C_ZL    278528
#define C_C     294912
#define C_YP    327680

// smem scratch offsets (floats, inside stage 0 after pipeline is drained)
#define RED_OFF   0        // 32 x 33 main reduce
#define REDW_OFF  1100     // 32 x 9 Whh reduce
#define SH4_OFF   1408     // 32 x 33 h4 staging

// ---------------------------------------------------------------------------
// helpers
// ---------------------------------------------------------------------------
__device__ __forceinline__ void mma16(float* d, const uint32_t* a, uint32_t b0, uint32_t b1) {
    asm volatile(
        "mma.sync.aligned.m16n8k16.row.col.f32.bf16.bf16.f32 "
        "{%0,%1,%2,%3},{%4,%5,%6,%7},{%8,%9},{%0,%1,%2,%3};"
        : "+f"(d[0]), "+f"(d[1]), "+f"(d[2]), "+f"(d[3])
        : "r"(a[0]), "r"(a[1]), "r"(a[2]), "r"(a[3]), "r"(b0), "r"(b1));
}
__device__ __forceinline__ void cpa16(uint32_t dst, const void* src) {
    asm volatile("cp.async.cg.shared.global [%0], [%1], 16;" :: "r"(dst), "l"(src));
}
__device__ __forceinline__ void barh(int h) {
    asm volatile("bar.sync %0, 256;" :: "r"(h + 1) : "memory");
}
__device__ __forceinline__ void wait_1b(int rem) {
    if (rem >= 2)      asm volatile("cp.async.wait_group 2;" ::: "memory");
    else if (rem == 1) asm volatile("cp.async.wait_group 1;" ::: "memory");
    else               asm volatile("cp.async.wait_group 0;" ::: "memory");
}
__device__ __forceinline__ void split_pack(float v0, float v1, uint32_t& hw, uint32_t& lw) {
    bf16 h0 = __float2bfloat16(v0);
    bf16 h1 = __float2bfloat16(v1);
    bf16 l0 = __float2bfloat16(v0 - __bfloat162float(h0));
    bf16 l1 = __float2bfloat16(v1 - __bfloat162float(h1));
    hw = ((uint32_t)__bfloat16_as_ushort(h1) << 16) | __bfloat16_as_ushort(h0);
    lw = ((uint32_t)__bfloat16_as_ushort(l1) << 16) | __bfloat16_as_ushort(l0);
}
__device__ __forceinline__ float2 comb2(uint32_t h, uint32_t l) {
    float2 r;
    r.x = __bfloat162float(__ushort_as_bfloat16((unsigned short)(h & 0xffff)))
        + __bfloat162float(__ushort_as_bfloat16((unsigned short)(l & 0xffff)));
    r.y = __bfloat162float(__ushort_as_bfloat16((unsigned short)(h >> 16)))
        + __bfloat162float(__ushort_as_bfloat16((unsigned short)(l >> 16)));
    return r;
}

__device__ __forceinline__ void ggsync(int g, unsigned& target) {
    target += 32;
    __syncthreads();
    __threadfence();
    if (threadIdx.x == 0) {
        atomicAdd(&g_gbar[g * 32], 1u);
        while (*((volatile unsigned*)&g_gbar[g * 32]) < target) {}
        __threadfence();
    }
    __syncthreads();
}

__global__ void splitw_all(const float* __restrict__ W1, const float* __restrict__ W2,
                           const float* __restrict__ W3, const float* __restrict__ W4,
                           const float* __restrict__ Whh)
{
    int i = blockIdx.x * 256 + threadIdx.x;
    if (i >= NW_TOT) return;
    const float* src; int off;
    if (i < OFF_W2)       { src = W1;  off = OFF_W1; }
    else if (i < OFF_W3)  { src = W2;  off = OFF_W2; }
    else if (i < OFF_W4)  { src = W3;  off = OFF_W3; }
    else if (i < OFF_WHH) { src = W4;  off = OFF_W4; }
    else                  { src = Whh; off = OFF_WHH; }
    float v = src[i - off];
    bf16 h = __float2bfloat16(v);
    g_WHB[i] = h;
    g_WLB[i] = __float2bfloat16(v - __bfloat162float(h));
}

__global__ void splitw_bf16(const float* __restrict__ src,
                            bf16* __restrict__ hi, bf16* __restrict__ lo, int n)
{
    int i = blockIdx.x * 256 + threadIdx.x;
    if (i < n) {
        float v = src[i];
        bf16 h = __float2bfloat16(v);
        hi[i] = h;
        lo[i] = __float2bfloat16(v - __bfloat162float(h));
    }
}

// ---------------------------------------------------------------------------
// Phase 1a (unchanged; zeroes group barriers)
// ---------------------------------------------------------------------------
__global__ void __launch_bounds__(256) phase1a_kernel(
    const float* __restrict__ y,
    const float* __restrict__ Wih, const float* __restrict__ Whh,
    const float* __restrict__ bih, const float* __restrict__ bhh,
    float* __restrict__ Z)
{
    const int b = blockIdx.x, tid = threadIdx.x;
    __shared__ float sz[LAT];
    __shared__ float sy[OBS];

    if (b == 0 && tid < 128) g_gbar[tid] = 0u;

    sz[tid] = 0.0f;
    __stcg(Z + (size_t)b * LAT + tid, 0.0f);
    float bsum = __ldg(bih + tid) + __ldg(bhh + tid);

    float4 wi[8];
    const float4* wip = (const float4*)(Wih + (size_t)tid * OBS);
#pragma unroll
    for (int k = 0; k < 8; k++) wi[k] = __ldg(wip + k);
    const float4* wh = (const float4*)(Whh + (size_t)tid * LAT);
    __syncthreads();

    for (int t = 0; t < TSTEPS; t++) {
        if (tid < OBS) sy[tid] = __ldg(y + ((size_t)b * TSTEPS + t) * OBS + tid);
        __syncthreads();
        float acc = bsum;
#pragma unroll
        for (int k = 0; k < 8; k++) {
            float4 w = wi[k];
            acc += sy[k*4+0]*w.x + sy[k*4+1]*w.y + sy[k*4+2]*w.z + sy[k*4+3]*w.w;
        }
#pragma unroll 8
        for (int k = 0; k < 64; k++) {
            float4 w = __ldg(wh + k);
            acc += sz[k*4+0]*w.x + sz[k*4+1]*w.y + sz[k*4+2]*w.z + sz[k*4+3]*w.w;
        }
        float zn = tanhf(acc);
        __syncthreads();
        sz[tid] = zn;
        __stcg(Z + ((size_t)t + 1) * ZSTRIDE + (size_t)b * LAT + tid, zn);
    }
}

// ---------------------------------------------------------------------------
// Phase 1b bf16-pair MMA GEMM: 128x128 tile, 3-stage (unchanged from round 13)
// ---------------------------------------------------------------------------
__global__ void __launch_bounds__(256) gemm_mma_128(
    const bf16* __restrict__ Xh, const bf16* __restrict__ Xl, int ldx,
    const bf16* __restrict__ Wh, const bf16* __restrict__ Wl, int ldw,
    const float* __restrict__ bias,
    bf16* __restrict__ Yh, bf16* __restrict__ Yl, int ldy, int K)
{
    extern __shared__ __align__(16) uint32_t SW[];
    const uint32_t sbase = (uint32_t)__cvta_generic_to_shared(SW);
    const int tid = threadIdx.x, lane = tid & 31, wid = tid >> 5;
    const int mw = wid >> 2, nw = wid & 3;
    const int mB = blockIdx.y * 128, nB = blockIdx.x * 128;
    const int nch = K >> 5;

    auto issue = [&](int c, int s) {
        const int k0 = c << 5;
        const uint32_t base = (uint32_t)s * (uint32_t)S1B_W;
#pragma unroll
        for (int ii = 0; ii < 8; ii++) {
            const int o = tid + ii * 256;
            const int p = o >> 9, q = o & 511, row = q >> 2, sg = q & 3;
            const uint32_t dw = base + (uint32_t)p * 2560u + row * 20u + sg * 4u;
            const bf16* src;
            if (p == 0)      src = Xh + (size_t)(mB + row) * ldx + k0 + sg * 8;
            else if (p == 1) src = Xl + (size_t)(mB + row) * ldx + k0 + sg * 8;
            else if (p == 2) src = Wh + (size_t)(nB + row) * ldw + k0 + sg * 8;
            else             src = Wl + (size_t)(nB + row) * ldw + k0 + sg * 8;
            cpa16(sbase + dw * 4u, src);
        }
        asm volatile("cp.async.commit_group;" ::: "memory");
    };

    float acc[4][4][4];
#pragma unroll
    for (int f = 0; f < 4; f++)
#pragma unroll
        for (int g = 0; g < 4; g++)
#pragma unroll
            for (int i = 0; i < 4; i++) acc[f][g][i] = 0.0f;

#pragma unroll
    for (int c0 = 0; c0 < NST1B; c0++)
        if (c0 < nch) issue(c0, c0);

    const int arow = lane >> 2, acol = lane & 3;
    int stage = 0;

    for (int c = 0; c < nch; c++) {
        wait_1b(nch - 1 - c);
        __syncthreads();
        const uint32_t* S   = SW + stage * S1B_W;
        const uint32_t* XHs = S;
        const uint32_t* XLs = S + 2560;
        const uint32_t* WHs = S + 5120;
        const uint32_t* WLs = S + 7680;
#pragma unroll
        for (int wb = 0; wb < 16; wb += 8) {
            uint32_t bh[4][2], bl[4][2];
#pragma unroll
            for (int g = 0; g < 4; g++) {
                int boff = (nw * 32 + g * 8 + arow) * 20 + acol + wb;
                bh[g][0] = WHs[boff]; bh[g][1] = WHs[boff + 4];
                bl[g][0] = WLs[boff]; bl[g][1] = WLs[boff + 4];
            }
#pragma unroll
            for (int f = 0; f < 4; f++) {
                int r = mw * 64 + f * 16 + arow;
                int aoff  = r * 20 + acol + wb;
                int aoff8 = (r + 8) * 20 + acol + wb;
                uint32_t ah[4] = {XHs[aoff], XHs[aoff8], XHs[aoff + 4], XHs[aoff8 + 4]};
                uint32_t al[4] = {XLs[aoff], XLs[aoff8], XLs[aoff + 4], XLs[aoff8 + 4]};
#pragma unroll
                for (int g = 0; g < 4; g++) {
                    mma16(acc[f][g], ah, bh[g][0], bh[g][1]);
                    mma16(acc[f][g], ah, bl[g][0], bl[g][1]);
                    mma16(acc[f][g], al, bh[g][0], bh[g][1]);
                }
            }
        }
        __syncthreads();
        if (c + NST1B < nch) issue(c + NST1B, stage);
        stage = (stage == NST1B - 1) ? 0 : stage + 1;
    }

#pragma unroll
    for (int f = 0; f < 4; f++) {
#pragma unroll
        for (int g = 0; g < 4; g++) {
            const int r0 = mB + mw * 64 + f * 16 + arow;
            const int col = nB + nw * 32 + g * 8 + acol * 2;
            float2 bb = *(const float2*)(bias + col);
            float v0 = fmaxf(acc[f][g][0] + bb.x, 0.f);
            float v1 = fmaxf(acc[f][g][1] + bb.y, 0.f);
            float v2 = fmaxf(acc[f][g][2] + bb.x, 0.f);
            float v3 = fmaxf(acc[f][g][3] + bb.y, 0.f);
            uint32_t hw, lw;
            split_pack(v0, v1, hw, lw);
            __stcg((uint32_t*)&Yh[(size_t)r0 * ldy + col], hw);
            __stcg((uint32_t*)&Yl[(size_t)r0 * ldy + col], lw);
            split_pack(v2, v3, hw, lw);
            __stcg((uint32_t*)&Yh[(size_t)(r0 + 8) * ldy + col], hw);
            __stcg((uint32_t*)&Yl[(size_t)(r0 + 8) * ldy + col], lw);
        }
    }
}

// ---------------------------------------------------------------------------
// Phase 1b output layer (unchanged)
// ---------------------------------------------------------------------------
__global__ void __launch_bounds__(256) gemm_out_bf(
    const bf16* __restrict__ Xh, const bf16* __restrict__ Xl, int ldx,
    const float* __restrict__ W, int ldw,
    const float* __restrict__ bias,
    float* __restrict__ out, int K, int t0)
{
    __shared__ __align__(16) float sX[16 * 132];
    __shared__ __align__(16) float sW[16 * 36];
    const int tid = threadIdx.x;
    const int ty = tid >> 4, tx = tid & 15;
    const int mB = blockIdx.y * 128;
    const int xr = tid >> 2, xc = tid & 3;

    const bf16* XpH0 = Xh + (size_t)(mB + xr) * ldx + xc * 4;
    const bf16* XpL0 = Xl + (size_t)(mB + xr) * ldx + xc * 4;
    const bf16* XpH1 = XpH0 + (size_t)64 * ldx;
    const bf16* XpL1 = XpL0 + (size_t)64 * ldx;
    const bool wp = tid < 128;
    const float* Wp = W + (size_t)xr * ldw + xc * 4;

    uint2 xh0 = __ldg((const uint2*)XpH0);
    uint2 xl0 = __ldg((const uint2*)XpL0);
    uint2 xh1 = __ldg((const uint2*)XpH1);
    uint2 xl1 = __ldg((const uint2*)XpL1);
    float4 wv = make_float4(0,0,0,0);
    if (wp) wv = __ldg((const float4*)Wp);

    float acc[8][2];
#pragma unroll
    for (int i = 0; i < 8; i++) { acc[i][0] = 0.f; acc[i][1] = 0.f; }

    for (int k0 = 0;;) {
        {
            float2 a = comb2(xh0.x, xl0.x), b = comb2(xh0.y, xl0.y);
            sX[(xc*4+0)*132 + xr] = a.x; sX[(xc*4+1)*132 + xr] = a.y;
            sX[(xc*4+2)*132 + xr] = b.x; sX[(xc*4+3)*132 + xr] = b.y;
            float2 c = comb2(xh1.x, xl1.x), d = comb2(xh1.y, xl1.y);
            sX[(xc*4+0)*132 + xr+64] = c.x; sX[(xc*4+1)*132 + xr+64] = c.y;
            sX[(xc*4+2)*132 + xr+64] = d.x; sX[(xc*4+3)*132 + xr+64] = d.y;
        }
        if (wp) {
            sW[(xc*4+0)*36 + xr] = wv.x; sW[(xc*4+1)*36 + xr] = wv.y;
            sW[(xc*4+2)*36 + xr] = wv.z; sW[(xc*4+3)*36 + xr] = wv.w;
        }
        __syncthreads();
        const int k1 = k0 + 16;
        if (k1 < K) {
            xh0 = __ldg((const uint2*)(XpH0 + k1));
            xl0 = __ldg((const uint2*)(XpL0 + k1));
            xh1 = __ldg((const uint2*)(XpH1 + k1));
            xl1 = __ldg((const uint2*)(XpL1 + k1));
            if (wp) wv = __ldg((const float4*)(Wp + k1));
        }
#pragma unroll
        for (int kk = 0; kk < 16; kk++) {
            float4 a0 = *(const float4*)&sX[kk*132 + ty*8];
            float4 a1 = *(const float4*)&sX[kk*132 + ty*8 + 4];
            float2 b  = *(const float2*)&sW[kk*36 + tx*2];
            acc[0][0]+=a0.x*b.x; acc[0][1]+=a0.x*b.y;
            acc[1][0]+=a0.y*b.x; acc[1][1]+=a0.y*b.y;
            acc[2][0]+=a0.z*b.x; acc[2][1]+=a0.z*b.y;
            acc[3][0]+=a0.w*b.x; acc[3][1]+=a0.w*b.y;
            acc[4][0]+=a1.x*b.x; acc[4][1]+=a1.x*b.y;
            acc[5][0]+=a1.y*b.x; acc[5][1]+=a1.y*b.y;
            acc[6][0]+=a1.z*b.x; acc[6][1]+=a1.z*b.y;
            acc[7][0]+=a1.w*b.x; acc[7][1]+=a1.w*b.y;
        }
        __syncthreads();
        if (k1 >= K) break;
        k0 = k1;
    }

    float2 bb = *(const float2*)(bias + tx * 2);
#pragma unroll
    for (int i = 0; i < 8; i++) {
        int r = mB + ty * 8 + i;
        int b = r & (BATCH - 1);
        int t = t0 + (r >> 7);
        float2 v = make_float2(acc[i][0] + bb.x, acc[i][1] + bb.y);
        *(float2*)(out + ((size_t)b * HORIZON + t) * OBS + tx * 2) = v;
    }
}

// ---------------------------------------------------------------------------
// Phase-2: per-half W prologue (2 commit groups), issued BEFORE the barrier.
// Half h prefetches its first 2 chunks' W (and V) into stages 2h, 2h+1.
// ---------------------------------------------------------------------------
template<bool DOV>
__device__ __forceinline__ void prologueW(
    uint32_t sbase, int nT, int K,
    const bf16* __restrict__ Wh, const bf16* __restrict__ Wl, int ldw,
    const bf16* __restrict__ Vh, const bf16* __restrict__ Vl, int whCol0)
{
    const int tid = threadIdx.x;
    const int half = tid >> 8, lt = tid & 255;
    const int nchH = (K >> 6) >> 1;
#pragma unroll
    for (int s = 0; s < 2; s++) {
        if (s < nchH) {
            const int c = half * nchH + s;
            const int k0 = c << 6;
            const uint32_t base = (uint32_t)(half * 2 + s) * (uint32_t)STAGE_W;
#pragma unroll
            for (int ii = 0; ii < 2; ii++) {
                const int o = lt + ii * 256;
                const int p = o >> 8, q = o & 255, row = q >> 3, sg = q & 7;
                const uint32_t dw = base + 2304u + (uint32_t)p * 1152u + row * 36u + sg * 4u;
                const bf16* src = (p ? Wl : Wh) + (size_t)(nT + row) * ldw + k0 + sg * 8;
                cpa16(sbase + dw * 4u, src);
            }
            if (DOV && lt < 128) {
                const int p = lt >> 6, q = lt & 63, row = q >> 3, sg = q & 7;
                const uint32_t dw = base + 4608u + (uint32_t)p * 288u + row * 36u + sg * 4u;
                const bf16* src = (p ? Vl : Vh) + (size_t)(whCol0 + row) * 256 + k0 + sg * 8;
                cpa16(sbase + dw * 4u, src);
            }
        }
        asm volatile("cp.async.commit_group;" ::: "memory");
    }
}

// ---------------------------------------------------------------------------
// Phase-2 region: warp-group split-K. 512 threads; half h handles chunks
// [h*nchH, (h+1)*nchH) with its own 2 stages and named barrier. Halves'
// partials reduced via smem; half 1 runs the epilogue.
// ---------------------------------------------------------------------------
template<bool RELU, bool DOWHH, bool DOL5>
__device__ void mma_region(
    uint32_t* SW, uint32_t sbase,
    int mT, int nT, int K,
    const bf16* __restrict__ Xh, const bf16* __restrict__ Xl, int ldx,
    const bf16* __restrict__ Wh, const bf16* __restrict__ Wl, int ldw,
    const float* __restrict__ bias,
    bf16* __restrict__ Yh, bf16* __restrict__ Yl, int ldy,
    float* __restrict__ Cout, int whCol0,
    const float* __restrict__ W5, float* __restrict__ yhpart, int jIdx)
{
    const int tid = threadIdx.x;
    const int half = tid >> 8, lt = tid & 255;
    const int lane = tid & 31, lwid = (tid >> 5) & 7;
    const int mw = lwid >> 2, nw = lwid & 3;
    const int nchH = (K >> 6) >> 1;
    const int cBase = half * nchH;
    const int sBase = half * 2;

    // X prologue: 2 commit groups (this half's stages)
#pragma unroll
    for (int s = 0; s < 2; s++) {
        if (s < nchH) {
            const int k0 = (cBase + s) << 6;
            const uint32_t base = (uint32_t)(sBase + s) * (uint32_t)STAGE_W;
#pragma unroll
            for (int ii = 0; ii < 2; ii++) {
                const int o = lt + ii * 256;
                const int p = o >> 8, q = o & 255, row = q >> 3, sg = q & 7;
                const uint32_t dw = base + (uint32_t)p * 1152u + row * 36u + sg * 4u;
                const bf16* src = (p ? Xl : Xh) + (size_t)(mT + row) * ldx + k0 + sg * 8;
                cpa16(sbase + dw * 4u, src);
            }
        }
        asm volatile("cp.async.commit_group;" ::: "memory");
    }

    auto issueC = [&](int lc) {
        const int k0 = (cBase + lc) << 6;
        const uint32_t base = (uint32_t)(sBase + (lc & 1)) * (uint32_t)STAGE_W;
#pragma unroll
        for (int ii = 0; ii < 4; ii++) {
            const int o = lt + ii * 256;
            const int p = o >> 8, q = o & 255, row = q >> 3, sg = q & 7;
            const uint32_t dw = base + (uint32_t)p * 1152u + row * 36u + sg * 4u;
            const bf16* src;
            if (p == 0)      src = Xh + (size_t)(mT + row) * ldx + k0 + sg * 8;
            else if (p == 1) src = Xl + (size_t)(mT + row) * ldx + k0 + sg * 8;
            else if (p == 2) src = Wh + (size_t)(nT + row) * ldw + k0 + sg * 8;
            else             src = Wl + (size_t)(nT + row) * ldw + k0 + sg * 8;
            cpa16(sbase + dw * 4u, src);
        }
        asm volatile("cp.async.commit_group;" ::: "memory");
    };

    float ahh[4] = {0,0,0,0}, ahl[4] = {0,0,0,0}, alh[4] = {0,0,0,0};
    float whh[4] = {0,0,0,0}, whl[4] = {0,0,0,0}, wlh[4] = {0,0,0,0};

    const int r0 = mw * 16 + (lane >> 2);
    const int wc = lane & 3;
    const int aoff0 = r0 * 36 + wc;
    const int aoff1 = (r0 + 8) * 36 + wc;
    const int boff = (nw * 8 + (lane >> 2)) * 36 + wc;
    const int voff = (lane >> 2) * 36 + wc;

    for (int lc = 0; lc < nchH; lc++) {
        if (lc == nchH - 1) asm volatile("cp.async.wait_group 0;" ::: "memory");
        else                asm volatile("cp.async.wait_group 1;" ::: "memory");
        barh(half);
        const uint32_t* S   = SW + (sBase + (lc & 1)) * STAGE_W;
        const uint32_t* XHs = S;
        const uint32_t* XLs = S + 1152;
        const uint32_t* WHs = S + 2304;
        const uint32_t* WLs = S + 3456;
        const uint32_t* VHs = S + 4608;
        const uint32_t* VLs = S + 4896;
#pragma unroll
        for (int wb = 0; wb < 32; wb += 8) {
            uint32_t ah[4], al[4];
            ah[0] = XHs[aoff0 + wb];     ah[1] = XHs[aoff1 + wb];
            ah[2] = XHs[aoff0 + wb + 4]; ah[3] = XHs[aoff1 + wb + 4];
            al[0] = XLs[aoff0 + wb];     al[1] = XLs[aoff1 + wb];
            al[2] = XLs[aoff0 + wb + 4]; al[3] = XLs[aoff1 + wb + 4];
            uint32_t bh0 = WHs[boff + wb], bh1 = WHs[boff + wb + 4];
            uint32_t bl0 = WLs[boff + wb], bl1 = WLs[boff + wb + 4];
            mma16(ahh, ah, bh0, bh1);
            mma16(ahl, ah, bl0, bl1);
            mma16(alh, al, bh0, bh1);
            if (DOWHH && nw == 0) {
                uint32_t vh0 = VHs[voff + wb], vh1 = VHs[voff + wb + 4];
                uint32_t vl0 = VLs[voff + wb], vl1 = VLs[voff + wb + 4];
                mma16(whh, ah, vh0, vh1);
                mma16(whl, ah, vl0, vl1);
                mma16(wlh, al, vh0, vh1);
            }
        }
        barh(half);
        if (lc + 2 < nchH) issueC(lc + 2);
    }

    // cross-half reduce
    float* RED  = (float*)SW + RED_OFF;
    float* REDW = (float*)SW + REDW_OFF;
    const int ocol_l = nw * 8 + wc * 2;
    __syncthreads();
    if (half == 0) {
        RED[r0 * 33 + ocol_l]           = ahh[0] + ahl[0] + alh[0];
        RED[r0 * 33 + ocol_l + 1]       = ahh[1] + ahl[1] + alh[1];
        RED[(r0 + 8) * 33 + ocol_l]     = ahh[2] + ahl[2] + alh[2];
        RED[(r0 + 8) * 33 + ocol_l + 1] = ahh[3] + ahl[3] + alh[3];
        if (DOWHH && nw == 0) {
            REDW[r0 * 9 + wc * 2]           = whh[0] + whl[0] + wlh[0];
            REDW[r0 * 9 + wc * 2 + 1]       = whh[1] + whl[1] + wlh[1];
            REDW[(r0 + 8) * 9 + wc * 2]     = whh[2] + whl[2] + wlh[2];
            REDW[(r0 + 8) * 9 + wc * 2 + 1] = whh[3] + whl[3] + wlh[3];
        }
    }
    __syncthreads();

    float* sh4 = (float*)SW + SH4_OFF;
    if (half == 1) {
        const int orow = mT + r0;
        const int ocol = nT + ocol_l;
        float2 bb = *(const float2*)(bias + ocol);
        float v0 = RED[r0 * 33 + ocol_l]           + ahh[0] + ahl[0] + alh[0] + bb.x;
        float v1 = RED[r0 * 33 + ocol_l + 1]       + ahh[1] + ahl[1] + alh[1] + bb.y;
        float v2 = RED[(r0 + 8) * 33 + ocol_l]     + ahh[2] + ahl[2] + alh[2] + bb.x;
        float v3 = RED[(r0 + 8) * 33 + ocol_l + 1] + ahh[3] + ahl[3] + alh[3] + bb.y;
        if (RELU) {
            v0 = fmaxf(v0, 0.f); v1 = fmaxf(v1, 0.f);
            v2 = fmaxf(v2, 0.f); v3 = fmaxf(v3, 0.f);
        }
        if (DOL5) {
            sh4[r0 * 33 + ocol_l]           = v0;
            sh4[r0 * 33 + ocol_l + 1]       = v1;
            sh4[(r0 + 8) * 33 + ocol_l]     = v2;
            sh4[(r0 + 8) * 33 + ocol_l + 1] = v3;
        } else {
            uint32_t hw, lw;
            split_pack(v0, v1, hw, lw);
            __stcg((uint32_t*)&Yh[(size_t)orow * ldy + ocol], hw);
            __stcg((uint32_t*)&Yl[(size_t)orow * ldy + ocol], lw);
            split_pack(v2, v3, hw, lw);
            __stcg((uint32_t*)&Yh[(size_t)(orow + 8) * ldy + ocol], hw);
            __stcg((uint32_t*)&Yl[(size_t)(orow + 8) * ldy + ocol], lw);
        }
        if (DOWHH && nw == 0) {
            const int wcol = whCol0 + wc * 2;
            float w0 = REDW[r0 * 9 + wc * 2]           + whh[0] + whl[0] + wlh[0];
            float w1 = REDW[r0 * 9 + wc * 2 + 1]       + whh[1] + whl[1] + wlh[1];
            float w2 = REDW[(r0 + 8) * 9 + wc * 2]     + whh[2] + whl[2] + wlh[2];
            float w3 = REDW[(r0 + 8) * 9 + wc * 2 + 1] + whh[3] + whl[3] + wlh[3];
            __stcg((float2*)&Cout[(size_t)(mT + r0) * LAT + wcol], make_float2(w0, w1));
            __stcg((float2*)&Cout[(size_t)(mT + r0 + 8) * LAT + wcol], make_float2(w2, w3));
        }
    }

    if (DOL5) {
        __syncthreads();
        // 512 threads: 16 warps x 2 rows; lane = output index s
        const float* w5r = W5 + (size_t)lane * HID + nT;
        float w5f[32];
#pragma unroll
        for (int q = 0; q < 8; q++) {
            float4 w = __ldg((const float4*)(w5r + q * 4));
            w5f[q*4+0] = w.x; w5f[q*4+1] = w.y; w5f[q*4+2] = w.z; w5f[q*4+3] = w.w;
        }
        const int wfull = tid >> 5;     // 0..15
#pragma unroll
        for (int i = 0; i < 2; i++) {
            const int r = wfull * 2 + i;
            const float* hr = sh4 + r * 33;
            float s = 0.f;
#pragma unroll
            for (int n = 0; n < 32; n++) s += hr[n] * w5f[n];
            __stcg(yhpart + (size_t)jIdx * (BATCH * 32) + (mT + r) * 32 + lane, s);
        }
    }
}

// ---------------------------------------------------------------------------
// Phase 2: 128 CTAs x 512 threads, 4 groups of 32, 5 barriers/step.
// ---------------------------------------------------------------------------
__global__ void __launch_bounds__(512, 1) phase2_kernel(
    const float* __restrict__ b1, const float* __restrict__ b2,
    const float* __restrict__ b3, const float* __restrict__ b4,
    const float* __restrict__ W5, const float* __restrict__ b5,
    const float* __restrict__ Wih,
    const float* __restrict__ bih, const float* __restrict__ bhh,
    const float* __restrict__ Z,
    float* __restrict__ PL,
    float* __restrict__ out)
{
    extern __shared__ __align__(16) uint32_t SW[];
    const uint32_t sbase = (uint32_t)__cvta_generic_to_shared(SW);
    const int bid = blockIdx.x, tid = threadIdx.x;
    const int g = bid >> 5, j = bid & 31;
    const int mT = g * 32, nT = j * 32;
    const int b = bid;
    unsigned target = 0;

    bf16* AH = (bf16*)(PL + C_AH);
    bf16* AL = (bf16*)(PL + C_AL);
    bf16* BH = (bf16*)(PL + C_BH);
    bf16* BL = (bf16*)(PL + C_BL);
    bf16* ZH = (bf16*)(PL + C_ZH);
    bf16* ZL = (bf16*)(PL + C_ZL);
    float* C  = PL + C_C;
    float* YP = PL + C_YP;

    const bf16 *W1H = g_WHB + OFF_W1,  *W1L = g_WLB + OFF_W1;
    const bf16 *W2H = g_WHB + OFF_W2,  *W2L = g_WLB + OFF_W2;
    const bf16 *W3H = g_WHB + OFF_W3,  *W3L = g_WLB + OFF_W3;
    const bf16 *W4H = g_WHB + OFF_W4,  *W4L = g_WLB + OFF_W4;
    const bf16 *VH  = g_WHB + OFF_WHH, *VL  = g_WLB + OFF_WHH;

    if (tid < 128) {
        float2 z2 = __ldcg((const float2*)(Z + (size_t)TSTEPS * ZSTRIDE + (size_t)b * LAT) + tid);
        uint32_t hw, lw;
        split_pack(z2.x, z2.y, hw, lw);
        __stcg((uint32_t*)(ZH + (size_t)b * LAT) + tid, hw);
        __stcg((uint32_t*)(ZL + (size_t)b * LAT) + tid, lw);
    }
    prologueW<true>(sbase, nT, LAT, W1H, W1L, LAT, VH, VL, j * 8);
    ggsync(g, target);

    for (int t = TSTEPS; t < HORIZON; t++) {
        mma_region<true, true, false>(SW, sbase, mT, nT, LAT,
                               ZH, ZL, LAT, W1H, W1L, LAT,
                               b1, AH, AL, HID, C, j * 8,
                               (const float*)0, (float*)0, 0);
        prologueW<false>(sbase, nT, HID, W2H, W2L, HID, (const bf16*)0, (const bf16*)0, 0);
        ggsync(g, target);
        mma_region<true, false, false>(SW, sbase, mT, nT, HID,
                                AH, AL, HID, W2H, W2L, HID,
                                b2, BH, BL, HID, (float*)0, 0,
                                (const float*)0, (float*)0, 0);
        prologueW<false>(sbase, nT, HID, W3H, W3L, HID, (const bf16*)0, (const bf16*)0, 0);
        ggsync(g, target);
        mma_region<true, false, false>(SW, sbase, mT, nT, HID,
                                BH, BL, HID, W3H, W3L, HID,
                                b3, AH, AL, HID, (float*)0, 0,
                                (const float*)0, (float*)0, 0);
        prologueW<false>(sbase, nT, HID, W4H, W4L, HID, (const bf16*)0, (const bf16*)0, 0);
        ggsync(g, target);
        mma_region<true, false, true>(SW, sbase, mT, nT, HID,
                                AH, AL, HID, W4H, W4L, HID,
                                b4, (bf16*)0, (bf16*)0, HID, (float*)0, 0,
                                W5, YP, j);
        ggsync(g, target);

        // R5: combine yh partials -> out; cell finish
        {
            float* FS = (float*)SW;
            if (tid < OBS) {
                float s = __ldg(b5 + tid);
                const float* yp = YP + (size_t)b * 32 + tid;
#pragma unroll
                for (int jj = 0; jj < 32; jj++)
                    s += __ldcg(yp + (size_t)jj * (BATCH * 32));
                __stcg(out + ((size_t)b * HORIZON + t) * OBS + tid, s);
                FS[tid] = s;
            }
            __syncthreads();
            if (t < HORIZON - 1) {
                if (tid < 256) {
                    const int n = tid;
                    float acc = __ldcg(C + (size_t)b * LAT + n)
                              + __ldg(bih + n) + __ldg(bhh + n);
                    const float4* wr = (const float4*)(Wih + (size_t)n * OBS);
#pragma unroll
                    for (int k = 0; k < 8; k++) {
                        float4 wv = __ldg(wr + k);
                        acc += FS[k*4+0]*wv.x + FS[k*4+1]*wv.y
                             + FS[k*4+2]*wv.z + FS[k*4+3]*wv.w;
                    }
                    FS[64 + n] = tanhf(acc);
                }
                __syncthreads();
                if (tid < 128) {
                    float z0 = FS[64 + 2*tid], z1 = FS[64 + 2*tid + 1];
                    uint32_t hw, lw;
                    split_pack(z0, z1, hw, lw);
                    __stcg((uint32_t*)(ZH + (size_t)b * LAT) + tid, hw);
                    __stcg((uint32_t*)(ZL + (size_t)b * LAT) + tid, lw);
                }
                __syncthreads();
                prologueW<true>(sbase, nT, LAT, W1H, W1L, LAT, VH, VL, j * 8);
            }
        }
        ggsync(g, target);
    }
}

// ---------------------------------------------------------------------------
// Launch (phase2 at our launch index 3 for ncu)
// ---------------------------------------------------------------------------
extern "C" void kernel_launch(void* const* d_in, const int* in_sizes, int n_in,
                              void* d_out, int out_size)
{
    const float* y   = (const float*)d_in[0];
    const float* Wih = (const float*)d_in[2];
    const float* Whh = (const float*)d_in[3];
    const float* bih = (const float*)d_in[4];
    const float* bhh = (const float*)d_in[5];
    const float* W1  = (const float*)d_in[6];
    const float* b1  = (const float*)d_in[7];
    const float* W2  = (const float*)d_in[8];
    const float* b2  = (const float*)d_in[9];
    const float* W3  = (const float*)d_in[10];
    const float* b3  = (const float*)d_in[11];
    const float* W4  = (const float*)d_in[12];
    const float* b4  = (const float*)d_in[13];
    const float* W5  = (const float*)d_in[14];
    const float* b5  = (const float*)d_in[15];
    float* out = (float*)d_out;

    float *Z, *A, *Bf;
    bf16 *WHB, *WLB, *ZPH, *ZPL;
    cudaGetSymbolAddress((void**)&Z,    g_Z);
    cudaGetSymbolAddress((void**)&A,    g_A);
    cudaGetSymbolAddress((void**)&Bf,   g_B);
    cudaGetSymbolAddress((void**)&WHB,  g_WHB);
    cudaGetSymbolAddress((void**)&WLB,  g_WLB);
    cudaGetSymbolAddress((void**)&ZPH,  g_ZPH);
    cudaGetSymbolAddress((void**)&ZPL,  g_ZPL);

    static int attr_done = 0;
    if (!attr_done) {
        cudaFuncSetAttribute(phase2_kernel,
                             cudaFuncAttributeMaxDynamicSharedMemorySize, P2_SMEM);
        cudaFuncSetAttribute(gemm_mma_128,
                             cudaFuncAttributeMaxDynamicSharedMemorySize, SMEM1B);
        attr_done = 1;
    }

    // [0] fused weight hi/lo split
    splitw_all<<<(NW_TOT + 255)/256, 256>>>(W1, W2, W3, W4, Whh);

    // [1] phase 1a (also zeroes group barriers)
    phase1a_kernel<<<BATCH, 256>>>(y, Wih, Whh, bih, bhh, Z);

    // [2] split teacher-forced z states into bf16 planes
    splitw_bf16<<<(TSTEPS * ZSTRIDE + 255)/256, 256>>>(Z, ZPH, ZPL, TSTEPS * ZSTRIDE);

    // [3] phase 2 (persistent AR rollout) — profiled launch
    phase2_kernel<<<128, 512, P2_SMEM>>>(b1, b2, b3, b4, W5, b5, Wih, bih, bhh,
                                         Z, Z + (size_t)P2_BASE, out);

    // [4..13] phase 1b: 2 chunks of 128 steps, bf16-pair MMA (128x128 tiles)
    const int CHUNK = 128;
    const int MBIG  = CHUNK * BATCH;
    bf16* AH = (bf16*)A;
    bf16* AL = (bf16*)A + (size_t)MBIG * HID;
    bf16* BH = (bf16*)Bf;
    bf16* BL = (bf16*)Bf + (size_t)MBIG * HID;
    for (int c = 0; c < TSTEPS / CHUNK; c++) {
        const bf16* XzH = ZPH + (size_t)c * CHUNK * ZSTRIDE;
        const bf16* XzL = ZPL + (size_t)c * CHUNK * ZSTRIDE;
        gemm_mma_128<<<dim3(HID/128, MBIG/128), 256, SMEM1B>>>(
            XzH, XzL, LAT, WHB + OFF_W1, WLB + OFF_W1, LAT, b1, AH, AL, HID, LAT);
        gemm_mma_128<<<dim3(HID/128, MBIG/128), 256, SMEM1B>>>(
            AH, AL, HID, WHB + OFF_W2, WLB + OFF_W2, HID, b2, BH, BL, HID, HID);
        gemm_mma_128<<<dim3(HID/128, MBIG/128), 256, SMEM1B>>>(
            BH, BL, HID, WHB + OFF_W3, WLB + OFF_W3, HID, b3, AH, AL, HID, HID);
        gemm_mma_128<<<dim3(HID/128, MBIG/128), 256, SMEM1B>>>(
            AH, AL, HID, WHB + OFF_W4, WLB + OFF_W4, HID, b4, BH, BL, HID, HID);
        gemm_out_bf<<<dim3(1, MBIG/128), 256>>>(
            BH, BL, HID, W5, HID, b5, out, HID, c * CHUNK);
    }
}

// round 15
// speedup vs baseline: 2.1720x; 1.0006x over previous
#include <cuda_runtime.h>
#include <cuda_bf16.h>
#include <math.h>
#include <stdint.h>

#define BATCH   128
#define TSTEPS  256
#define HORIZON 512
#define OBS     32
#define LAT     256
#define HID     1024
#define ZSTRIDE (BATCH * LAT)

typedef __nv_bfloat16 bf16;

// old-layout stage (R1: X+W+V), words
#define STAGE_W 5184
// new-layout stage (R2-R4: X+W only, K=128 chunks), words
#define STAGE2_W 8704
#define P2_SMEM (4 * STAGE2_W * 4)      // 139,264 B

#define S1B_W   10240
#define NST1B   3
#define SMEM1B  (NST1B * S1B_W * 4)

// ---------------------------------------------------------------------------
// Scratch
// ---------------------------------------------------------------------------
__device__ float g_Z[(size_t)(HORIZON + 1) * ZSTRIDE];
__device__ float g_A[(size_t)128 * BATCH * HID];
__device__ float g_B[(size_t)128 * BATCH * HID];
__device__ bf16  g_ZPH[(size_t)TSTEPS * ZSTRIDE];
__device__ bf16  g_ZPL[(size_t)TSTEPS * ZSTRIDE];
__device__ bf16  g_WHB[3473408];
__device__ bf16  g_WLB[3473408];
__device__ unsigned g_gbar[4 * 32];

#define OFF_W1  0
#define OFF_W2  262144
#define OFF_W3  1310720
#define OFF_W4  2359296
#define OFF_WHH 3407872
#define NW_TOT  3473408

#define P2_BASE (320 * ZSTRIDE)
#define C_AH    0
#define C_AL    65536
#define C_BH    131072
#define C_BL    196608
#define C_ZH    262144
#define C_ZL    278528
#define C_C     294912
#define C_YP    327680

// smem scratch offsets (floats)
#define RED_OFF   0
#define REDW_OFF  1100
#define SH4_OFF   1408

// ---------------------------------------------------------------------------
// helpers
// ---------------------------------------------------------------------------
__device__ __forceinline__ void mma16(float* d, const uint32_t* a, uint32_t b0, uint32_t b1) {
    asm volatile(
        "mma.sync.aligned.m16n8k16.row.col.f32.bf16.bf16.f32 "
        "{%0,%1,%2,%3},{%4,%5,%6,%7},{%8,%9},{%0,%1,%2,%3};"
        : "+f"(d[0]), "+f"(d[1]), "+f"(d[2]), "+f"(d[3])
        : "r"(a[0]), "r"(a[1]), "r"(a[2]), "r"(a[3]), "r"(b0), "r"(b1));
}
__device__ __forceinline__ void cpa16(uint32_t dst, const void* src) {
    asm volatile("cp.async.cg.shared.global [%0], [%1], 16;" :: "r"(dst), "l"(src));
}
__device__ __forceinline__ void barh(int h) {
    asm volatile("bar.sync %0, 256;" :: "r"(h + 1) : "memory");
}
__device__ __forceinline__ void wait_1b(int rem) {
    if (rem >= 2)      asm volatile("cp.async.wait_group 2;" ::: "memory");
    else if (rem == 1) asm volatile("cp.async.wait_group 1;" ::: "memory");
    else               asm volatile("cp.async.wait_group 0;" ::: "memory");
}
__device__ __forceinline__ void split_pack(float v0, float v1, uint32_t& hw, uint32_t& lw) {
    bf16 h0 = __float2bfloat16(v0);
    bf16 h1 = __float2bfloat16(v1);
    bf16 l0 = __float2bfloat16(v0 - __bfloat162float(h0));
    bf16 l1 = __float2bfloat16(v1 - __bfloat162float(h1));
    hw = ((uint32_t)__bfloat16_as_ushort(h1) << 16) | __bfloat16_as_ushort(h0);
    lw = ((uint32_t)__bfloat16_as_ushort(l1) << 16) | __bfloat16_as_ushort(l0);
}
__device__ __forceinline__ float2 comb2(uint32_t h, uint32_t l) {
    float2 r;
    r.x = __bfloat162float(__ushort_as_bfloat16((unsigned short)(h & 0xffff)))
        + __bfloat162float(__ushort_as_bfloat16((unsigned short)(l & 0xffff)));
    r.y = __bfloat162float(__ushort_as_bfloat16((unsigned short)(h >> 16)))
        + __bfloat162float(__ushort_as_bfloat16((unsigned short)(l >> 16)));
    return r;
}

__device__ __forceinline__ void ggsync(int g, unsigned& target) {
    target += 32;
    __syncthreads();
    __threadfence();
    if (threadIdx.x == 0) {
        atomicAdd(&g_gbar[g * 32], 1u);
        while (*((volatile unsigned*)&g_gbar[g * 32]) < target) {}
        __threadfence();
    }
    __syncthreads();
}

__global__ void splitw_all(const float* __restrict__ W1, const float* __restrict__ W2,
                           const float* __restrict__ W3, const float* __restrict__ W4,
                           const float* __restrict__ Whh)
{
    int i = blockIdx.x * 256 + threadIdx.x;
    if (i >= NW_TOT) return;
    const float* src; int off;
    if (i < OFF_W2)       { src = W1;  off = OFF_W1; }
    else if (i < OFF_W3)  { src = W2;  off = OFF_W2; }
    else if (i < OFF_W4)  { src = W3;  off = OFF_W3; }
    else if (i < OFF_WHH) { src = W4;  off = OFF_W4; }
    else                  { src = Whh; off = OFF_WHH; }
    float v = src[i - off];
    bf16 h = __float2bfloat16(v);
    g_WHB[i] = h;
    g_WLB[i] = __float2bfloat16(v - __bfloat162float(h));
}

__global__ void splitw_bf16(const float* __restrict__ src,
                            bf16* __restrict__ hi, bf16* __restrict__ lo, int n)
{
    int i = blockIdx.x * 256 + threadIdx.x;
    if (i < n) {
        float v = src[i];
        bf16 h = __float2bfloat16(v);
        hi[i] = h;
        lo[i] = __float2bfloat16(v - __bfloat162float(h));
    }
}

// ---------------------------------------------------------------------------
// Phase 1a: 64 CTAs x 2 batch rows; thread n applies its Whh row to both.
// fp32 op order per output identical to before (bitwise same z).
// ---------------------------------------------------------------------------
__global__ void __launch_bounds__(256) phase1a_kernel(
    const float* __restrict__ y,
    const float* __restrict__ Wih, const float* __restrict__ Whh,
    const float* __restrict__ bih, const float* __restrict__ bhh,
    float* __restrict__ Z)
{
    const int tid = threadIdx.x;
    const int r0 = blockIdx.x * 2, r1 = r0 + 1;
    __shared__ float sz0[LAT], sz1[LAT];
    __shared__ float sy0[OBS], sy1[OBS];

    if (blockIdx.x == 0 && tid < 128) g_gbar[tid] = 0u;

    sz0[tid] = 0.0f; sz1[tid] = 0.0f;
    __stcg(Z + (size_t)r0 * LAT + tid, 0.0f);
    __stcg(Z + (size_t)r1 * LAT + tid, 0.0f);
    float bsum = __ldg(bih + tid) + __ldg(bhh + tid);

    float4 wi[8];
    const float4* wip = (const float4*)(Wih + (size_t)tid * OBS);
#pragma unroll
    for (int k = 0; k < 8; k++) wi[k] = __ldg(wip + k);
    const float4* wh = (const float4*)(Whh + (size_t)tid * LAT);
    __syncthreads();

    for (int t = 0; t < TSTEPS; t++) {
        if (tid < OBS)
            sy0[tid] = __ldg(y + ((size_t)r0 * TSTEPS + t) * OBS + tid);
        else if (tid < 2 * OBS)
            sy1[tid - OBS] = __ldg(y + ((size_t)r1 * TSTEPS + t) * OBS + (tid - OBS));
        __syncthreads();
        float acc0 = bsum, acc1 = bsum;
#pragma unroll
        for (int k = 0; k < 8; k++) {
            float4 w = wi[k];
            acc0 += sy0[k*4+0]*w.x + sy0[k*4+1]*w.y + sy0[k*4+2]*w.z + sy0[k*4+3]*w.w;
            acc1 += sy1[k*4+0]*w.x + sy1[k*4+1]*w.y + sy1[k*4+2]*w.z + sy1[k*4+3]*w.w;
        }
#pragma unroll 8
        for (int k = 0; k < 64; k++) {
            float4 w = __ldg(wh + k);
            acc0 += sz0[k*4+0]*w.x + sz0[k*4+1]*w.y + sz0[k*4+2]*w.z + sz0[k*4+3]*w.w;
            acc1 += sz1[k*4+0]*w.x + sz1[k*4+1]*w.y + sz1[k*4+2]*w.z + sz1[k*4+3]*w.w;
        }
        float z0 = tanhf(acc0), z1 = tanhf(acc1);
        __syncthreads();
        sz0[tid] = z0; sz1[tid] = z1;
        __stcg(Z + ((size_t)t + 1) * ZSTRIDE + (size_t)r0 * LAT + tid, z0);
        __stcg(Z + ((size_t)t + 1) * ZSTRIDE + (size_t)r1 * LAT + tid, z1);
    }
}

// ---------------------------------------------------------------------------
// Phase 1b bf16-pair MMA GEMM: 128x128 tile (unchanged)
// ---------------------------------------------------------------------------
__global__ void __launch_bounds__(256) gemm_mma_128(
    const bf16* __restrict__ Xh, const bf16* __restrict__ Xl, int ldx,
    const bf16* __restrict__ Wh, const bf16* __restrict__ Wl, int ldw,
    const float* __restrict__ bias,
    bf16* __restrict__ Yh, bf16* __restrict__ Yl, int ldy, int K)
{
    extern __shared__ __align__(16) uint32_t SW[];
    const uint32_t sbase = (uint32_t)__cvta_generic_to_shared(SW);
    const int tid = threadIdx.x, lane = tid & 31, wid = tid >> 5;
    const int mw = wid >> 2, nw = wid & 3;
    const int mB = blockIdx.y * 128, nB = blockIdx.x * 128;
    const int nch = K >> 5;

    auto issue = [&](int c, int s) {
        const int k0 = c << 5;
        const uint32_t base = (uint32_t)s * (uint32_t)S1B_W;
#pragma unroll
        for (int ii = 0; ii < 8; ii++) {
            const int o = tid + ii * 256;
            const int p = o >> 9, q = o & 511, row = q >> 2, sg = q & 3;
            const uint32_t dw = base + (uint32_t)p * 2560u + row * 20u + sg * 4u;
            const bf16* src;
            if (p == 0)      src = Xh + (size_t)(mB + row) * ldx + k0 + sg * 8;
            else if (p == 1) src = Xl + (size_t)(mB + row) * ldx + k0 + sg * 8;
            else if (p == 2) src = Wh + (size_t)(nB + row) * ldw + k0 + sg * 8;
            else             src = Wl + (size_t)(nB + row) * ldw + k0 + sg * 8;
            cpa16(sbase + dw * 4u, src);
        }
        asm volatile("cp.async.commit_group;" ::: "memory");
    };

    float acc[4][4][4];
#pragma unroll
    for (int f = 0; f < 4; f++)
#pragma unroll
        for (int g = 0; g < 4; g++)
#pragma unroll
            for (int i = 0; i < 4; i++) acc[f][g][i] = 0.0f;

#pragma unroll
    for (int c0 = 0; c0 < NST1B; c0++)
        if (c0 < nch) issue(c0, c0);

    const int arow = lane >> 2, acol = lane & 3;
    int stage = 0;

    for (int c = 0; c < nch; c++) {
        wait_1b(nch - 1 - c);
        __syncthreads();
        const uint32_t* S   = SW + stage * S1B_W;
        const uint32_t* XHs = S;
        const uint32_t* XLs = S + 2560;
        const uint32_t* WHs = S + 5120;
        const uint32_t* WLs = S + 7680;
#pragma unroll
        for (int wb = 0; wb < 16; wb += 8) {
            uint32_t bh[4][2], bl[4][2];
#pragma unroll
            for (int g = 0; g < 4; g++) {
                int boff = (nw * 32 + g * 8 + arow) * 20 + acol + wb;
                bh[g][0] = WHs[boff]; bh[g][1] = WHs[boff + 4];
                bl[g][0] = WLs[boff]; bl[g][1] = WLs[boff + 4];
            }
#pragma unroll
            for (int f = 0; f < 4; f++) {
                int r = mw * 64 + f * 16 + arow;
                int aoff  = r * 20 + acol + wb;
                int aoff8 = (r + 8) * 20 + acol + wb;
                uint32_t ah[4] = {XHs[aoff], XHs[aoff8], XHs[aoff + 4], XHs[aoff8 + 4]};
                uint32_t al[4] = {XLs[aoff], XLs[aoff8], XLs[aoff + 4], XLs[aoff8 + 4]};
#pragma unroll
                for (int g = 0; g < 4; g++) {
                    mma16(acc[f][g], ah, bh[g][0], bh[g][1]);
                    mma16(acc[f][g], ah, bl[g][0], bl[g][1]);
                    mma16(acc[f][g], al, bh[g][0], bh[g][1]);
                }
            }
        }
        __syncthreads();
        if (c + NST1B < nch) issue(c + NST1B, stage);
        stage = (stage == NST1B - 1) ? 0 : stage + 1;
    }

#pragma unroll
    for (int f = 0; f < 4; f++) {
#pragma unroll
        for (int g = 0; g < 4; g++) {
            const int r0 = mB + mw * 64 + f * 16 + arow;
            const int col = nB + nw * 32 + g * 8 + acol * 2;
            float2 bb = *(const float2*)(bias + col);
            float v0 = fmaxf(acc[f][g][0] + bb.x, 0.f);
            float v1 = fmaxf(acc[f][g][1] + bb.y, 0.f);
            float v2 = fmaxf(acc[f][g][2] + bb.x, 0.f);
            float v3 = fmaxf(acc[f][g][3] + bb.y, 0.f);
            uint32_t hw, lw;
            split_pack(v0, v1, hw, lw);
            __stcg((uint32_t*)&Yh[(size_t)r0 * ldy + col], hw);
            __stcg((uint32_t*)&Yl[(size_t)r0 * ldy + col], lw);
            split_pack(v2, v3, hw, lw);
            __stcg((uint32_t*)&Yh[(size_t)(r0 + 8) * ldy + col], hw);
            __stcg((uint32_t*)&Yl[(size_t)(r0 + 8) * ldy + col], lw);
        }
    }
}

// ---------------------------------------------------------------------------
// Phase 1b output layer (unchanged)
// ---------------------------------------------------------------------------
__global__ void __launch_bounds__(256) gemm_out_bf(
    const bf16* __restrict__ Xh, const bf16* __restrict__ Xl, int ldx,
    const float* __restrict__ W, int ldw,
    const float* __restrict__ bias,
    float* __restrict__ out, int K, int t0)
{
    __shared__ __align__(16) float sX[16 * 132];
    __shared__ __align__(16) float sW[16 * 36];
    const int tid = threadIdx.x;
    const int ty = tid >> 4, tx = tid & 15;
    const int mB = blockIdx.y * 128;
    const int xr = tid >> 2, xc = tid & 3;

    const bf16* XpH0 = Xh + (size_t)(mB + xr) * ldx + xc * 4;
    const bf16* XpL0 = Xl + (size_t)(mB + xr) * ldx + xc * 4;
    const bf16* XpH1 = XpH0 + (size_t)64 * ldx;
    const bf16* XpL1 = XpL0 + (size_t)64 * ldx;
    const bool wp = tid < 128;
    const float* Wp = W + (size_t)xr * ldw + xc * 4;

    uint2 xh0 = __ldg((const uint2*)XpH0);
    uint2 xl0 = __ldg((const uint2*)XpL0);
    uint2 xh1 = __ldg((const uint2*)XpH1);
    uint2 xl1 = __ldg((const uint2*)XpL1);
    float4 wv = make_float4(0,0,0,0);
    if (wp) wv = __ldg((const float4*)Wp);

    float acc[8][2];
#pragma unroll
    for (int i = 0; i < 8; i++) { acc[i][0] = 0.f; acc[i][1] = 0.f; }

    for (int k0 = 0;;) {
        {
            float2 a = comb2(xh0.x, xl0.x), b = comb2(xh0.y, xl0.y);
            sX[(xc*4+0)*132 + xr] = a.x; sX[(xc*4+1)*132 + xr] = a.y;
            sX[(xc*4+2)*132 + xr] = b.x; sX[(xc*4+3)*132 + xr] = b.y;
            float2 c = comb2(xh1.x, xl1.x), d = comb2(xh1.y, xl1.y);
            sX[(xc*4+0)*132 + xr+64] = c.x; sX[(xc*4+1)*132 + xr+64] = c.y;
            sX[(xc*4+2)*132 + xr+64] = d.x; sX[(xc*4+3)*132 + xr+64] = d.y;
        }
        if (wp) {
            sW[(xc*4+0)*36 + xr] = wv.x; sW[(xc*4+1)*36 + xr] = wv.y;
            sW[(xc*4+2)*36 + xr] = wv.z; sW[(xc*4+3)*36 + xr] = wv.w;
        }
        __syncthreads();
        const int k1 = k0 + 16;
        if (k1 < K) {
            xh0 = __ldg((const uint2*)(XpH0 + k1));
            xl0 = __ldg((const uint2*)(XpL0 + k1));
            xh1 = __ldg((const uint2*)(XpH1 + k1));
            xl1 = __ldg((const uint2*)(XpL1 + k1));
            if (wp) wv = __ldg((const float4*)(Wp + k1));
        }
#pragma unroll
        for (int kk = 0; kk < 16; kk++) {
            float4 a0 = *(const float4*)&sX[kk*132 + ty*8];
            float4 a1 = *(const float4*)&sX[kk*132 + ty*8 + 4];
            float2 b  = *(const float2*)&sW[kk*36 + tx*2];
            acc[0][0]+=a0.x*b.x; acc[0][1]+=a0.x*b.y;
            acc[1][0]+=a0.y*b.x; acc[1][1]+=a0.y*b.y;
            acc[2][0]+=a0.z*b.x; acc[2][1]+=a0.z*b.y;
            acc[3][0]+=a0.w*b.x; acc[3][1]+=a0.w*b.y;
            acc[4][0]+=a1.x*b.x; acc[4][1]+=a1.x*b.y;
            acc[5][0]+=a1.y*b.x; acc[5][1]+=a1.y*b.y;
            acc[6][0]+=a1.z*b.x; acc[6][1]+=a1.z*b.y;
            acc[7][0]+=a1.w*b.x; acc[7][1]+=a1.w*b.y;
        }
        __syncthreads();
        if (k1 >= K) break;
        k0 = k1;
    }

    float2 bb = *(const float2*)(bias + tx * 2);
#pragma unroll
    for (int i = 0; i < 8; i++) {
        int r = mB + ty * 8 + i;
        int b = r & (BATCH - 1);
        int t = t0 + (r >> 7);
        float2 v = make_float2(acc[i][0] + bb.x, acc[i][1] + bb.y);
        *(float2*)(out + ((size_t)b * HORIZON + t) * OBS + tx * 2) = v;
    }
}

// ---------------------------------------------------------------------------
// Phase-2 R1 prologue (old layout, W + V), 2 commit groups per half.
// ---------------------------------------------------------------------------
__device__ __forceinline__ void prologueW1(
    uint32_t sbase, int nT,
    const bf16* __restrict__ Wh, const bf16* __restrict__ Wl,
    const bf16* __restrict__ Vh, const bf16* __restrict__ Vl, int whCol0)
{
    const int tid = threadIdx.x;
    const int half = tid >> 8, lt = tid & 255;
#pragma unroll
    for (int s = 0; s < 2; s++) {
        const int c = half * 2 + s;
        const int k0 = c << 6;
        const uint32_t base = (uint32_t)c * (uint32_t)STAGE_W;
#pragma unroll
        for (int ii = 0; ii < 2; ii++) {
            const int o = lt + ii * 256;
            const int p = o >> 8, q = o & 255, row = q >> 3, sg = q & 7;
            const uint32_t dw = base + 2304u + (uint32_t)p * 1152u + row * 36u + sg * 4u;
            const bf16* src = (p ? Wl : Wh) + (size_t)(nT + row) * LAT + k0 + sg * 8;
            cpa16(sbase + dw * 4u, src);
        }
        if (lt < 128) {
            const int p = lt >> 6, q = lt & 63, row = q >> 3, sg = q & 7;
            const uint32_t dw = base + 4608u + (uint32_t)p * 288u + row * 36u + sg * 4u;
            const bf16* src = (p ? Vl : Vh) + (size_t)(whCol0 + row) * 256 + k0 + sg * 8;
            cpa16(sbase + dw * 4u, src);
        }
        asm volatile("cp.async.commit_group;" ::: "memory");
    }
}

// ---------------------------------------------------------------------------
// Phase-2 R1 region (old 64-chunk layout, warp-split halves, Whh strip).
// K = 256 fixed: nchH = 2 per half.
// ---------------------------------------------------------------------------
__device__ void mma_region1(
    uint32_t* SW, uint32_t sbase,
    int mT, int nT,
    const bf16* __restrict__ Xh, const bf16* __restrict__ Xl,
    const bf16* __restrict__ Wh, const bf16* __restrict__ Wl,
    const float* __restrict__ bias,
    bf16* __restrict__ Yh, bf16* __restrict__ Yl,
    float* __restrict__ Cout, int whCol0)
{
    const int tid = threadIdx.x;
    const int half = tid >> 8, lt = tid & 255;
    const int lane = tid & 31, lwid = (tid >> 5) & 7;
    const int mw = lwid >> 2, nw = lwid & 3;
    const int cBase = half * 2;

    // X prologue: 2 commit groups
#pragma unroll
    for (int s = 0; s < 2; s++) {
        const int k0 = (cBase + s) << 6;
        const uint32_t base = (uint32_t)(cBase + s) * (uint32_t)STAGE_W;
#pragma unroll
        for (int ii = 0; ii < 2; ii++) {
            const int o = lt + ii * 256;
            const int p = o >> 8, q = o & 255, row = q >> 3, sg = q & 7;
            const uint32_t dw = base + (uint32_t)p * 1152u + row * 36u + sg * 4u;
            const bf16* src = (p ? Xl : Xh) + (size_t)(mT + row) * LAT + k0 + sg * 8;
            cpa16(sbase + dw * 4u, src);
        }
        asm volatile("cp.async.commit_group;" ::: "memory");
    }

    float ahh[4] = {0,0,0,0}, ahl[4] = {0,0,0,0}, alh[4] = {0,0,0,0};
    float whh[4] = {0,0,0,0}, whl[4] = {0,0,0,0}, wlh[4] = {0,0,0,0};

    const int r0 = mw * 16 + (lane >> 2);
    const int wc = lane & 3;
    const int aoff0 = r0 * 36 + wc;
    const int aoff1 = (r0 + 8) * 36 + wc;
    const int boff = (nw * 8 + (lane >> 2)) * 36 + wc;
    const int voff = (lane >> 2) * 36 + wc;

    for (int lc = 0; lc < 2; lc++) {
        if (lc == 1) asm volatile("cp.async.wait_group 0;" ::: "memory");
        else         asm volatile("cp.async.wait_group 1;" ::: "memory");
        barh(half);
        const uint32_t* S   = SW + (cBase + lc) * STAGE_W;
        const uint32_t* XHs = S;
        const uint32_t* XLs = S + 1152;
        const uint32_t* WHs = S + 2304;
        const uint32_t* WLs = S + 3456;
        const uint32_t* VHs = S + 4608;
        const uint32_t* VLs = S + 4896;
#pragma unroll
        for (int wb = 0; wb < 32; wb += 8) {
            uint32_t ah[4], al[4];
            ah[0] = XHs[aoff0 + wb];     ah[1] = XHs[aoff1 + wb];
            ah[2] = XHs[aoff0 + wb + 4]; ah[3] = XHs[aoff1 + wb + 4];
            al[0] = XLs[aoff0 + wb];     al[1] = XLs[aoff1 + wb];
            al[2] = XLs[aoff0 + wb + 4]; al[3] = XLs[aoff1 + wb + 4];
            uint32_t bh0 = WHs[boff + wb], bh1 = WHs[boff + wb + 4];
            uint32_t bl0 = WLs[boff + wb], bl1 = WLs[boff + wb + 4];
            mma16(ahh, ah, bh0, bh1);
            mma16(ahl, ah, bl0, bl1);
            mma16(alh, al, bh0, bh1);
            if (nw == 0) {
                uint32_t vh0 = VHs[voff + wb], vh1 = VHs[voff + wb + 4];
                uint32_t vl0 = VLs[voff + wb], vl1 = VLs[voff + wb + 4];
                mma16(whh, ah, vh0, vh1);
                mma16(whl, ah, vl0, vl1);
                mma16(wlh, al, vh0, vh1);
            }
        }
        barh(half);
    }

    // cross-half reduce + epilogue
    float* RED  = (float*)SW + RED_OFF;
    float* REDW = (float*)SW + REDW_OFF;
    const int ocol_l = nw * 8 + wc * 2;
    __syncthreads();
    if (half == 0) {
        RED[r0 * 33 + ocol_l]           = ahh[0] + ahl[0] + alh[0];
        RED[r0 * 33 + ocol_l + 1]       = ahh[1] + ahl[1] + alh[1];
        RED[(r0 + 8) * 33 + ocol_l]     = ahh[2] + ahl[2] + alh[2];
        RED[(r0 + 8) * 33 + ocol_l + 1] = ahh[3] + ahl[3] + alh[3];
        if (nw == 0) {
            REDW[r0 * 9 + wc * 2]           = whh[0] + whl[0] + wlh[0];
            REDW[r0 * 9 + wc * 2 + 1]       = whh[1] + whl[1] + wlh[1];
            REDW[(r0 + 8) * 9 + wc * 2]     = whh[2] + whl[2] + wlh[2];
            REDW[(r0 + 8) * 9 + wc * 2 + 1] = whh[3] + whl[3] + wlh[3];
        }
    }
    __syncthreads();

    if (half == 1) {
        const int orow = mT + r0;
        const int ocol = nT + ocol_l;
        float2 bb = *(const float2*)(bias + ocol);
        float v0 = RED[r0 * 33 + ocol_l]           + ahh[0] + ahl[0] + alh[0] + bb.x;
        float v1 = RED[r0 * 33 + ocol_l + 1]       + ahh[1] + ahl[1] + alh[1] + bb.y;
        float v2 = RED[(r0 + 8) * 33 + ocol_l]     + ahh[2] + ahl[2] + alh[2] + bb.x;
        float v3 = RED[(r0 + 8) * 33 + ocol_l + 1] + ahh[3] + ahl[3] + alh[3] + bb.y;
        v0 = fmaxf(v0, 0.f); v1 = fmaxf(v1, 0.f);
        v2 = fmaxf(v2, 0.f); v3 = fmaxf(v3, 0.f);
        uint32_t hw, lw;
        split_pack(v0, v1, hw, lw);
        __stcg((uint32_t*)&Yh[(size_t)orow * HID + ocol], hw);
        __stcg((uint32_t*)&Yl[(size_t)orow * HID + ocol], lw);
        split_pack(v2, v3, hw, lw);
        __stcg((uint32_t*)&Yh[(size_t)(orow + 8) * HID + ocol], hw);
        __stcg((uint32_t*)&Yl[(size_t)(orow + 8) * HID + ocol], lw);
        if (nw == 0) {
            const int wcol = whCol0 + wc * 2;
            float w0 = REDW[r0 * 9 + wc * 2]           + whh[0] + whl[0] + wlh[0];
            float w1 = REDW[r0 * 9 + wc * 2 + 1]       + whh[1] + whl[1] + wlh[1];
            float w2 = REDW[(r0 + 8) * 9 + wc * 2]     + whh[2] + whl[2] + wlh[2];
            float w3 = REDW[(r0 + 8) * 9 + wc * 2 + 1] + whh[3] + whl[3] + wlh[3];
            __stcg((float2*)&Cout[(size_t)(mT + r0) * LAT + wcol], make_float2(w0, w1));
            __stcg((float2*)&Cout[(size_t)(mT + r0 + 8) * LAT + wcol], make_float2(w2, w3));
        }
    }
}

// ---------------------------------------------------------------------------
// Phase-2 R2-R4 W prologue (new layout, K=128 chunks), 2 commit groups/half.
// ---------------------------------------------------------------------------
__device__ __forceinline__ void prologueW2(
    uint32_t sbase, int nT,
    const bf16* __restrict__ Wh, const bf16* __restrict__ Wl)
{
    const int tid = threadIdx.x;
    const int half = tid >> 8, lt = tid & 255;
#pragma unroll
    for (int s = 0; s < 2; s++) {
        const int c = half * 4 + s;
        const int k0 = c << 7;
        const uint32_t base = (uint32_t)(half * 2 + s) * (uint32_t)STAGE2_W;
#pragma unroll
        for (int ii = 0; ii < 4; ii++) {
            const int o = lt + ii * 256;
            const int p = o >> 9, q = o & 511, row = q >> 4, sx = q & 15;
            const uint32_t dw = base + 4352u + (uint32_t)p * 2176u + row * 68u + sx * 4u;
            const bf16* src = (p ? Wl : Wh) + (size_t)(nT + row) * HID + k0 + sx * 8;
            cpa16(sbase + dw * 4u, src);
        }
        asm volatile("cp.async.commit_group;" ::: "memory");
    }
}

// ---------------------------------------------------------------------------
// Phase-2 R2-R4 region: K=1024, K=128 chunks, 4/half, 2 stages/half.
// ---------------------------------------------------------------------------
template<bool DOL5>
__device__ void mma_region2(
    uint32_t* SW, uint32_t sbase,
    int mT, int nT,
    const bf16* __restrict__ Xh, const bf16* __restrict__ Xl,
    const bf16* __restrict__ Wh, const bf16* __restrict__ Wl,
    const float* __restrict__ bias,
    bf16* __restrict__ Yh, bf16* __restrict__ Yl,
    const float* __restrict__ W5, float* __restrict__ yhpart, int jIdx)
{
    const int tid = threadIdx.x;
    const int half = tid >> 8, lt = tid & 255;
    const int lane = tid & 31, lwid = (tid >> 5) & 7;
    const int mw = lwid >> 2, nw = lwid & 3;
    const int cBase = half * 4;
    const int sBase = half * 2;

    // X prologue: 2 commit groups
#pragma unroll
    for (int s = 0; s < 2; s++) {
        const int k0 = (cBase + s) << 7;
        const uint32_t base = (uint32_t)(sBase + s) * (uint32_t)STAGE2_W;
#pragma unroll
        for (int ii = 0; ii < 4; ii++) {
            const int o = lt + ii * 256;
            const int p = o >> 9, q = o & 511, row = q >> 4, sx = q & 15;
            const uint32_t dw = base + (uint32_t)p * 2176u + row * 68u + sx * 4u;
            const bf16* src = (p ? Xl : Xh) + (size_t)(mT + row) * HID + k0 + sx * 8;
            cpa16(sbase + dw * 4u, src);
        }
        asm volatile("cp.async.commit_group;" ::: "memory");
    }

    auto issueC = [&](int lc) {
        const int k0 = (cBase + lc) << 7;
        const uint32_t base = (uint32_t)(sBase + (lc & 1)) * (uint32_t)STAGE2_W;
#pragma unroll
        for (int ii = 0; ii < 8; ii++) {
            const int o = lt + ii * 256;
            const int p = o >> 9, q = o & 511, row = q >> 4, sx = q & 15;
            const int plane = p & 1;
            const uint32_t dw = base + (uint32_t)(p >> 1) * 4352u
                              + (uint32_t)plane * 2176u + row * 68u + sx * 4u;
            const bf16* src;
            if (p == 0)      src = Xh + (size_t)(mT + row) * HID + k0 + sx * 8;
            else if (p == 1) src = Xl + (size_t)(mT + row) * HID + k0 + sx * 8;
            else if (p == 2) src = Wh + (size_t)(nT + row) * HID + k0 + sx * 8;
            else             src = Wl + (size_t)(nT + row) * HID + k0 + sx * 8;
            cpa16(sbase + dw * 4u, src);
        }
        asm volatile("cp.async.commit_group;" ::: "memory");
    };

    float ahh[4] = {0,0,0,0}, ahl[4] = {0,0,0,0}, alh[4] = {0,0,0,0};

    const int r0 = mw * 16 + (lane >> 2);
    const int wc = lane & 3;
    const int aoff0 = r0 * 68 + wc;
    const int aoff1 = (r0 + 8) * 68 + wc;
    const int boff = (nw * 8 + (lane >> 2)) * 68 + wc;

    for (int lc = 0; lc < 4; lc++) {
        if (lc >= 3) asm volatile("cp.async.wait_group 0;" ::: "memory");
        else         asm volatile("cp.async.wait_group 1;" ::: "memory");
        barh(half);
        const uint32_t* S   = SW + (sBase + (lc & 1)) * STAGE2_W;
        const uint32_t* XHs = S;
        const uint32_t* XLs = S + 2176;
        const uint32_t* WHs = S + 4352;
        const uint32_t* WLs = S + 6528;
#pragma unroll
        for (int wb = 0; wb < 64; wb += 8) {
            uint32_t ah[4], al[4];
            ah[0] = XHs[aoff0 + wb];     ah[1] = XHs[aoff1 + wb];
            ah[2] = XHs[aoff0 + wb + 4]; ah[3] = XHs[aoff1 + wb + 4];
            al[0] = XLs[aoff0 + wb];     al[1] = XLs[aoff1 + wb];
            al[2] = XLs[aoff0 + wb + 4]; al[3] = XLs[aoff1 + wb + 4];
            uint32_t bh0 = WHs[boff + wb], bh1 = WHs[boff + wb + 4];
            uint32_t bl0 = WLs[boff + wb], bl1 = WLs[boff + wb + 4];
            mma16(ahh, ah, bh0, bh1);
            mma16(ahl, ah, bl0, bl1);
            mma16(alh, al, bh0, bh1);
        }
        barh(half);
        if (lc + 2 < 4) issueC(lc + 2);
    }

    float* RED = (float*)SW + RED_OFF;
    const int ocol_l = nw * 8 + wc * 2;
    __syncthreads();
    if (half == 0) {
        RED[r0 * 33 + ocol_l]           = ahh[0] + ahl[0] + alh[0];
        RED[r0 * 33 + ocol_l + 1]       = ahh[1] + ahl[1] + alh[1];
        RED[(r0 + 8) * 33 + ocol_l]     = ahh[2] + ahl[2] + alh[2];
        RED[(r0 + 8) * 33 + ocol_l + 1] = ahh[3] + ahl[3] + alh[3];
    }
    __syncthreads();

    float* sh4 = (float*)SW + SH4_OFF;
    if (half == 1) {
        const int orow = mT + r0;
        const int ocol = nT + ocol_l;
        float2 bb = *(const float2*)(bias + ocol);
        float v0 = RED[r0 * 33 + ocol_l]           + ahh[0] + ahl[0] + alh[0] + bb.x;
        float v1 = RED[r0 * 33 + ocol_l + 1]       + ahh[1] + ahl[1] + alh[1] + bb.y;
        float v2 = RED[(r0 + 8) * 33 + ocol_l]     + ahh[2] + ahl[2] + alh[2] + bb.x;
        float v3 = RED[(r0 + 8) * 33 + ocol_l + 1] + ahh[3] + ahl[3] + alh[3] + bb.y;
        v0 = fmaxf(v0, 0.f); v1 = fmaxf(v1, 0.f);
        v2 = fmaxf(v2, 0.f); v3 = fmaxf(v3, 0.f);
        if (DOL5) {
            sh4[r0 * 33 + ocol_l]           = v0;
            sh4[r0 * 33 + ocol_l + 1]       = v1;
            sh4[(r0 + 8) * 33 + ocol_l]     = v2;
            sh4[(r0 + 8) * 33 + ocol_l + 1] = v3;
        } else {
            uint32_t hw, lw;
            split_pack(v0, v1, hw, lw);
            __stcg((uint32_t*)&Yh[(size_t)orow * HID + ocol], hw);
            __stcg((uint32_t*)&Yl[(size_t)orow * HID + ocol], lw);
            split_pack(v2, v3, hw, lw);
            __stcg((uint32_t*)&Yh[(size_t)(orow + 8) * HID + ocol], hw);
            __stcg((uint32_t*)&Yl[(size_t)(orow + 8) * HID + ocol], lw);
        }
    }

    if (DOL5) {
        __syncthreads();
        const float* w5r = W5 + (size_t)lane * HID + nT;
        float w5f[32];
#pragma unroll
        for (int q = 0; q < 8; q++) {
            float4 w = __ldg((const float4*)(w5r + q * 4));
            w5f[q*4+0] = w.x; w5f[q*4+1] = w.y; w5f[q*4+2] = w.z; w5f[q*4+3] = w.w;
        }
        const int wfull = tid >> 5;
#pragma unroll
        for (int i = 0; i < 2; i++) {
            const int r = wfull * 2 + i;
            const float* hr = sh4 + r * 33;
            float s = 0.f;
#pragma unroll
            for (int n = 0; n < 32; n++) s += hr[n] * w5f[n];
            __stcg(yhpart + (size_t)jIdx * (BATCH * 32) + (mT + r) * 32 + lane, s);
        }
    }
}

// ---------------------------------------------------------------------------
// Phase 2: 128 CTAs x 512 threads, 4 groups of 32, 5 barriers/step.
// ---------------------------------------------------------------------------
__global__ void __launch_bounds__(512, 1) phase2_kernel(
    const float* __restrict__ b1, const float* __restrict__ b2,
    const float* __restrict__ b3, const float* __restrict__ b4,
    const float* __restrict__ W5, const float* __restrict__ b5,
    const float* __restrict__ Wih,
    const float* __restrict__ bih, const float* __restrict__ bhh,
    const float* __restrict__ Z,
    float* __restrict__ PL,
    float* __restrict__ out)
{
    extern __shared__ __align__(16) uint32_t SW[];
    const uint32_t sbase = (uint32_t)__cvta_generic_to_shared(SW);
    const int bid = blockIdx.x, tid = threadIdx.x;
    const int g = bid >> 5, j = bid & 31;
    const int mT = g * 32, nT = j * 32;
    const int b = bid;
    unsigned target = 0;

    bf16* AH = (bf16*)(PL + C_AH);
    bf16* AL = (bf16*)(PL + C_AL);
    bf16* BH = (bf16*)(PL + C_BH);
    bf16* BL = (bf16*)(PL + C_BL);
    bf16* ZH = (bf16*)(PL + C_ZH);
    bf16* ZL = (bf16*)(PL + C_ZL);
    float* C  = PL + C_C;
    float* YP = PL + C_YP;

    const bf16 *W1H = g_WHB + OFF_W1,  *W1L = g_WLB + OFF_W1;
    const bf16 *W2H = g_WHB + OFF_W2,  *W2L = g_WLB + OFF_W2;
    const bf16 *W3H = g_WHB + OFF_W3,  *W3L = g_WLB + OFF_W3;
    const bf16 *W4H = g_WHB + OFF_W4,  *W4L = g_WLB + OFF_W4;
    const bf16 *VH  = g_WHB + OFF_WHH, *VL  = g_WLB + OFF_WHH;

    if (tid < 128) {
        float2 z2 = __ldcg((const float2*)(Z + (size_t)TSTEPS * ZSTRIDE + (size_t)b * LAT) + tid);
        uint32_t hw, lw;
        split_pack(z2.x, z2.y, hw, lw);
        __stcg((uint32_t*)(ZH + (size_t)b * LAT) + tid, hw);
        __stcg((uint32_t*)(ZL + (size_t)b * LAT) + tid, lw);
    }
    prologueW1(sbase, nT, W1H, W1L, VH, VL, j * 8);
    ggsync(g, target);

    for (int t = TSTEPS; t < HORIZON; t++) {
        mma_region1(SW, sbase, mT, nT, ZH, ZL, W1H, W1L, b1, AH, AL, C, j * 8);
        prologueW2(sbase, nT, W2H, W2L);
        ggsync(g, target);
        mma_region2<false>(SW, sbase, mT, nT, AH, AL, W2H, W2L, b2, BH, BL,
                           (const float*)0, (float*)0, 0);
        prologueW2(sbase, nT, W3H, W3L);
        ggsync(g, target);
        mma_region2<false>(SW, sbase, mT, nT, BH, BL, W3H, W3L, b3, AH, AL,
                           (const float*)0, (float*)0, 0);
        prologueW2(sbase, nT, W4H, W4L);
        ggsync(g, target);
        mma_region2<true>(SW, sbase, mT, nT, AH, AL, W4H, W4L, b4,
                          (bf16*)0, (bf16*)0, W5, YP, j);
        ggsync(g, target);

        // R5: combine yh partials -> out; cell finish
        {
            float* FS = (float*)SW;
            if (tid < OBS) {
                float s = __ldg(b5 + tid);
                const float* yp = YP + (size_t)b * 32 + tid;
#pragma unroll
                for (int jj = 0; jj < 32; jj++)
                    s += __ldcg(yp + (size_t)jj * (BATCH * 32));
                __stcg(out + ((size_t)b * HORIZON + t) * OBS + tid, s);
                FS[tid] = s;
            }
            __syncthreads();
            if (t < HORIZON - 1) {
                if (tid < 256) {
                    const int n = tid;
                    float acc = __ldcg(C + (size_t)b * LAT + n)
                              + __ldg(bih + n) + __ldg(bhh + n);
                    const float4* wr = (const float4*)(Wih + (size_t)n * OBS);
#pragma unroll
                    for (int k = 0; k < 8; k++) {
                        float4 wv = __ldg(wr + k);
                        acc += FS[k*4+0]*wv.x + FS[k*4+1]*wv.y
                             + FS[k*4+2]*wv.z + FS[k*4+3]*wv.w;
                    }
                    FS[64 + n] = tanhf(acc);
                }
                __syncthreads();
                if (tid < 128) {
                    float z0 = FS[64 + 2*tid], z1 = FS[64 + 2*tid + 1];
                    uint32_t hw, lw;
                    split_pack(z0, z1, hw, lw);
                    __stcg((uint32_t*)(ZH + (size_t)b * LAT) + tid, hw);
                    __stcg((uint32_t*)(ZL + (size_t)b * LAT) + tid, lw);
                }
                __syncthreads();
                prologueW1(sbase, nT, W1H, W1L, VH, VL, j * 8);
            }
        }
        ggsync(g, target);
    }
}

// ---------------------------------------------------------------------------
// Launch (phase2 at our launch index 3 for ncu)
// ---------------------------------------------------------------------------
extern "C" void kernel_launch(void* const* d_in, const int* in_sizes, int n_in,
                              void* d_out, int out_size)
{
    const float* y   = (const float*)d_in[0];
    const float* Wih = (const float*)d_in[2];
    const float* Whh = (const float*)d_in[3];
    const float* bih = (const float*)d_in[4];
    const float* bhh = (const float*)d_in[5];
    const float* W1  = (const float*)d_in[6];
    const float* b1  = (const float*)d_in[7];
    const float* W2  = (const float*)d_in[8];
    const float* b2  = (const float*)d_in[9];
    const float* W3  = (const float*)d_in[10];
    const float* b3  = (const float*)d_in[11];
    const float* W4  = (const float*)d_in[12];
    const float* b4  = (const float*)d_in[13];
    const float* W5  = (const float*)d_in[14];
    const float* b5  = (const float*)d_in[15];
    float* out = (float*)d_out;

    float *Z, *A, *Bf;
    bf16 *WHB, *WLB, *ZPH, *ZPL;
    cudaGetSymbolAddress((void**)&Z,    g_Z);
    cudaGetSymbolAddress((void**)&A,    g_A);
    cudaGetSymbolAddress((void**)&Bf,   g_B);
    cudaGetSymbolAddress((void**)&WHB,  g_WHB);
    cudaGetSymbolAddress((void**)&WLB,  g_WLB);
    cudaGetSymbolAddress((void**)&ZPH,  g_ZPH);
    cudaGetSymbolAddress((void**)&ZPL,  g_ZPL);

    static int attr_done = 0;
    if (!attr_done) {
        cudaFuncSetAttribute(phase2_kernel,
                             cudaFuncAttributeMaxDynamicSharedMemorySize, P2_SMEM);
        cudaFuncSetAttribute(gemm_mma_128,
                             cudaFuncAttributeMaxDynamicSharedMemorySize, SMEM1B);
        attr_done = 1;
    }

    // [0] fused weight hi/lo split
    splitw_all<<<(NW_TOT + 255)/256, 256>>>(W1, W2, W3, W4, Whh);

    // [1] phase 1a (64 CTAs x 2 rows; also zeroes group barriers)
    phase1a_kernel<<<BATCH / 2, 256>>>(y, Wih, Whh, bih, bhh, Z);

    // [2] split teacher-forced z states into bf16 planes
    splitw_bf16<<<(TSTEPS * ZSTRIDE + 255)/256, 256>>>(Z, ZPH, ZPL, TSTEPS * ZSTRIDE);

    // [3] phase 2 (persistent AR rollout) — profiled launch
    phase2_kernel<<<128, 512, P2_SMEM>>>(b1, b2, b3, b4, W5, b5, Wih, bih, bhh,
                                         Z, Z + (size_t)P2_BASE, out);

    // [4..13] phase 1b: 2 chunks of 128 steps, bf16-pair MMA (128x128 tiles)
    const int CHUNK = 128;
    const int MBIG  = CHUNK * BATCH;
    bf16* AH = (bf16*)A;
    bf16* AL = (bf16*)A + (size_t)MBIG * HID;
    bf16* BH = (bf16*)Bf;
    bf16* BL = (bf16*)Bf + (size_t)MBIG * HID;
    for (int c = 0; c < TSTEPS / CHUNK; c++) {
        const bf16* XzH = ZPH + (size_t)c * CHUNK * ZSTRIDE;
        const bf16* XzL = ZPL + (size_t)c * CHUNK * ZSTRIDE;
        gemm_mma_128<<<dim3(HID/128, MBIG/128), 256, SMEM1B>>>(
            XzH, XzL, LAT, WHB + OFF_W1, WLB + OFF_W1, LAT, b1, AH, AL, HID, LAT);
        gemm_mma_128<<<dim3(HID/128, MBIG/128), 256, SMEM1B>>>(
            AH, AL, HID, WHB + OFF_W2, WLB + OFF_W2, HID, b2, BH, BL, HID, HID);
        gemm_mma_128<<<dim3(HID/128, MBIG/128), 256, SMEM1B>>>(
            BH, BL, HID, WHB + OFF_W3, WLB + OFF_W3, HID, b3, AH, AL, HID, HID);
        gemm_mma_128<<<dim3(HID/128, MBIG/128), 256, SMEM1B>>>(
            AH, AL, HID, WHB + OFF_W4, WLB + OFF_W4, HID, b4, BH, BL, HID, HID);
        gemm_out_bf<<<dim3(1, MBIG/128), 256>>>(
            BH, BL, HID, W5, HID, b5, out, HID, c * CHUNK);
    }
}

// round 17
// speedup vs baseline: 2.4401x; 1.1235x over previous
#include <cuda_runtime.h>
#include <cuda_bf16.h>
#include <math.h>
#include <stdint.h>

#define BATCH   128
#define TSTEPS  256
#define HORIZON 512
#define OBS     32
#define LAT     256
#define HID     1024
#define ZSTRIDE (BATCH * LAT)

typedef __nv_bfloat16 bf16;

#define STAGE_W 5184
#define STAGE2_W 8704
#define P2_SMEM (4 * STAGE2_W * 4)

#define S1B_W   10240
#define NST1B   3
#define SMEM1B  (NST1B * S1B_W * 4)

// ---------------------------------------------------------------------------
// Scratch
// ---------------------------------------------------------------------------
__device__ float g_Z[(size_t)(HORIZON + 1) * ZSTRIDE];
__device__ float g_A[(size_t)128 * BATCH * HID];
__device__ float g_B[(size_t)128 * BATCH * HID];
__device__ bf16  g_ZPH[(size_t)TSTEPS * ZSTRIDE];
__device__ bf16  g_ZPL[(size_t)TSTEPS * ZSTRIDE];
__device__ bf16  g_WHB[3473408];
__device__ bf16  g_WLB[3473408];
__device__ unsigned g_gbar[4 * 32];

#define OFF_W1  0
#define OFF_W2  262144
#define OFF_W3  1310720
#define OFF_W4  2359296
#define OFF_WHH 3407872
#define NW_TOT  3473408

#define P2_BASE (320 * ZSTRIDE)
#define C_AH    0
#define C_AL    65536
#define C_BH    131072
#define C_BL    196608
#define C_ZH    262144
#define C_ZL    278528
#define C_C     294912
#define C_YP    327680

#define RED_OFF   0
#define REDW_OFF  1100
#define SH4_OFF   1408

// ---------------------------------------------------------------------------
// helpers
// ---------------------------------------------------------------------------
__device__ __forceinline__ void mma16(float* d, const uint32_t* a, uint32_t b0, uint32_t b1) {
    asm volatile(
        "mma.sync.aligned.m16n8k16.row.col.f32.bf16.bf16.f32 "
        "{%0,%1,%2,%3},{%4,%5,%6,%7},{%8,%9},{%0,%1,%2,%3};"
        : "+f"(d[0]), "+f"(d[1]), "+f"(d[2]), "+f"(d[3])
        : "r"(a[0]), "r"(a[1]), "r"(a[2]), "r"(a[3]), "r"(b0), "r"(b1));
}
__device__ __forceinline__ void cpa16(uint32_t dst, const void* src) {
    asm volatile("cp.async.cg.shared.global [%0], [%1], 16;" :: "r"(dst), "l"(src));
}
__device__ __forceinline__ void barh(int h) {
    asm volatile("bar.sync %0, 256;" :: "r"(h + 1) : "memory");
}
__device__ __forceinline__ void wait_1b(int rem) {
    if (rem >= 2)      asm volatile("cp.async.wait_group 2;" ::: "memory");
    else if (rem == 1) asm volatile("cp.async.wait_group 1;" ::: "memory");
    else               asm volatile("cp.async.wait_group 0;" ::: "memory");
}
__device__ __forceinline__ void split_pack(float v0, float v1, uint32_t& hw, uint32_t& lw) {
    bf16 h0 = __float2bfloat16(v0);
    bf16 h1 = __float2bfloat16(v1);
    bf16 l0 = __float2bfloat16(v0 - __bfloat162float(h0));
    bf16 l1 = __float2bfloat16(v1 - __bfloat162float(h1));
    hw = ((uint32_t)__bfloat16_as_ushort(h1) << 16) | __bfloat16_as_ushort(h0);
    lw = ((uint32_t)__bfloat16_as_ushort(l1) << 16) | __bfloat16_as_ushort(l0);
}
__device__ __forceinline__ float2 comb2(uint32_t h, uint32_t l) {
    float2 r;
    r.x = __bfloat162float(__ushort_as_bfloat16((unsigned short)(h & 0xffff)))
        + __bfloat162float(__ushort_as_bfloat16((unsigned short)(l & 0xffff)));
    r.y = __bfloat162float(__ushort_as_bfloat16((unsigned short)(h >> 16)))
        + __bfloat162float(__ushort_as_bfloat16((unsigned short)(l >> 16)));
    return r;
}

__device__ __forceinline__ void ggsync(int g, unsigned& target) {
    target += 32;
    __syncthreads();
    __threadfence();
    if (threadIdx.x == 0) {
        atomicAdd(&g_gbar[g * 32], 1u);
        while (*((volatile unsigned*)&g_gbar[g * 32]) < target) {}
        __threadfence();
    }
    __syncthreads();
}

__global__ void splitw_all(const float* __restrict__ W1, const float* __restrict__ W2,
                           const float* __restrict__ W3, const float* __restrict__ W4,
                           const float* __restrict__ Whh)
{
    int i = blockIdx.x * 256 + threadIdx.x;
    if (i >= NW_TOT) return;
    const float* src; int off;
    if (i < OFF_W2)       { src = W1;  off = OFF_W1; }
    else if (i < OFF_W3)  { src = W2;  off = OFF_W2; }
    else if (i < OFF_W4)  { src = W3;  off = OFF_W3; }
    else if (i < OFF_WHH) { src = W4;  off = OFF_W4; }
    else                  { src = Whh; off = OFF_WHH; }
    float v = src[i - off];
    bf16 h = __float2bfloat16(v);
    g_WHB[i] = h;
    g_WLB[i] = __float2bfloat16(v - __bfloat162float(h));
}

__global__ void splitw_bf16(const float* __restrict__ src,
                            bf16* __restrict__ hi, bf16* __restrict__ lo, int n)
{
    int i = blockIdx.x * 256 + threadIdx.x;
    if (i < n) {
        float v = src[i];
        bf16 h = __float2bfloat16(v);
        hi[i] = h;
        lo[i] = __float2bfloat16(v - __bfloat162float(h));
    }
}

// ---------------------------------------------------------------------------
// Phase 1a: 64 CTAs x 2 batch rows (unchanged; zeroes group barriers)
// ---------------------------------------------------------------------------
__global__ void __launch_bounds__(256) phase1a_kernel(
    const float* __restrict__ y,
    const float* __restrict__ Wih, const float* __restrict__ Whh,
    const float* __restrict__ bih, const float* __restrict__ bhh,
    float* __restrict__ Z)
{
    const int tid = threadIdx.x;
    const int r0 = blockIdx.x * 2, r1 = r0 + 1;
    __shared__ float sz0[LAT], sz1[LAT];
    __shared__ float sy0[OBS], sy1[OBS];

    if (blockIdx.x == 0 && tid < 128) g_gbar[tid] = 0u;

    sz0[tid] = 0.0f; sz1[tid] = 0.0f;
    __stcg(Z + (size_t)r0 * LAT + tid, 0.0f);
    __stcg(Z + (size_t)r1 * LAT + tid, 0.0f);
    float bsum = __ldg(bih + tid) + __ldg(bhh + tid);

    float4 wi[8];
    const float4* wip = (const float4*)(Wih + (size_t)tid * OBS);
#pragma unroll
    for (int k = 0; k < 8; k++) wi[k] = __ldg(wip + k);
    const float4* wh = (const float4*)(Whh + (size_t)tid * LAT);
    __syncthreads();

    for (int t = 0; t < TSTEPS; t++) {
        if (tid < OBS)
            sy0[tid] = __ldg(y + ((size_t)r0 * TSTEPS + t) * OBS + tid);
        else if (tid < 2 * OBS)
            sy1[tid - OBS] = __ldg(y + ((size_t)r1 * TSTEPS + t) * OBS + (tid - OBS));
        __syncthreads();
        float acc0 = bsum, acc1 = bsum;
#pragma unroll
        for (int k = 0; k < 8; k++) {
            float4 w = wi[k];
            acc0 += sy0[k*4+0]*w.x + sy0[k*4+1]*w.y + sy0[k*4+2]*w.z + sy0[k*4+3]*w.w;
            acc1 += sy1[k*4+0]*w.x + sy1[k*4+1]*w.y + sy1[k*4+2]*w.z + sy1[k*4+3]*w.w;
        }
#pragma unroll 8
        for (int k = 0; k < 64; k++) {
            float4 w = __ldg(wh + k);
            acc0 += sz0[k*4+0]*w.x + sz0[k*4+1]*w.y + sz0[k*4+2]*w.z + sz0[k*4+3]*w.w;
            acc1 += sz1[k*4+0]*w.x + sz1[k*4+1]*w.y + sz1[k*4+2]*w.z + sz1[k*4+3]*w.w;
        }
        float z0 = tanhf(acc0), z1 = tanhf(acc1);
        __syncthreads();
        sz0[tid] = z0; sz1[tid] = z1;
        __stcg(Z + ((size_t)t + 1) * ZSTRIDE + (size_t)r0 * LAT + tid, z0);
        __stcg(Z + ((size_t)t + 1) * ZSTRIDE + (size_t)r1 * LAT + tid, z1);
    }
}

// ---------------------------------------------------------------------------
// Phase 1b bf16-pair MMA GEMM: 128x128 tile, 3-stage (round-15 version)
// ---------------------------------------------------------------------------
__global__ void __launch_bounds__(256) gemm_mma_128(
    const bf16* __restrict__ Xh, const bf16* __restrict__ Xl, int ldx,
    const bf16* __restrict__ Wh, const bf16* __restrict__ Wl, int ldw,
    const float* __restrict__ bias,
    bf16* __restrict__ Yh, bf16* __restrict__ Yl, int ldy, int K)
{
    extern __shared__ __align__(16) uint32_t SW[];
    const uint32_t sbase = (uint32_t)__cvta_generic_to_shared(SW);
    const int tid = threadIdx.x, lane = tid & 31, wid = tid >> 5;
    const int mw = wid >> 2, nw = wid & 3;
    const int mB = blockIdx.y * 128, nB = blockIdx.x * 128;
    const int nch = K >> 5;

    auto issue = [&](int c, int s) {
        const int k0 = c << 5;
        const uint32_t base = (uint32_t)s * (uint32_t)S1B_W;
#pragma unroll
        for (int ii = 0; ii < 8; ii++) {
            const int o = tid + ii * 256;
            const int p = o >> 9, q = o & 511, row = q >> 2, sg = q & 3;
            const uint32_t dw = base + (uint32_t)p * 2560u + row * 20u + sg * 4u;
            const bf16* src;
            if (p == 0)      src = Xh + (size_t)(mB + row) * ldx + k0 + sg * 8;
            else if (p == 1) src = Xl + (size_t)(mB + row) * ldx + k0 + sg * 8;
            else if (p == 2) src = Wh + (size_t)(nB + row) * ldw + k0 + sg * 8;
            else             src = Wl + (size_t)(nB + row) * ldw + k0 + sg * 8;
            cpa16(sbase + dw * 4u, src);
        }
        asm volatile("cp.async.commit_group;" ::: "memory");
    };

    float acc[4][4][4];
#pragma unroll
    for (int f = 0; f < 4; f++)
#pragma unroll
        for (int g = 0; g < 4; g++)
#pragma unroll
            for (int i = 0; i < 4; i++) acc[f][g][i] = 0.0f;

#pragma unroll
    for (int c0 = 0; c0 < NST1B; c0++)
        if (c0 < nch) issue(c0, c0);

    const int arow = lane >> 2, acol = lane & 3;
    int stage = 0;

    for (int c = 0; c < nch; c++) {
        wait_1b(nch - 1 - c);
        __syncthreads();
        const uint32_t* S   = SW + stage * S1B_W;
        const uint32_t* XHs = S;
        const uint32_t* XLs = S + 2560;
        const uint32_t* WHs = S + 5120;
        const uint32_t* WLs = S + 7680;
#pragma unroll
        for (int wb = 0; wb < 16; wb += 8) {
            uint32_t bh[4][2], bl[4][2];
#pragma unroll
            for (int g = 0; g < 4; g++) {
                int boff = (nw * 32 + g * 8 + arow) * 20 + acol + wb;
                bh[g][0] = WHs[boff]; bh[g][1] = WHs[boff + 4];
                bl[g][0] = WLs[boff]; bl[g][1] = WLs[boff + 4];
            }
#pragma unroll
            for (int f = 0; f < 4; f++) {
                int r = mw * 64 + f * 16 + arow;
                int aoff  = r * 20 + acol + wb;
                int aoff8 = (r + 8) * 20 + acol + wb;
                uint32_t ah[4] = {XHs[aoff], XHs[aoff8], XHs[aoff + 4], XHs[aoff8 + 4]};
                uint32_t al[4] = {XLs[aoff], XLs[aoff8], XLs[aoff + 4], XLs[aoff8 + 4]};
#pragma unroll
                for (int g = 0; g < 4; g++) {
                    mma16(acc[f][g], ah, bh[g][0], bh[g][1]);
                    mma16(acc[f][g], ah, bl[g][0], bl[g][1]);
                    mma16(acc[f][g], al, bh[g][0], bh[g][1]);
                }
            }
        }
        __syncthreads();
        if (c + NST1B < nch) issue(c + NST1B, stage);
        stage = (stage == NST1B - 1) ? 0 : stage + 1;
    }

#pragma unroll
    for (int f = 0; f < 4; f++) {
#pragma unroll
        for (int g = 0; g < 4; g++) {
            const int r0 = mB + mw * 64 + f * 16 + arow;
            const int col = nB + nw * 32 + g * 8 + acol * 2;
            float2 bb = *(const float2*)(bias + col);
            float v0 = fmaxf(acc[f][g][0] + bb.x, 0.f);
            float v1 = fmaxf(acc[f][g][1] + bb.y, 0.f);
            float v2 = fmaxf(acc[f][g][2] + bb.x, 0.f);
            float v3 = fmaxf(acc[f][g][3] + bb.y, 0.f);
            uint32_t hw, lw;
            split_pack(v0, v1, hw, lw);
            __stcg((uint32_t*)&Yh[(size_t)r0 * ldy + col], hw);
            __stcg((uint32_t*)&Yl[(size_t)r0 * ldy + col], lw);
            split_pack(v2, v3, hw, lw);
            __stcg((uint32_t*)&Yh[(size_t)(r0 + 8) * ldy + col], hw);
            __stcg((uint32_t*)&Yl[(size_t)(r0 + 8) * ldy + col], lw);
        }
    }
}

// ---------------------------------------------------------------------------
// Phase 1b output layer (unchanged)
// ---------------------------------------------------------------------------
__global__ void __launch_bounds__(256) gemm_out_bf(
    const bf16* __restrict__ Xh, const bf16* __restrict__ Xl, int ldx,
    const float* __restrict__ W, int ldw,
    const float* __restrict__ bias,
    float* __restrict__ out, int K, int t0)
{
    __shared__ __align__(16) float sX[16 * 132];
    __shared__ __align__(16) float sW[16 * 36];
    const int tid = threadIdx.x;
    const int ty = tid >> 4, tx = tid & 15;
    const int mB = blockIdx.y * 128;
    const int xr = tid >> 2, xc = tid & 3;

    const bf16* XpH0 = Xh + (size_t)(mB + xr) * ldx + xc * 4;
    const bf16* XpL0 = Xl + (size_t)(mB + xr) * ldx + xc * 4;
    const bf16* XpH1 = XpH0 + (size_t)64 * ldx;
    const bf16* XpL1 = XpL0 + (size_t)64 * ldx;
    const bool wp = tid < 128;
    const float* Wp = W + (size_t)xr * ldw + xc * 4;

    uint2 xh0 = __ldg((const uint2*)XpH0);
    uint2 xl0 = __ldg((const uint2*)XpL0);
    uint2 xh1 = __ldg((const uint2*)XpH1);
    uint2 xl1 = __ldg((const uint2*)XpL1);
    float4 wv = make_float4(0,0,0,0);
    if (wp) wv = __ldg((const float4*)Wp);

    float acc[8][2];
#pragma unroll
    for (int i = 0; i < 8; i++) { acc[i][0] = 0.f; acc[i][1] = 0.f; }

    for (int k0 = 0;;) {
        {
            float2 a = comb2(xh0.x, xl0.x), b = comb2(xh0.y, xl0.y);
            sX[(xc*4+0)*132 + xr] = a.x; sX[(xc*4+1)*132 + xr] = a.y;
            sX[(xc*4+2)*132 + xr] = b.x; sX[(xc*4+3)*132 + xr] = b.y;
            float2 c = comb2(xh1.x, xl1.x), d = comb2(xh1.y, xl1.y);
            sX[(xc*4+0)*132 + xr+64] = c.x; sX[(xc*4+1)*132 + xr+64] = c.y;
            sX[(xc*4+2)*132 + xr+64] = d.x; sX[(xc*4+3)*132 + xr+64] = d.y;
        }
        if (wp) {
            sW[(xc*4+0)*36 + xr] = wv.x; sW[(xc*4+1)*36 + xr] = wv.y;
            sW[(xc*4+2)*36 + xr] = wv.z; sW[(xc*4+3)*36 + xr] = wv.w;
        }
        __syncthreads();
        const int k1 = k0 + 16;
        if (k1 < K) {
            xh0 = __ldg((const uint2*)(XpH0 + k1));
            xl0 = __ldg((const uint2*)(XpL0 + k1));
            xh1 = __ldg((const uint2*)(XpH1 + k1));
            xl1 = __ldg((const uint2*)(XpL1 + k1));
            if (wp) wv = __ldg((const float4*)(Wp + k1));
        }
#pragma unroll
        for (int kk = 0; kk < 16; kk++) {
            float4 a0 = *(const float4*)&sX[kk*132 + ty*8];
            float4 a1 = *(const float4*)&sX[kk*132 + ty*8 + 4];
            float2 b  = *(const float2*)&sW[kk*36 + tx*2];
            acc[0][0]+=a0.x*b.x; acc[0][1]+=a0.x*b.y;
            acc[1][0]+=a0.y*b.x; acc[1][1]+=a0.y*b.y;
            acc[2][0]+=a0.z*b.x; acc[2][1]+=a0.z*b.y;
            acc[3][0]+=a0.w*b.x; acc[3][1]+=a0.w*b.y;
            acc[4][0]+=a1.x*b.x; acc[4][1]+=a1.x*b.y;
            acc[5][0]+=a1.y*b.x; acc[5][1]+=a1.y*b.y;
            acc[6][0]+=a1.z*b.x; acc[6][1]+=a1.z*b.y;
            acc[7][0]+=a1.w*b.x; acc[7][1]+=a1.w*b.y;
        }
        __syncthreads();
        if (k1 >= K) break;
        k0 = k1;
    }

    float2 bb = *(const float2*)(bias + tx * 2);
#pragma unroll
    for (int i = 0; i < 8; i++) {
        int r = mB + ty * 8 + i;
        int b = r & (BATCH - 1);
        int t = t0 + (r >> 7);
        float2 v = make_float2(acc[i][0] + bb.x, acc[i][1] + bb.y);
        *(float2*)(out + ((size_t)b * HORIZON + t) * OBS + tx * 2) = v;
    }
}

// ---------------------------------------------------------------------------
// Phase-2 R1 prologue (unchanged from round 15)
// ---------------------------------------------------------------------------
__device__ __forceinline__ void prologueW1(
    uint32_t sbase, int nT,
    const bf16* __restrict__ Wh, const bf16* __restrict__ Wl,
    const bf16* __restrict__ Vh, const bf16* __restrict__ Vl, int whCol0)
{
    const int tid = threadIdx.x;
    const int half = tid >> 8, lt = tid & 255;
#pragma unroll
    for (int s = 0; s < 2; s++) {
        const int c = half * 2 + s;
        const int k0 = c << 6;
        const uint32_t base = (uint32_t)c * (uint32_t)STAGE_W;
#pragma unroll
        for (int ii = 0; ii < 2; ii++) {
            const int o = lt + ii * 256;
            const int p = o >> 8, q = o & 255, row = q >> 3, sg = q & 7;
            const uint32_t dw = base + 2304u + (uint32_t)p * 1152u + row * 36u + sg * 4u;
            const bf16* src = (p ? Wl : Wh) + (size_t)(nT + row) * LAT + k0 + sg * 8;
            cpa16(sbase + dw * 4u, src);
        }
        if (lt < 128) {
            const int p = lt >> 6, q = lt & 63, row = q >> 3, sg = q & 7;
            const uint32_t dw = base + 4608u + (uint32_t)p * 288u + row * 36u + sg * 4u;
            const bf16* src = (p ? Vl : Vh) + (size_t)(whCol0 + row) * 256 + k0 + sg * 8;
            cpa16(sbase + dw * 4u, src);
        }
        asm volatile("cp.async.commit_group;" ::: "memory");
    }
}

// ---------------------------------------------------------------------------
// Phase-2 R1 region (unchanged from round 15)
// ---------------------------------------------------------------------------
__device__ void mma_region1(
    uint32_t* SW, uint32_t sbase,
    int mT, int nT,
    const bf16* __restrict__ Xh, const bf16* __restrict__ Xl,
    const bf16* __restrict__ Wh, const bf16* __restrict__ Wl,
    const float* __restrict__ bias,
    bf16* __restrict__ Yh, bf16* __restrict__ Yl,
    float* __restrict__ Cout, int whCol0)
{
    const int tid = threadIdx.x;
    const int half = tid >> 8, lt = tid & 255;
    const int lane = tid & 31, lwid = (tid >> 5) & 7;
    const int mw = lwid >> 2, nw = lwid & 3;
    const int cBase = half * 2;

#pragma unroll
    for (int s = 0; s < 2; s++) {
        const int k0 = (cBase + s) << 6;
        const uint32_t base = (uint32_t)(cBase + s) * (uint32_t)STAGE_W;
#pragma unroll
        for (int ii = 0; ii < 2; ii++) {
            const int o = lt + ii * 256;
            const int p = o >> 8, q = o & 255, row = q >> 3, sg = q & 7;
            const uint32_t dw = base + (uint32_t)p * 1152u + row * 36u + sg * 4u;
            const bf16* src = (p ? Xl : Xh) + (size_t)(mT + row) * LAT + k0 + sg * 8;
            cpa16(sbase + dw * 4u, src);
        }
        asm volatile("cp.async.commit_group;" ::: "memory");
    }

    float ahh[4] = {0,0,0,0}, ahl[4] = {0,0,0,0}, alh[4] = {0,0,0,0};
    float whh[4] = {0,0,0,0}, whl[4] = {0,0,0,0}, wlh[4] = {0,0,0,0};

    const int r0 = mw * 16 + (lane >> 2);
    const int wc = lane & 3;
    const int aoff0 = r0 * 36 + wc;
    const int aoff1 = (r0 + 8) * 36 + wc;
    const int boff = (nw * 8 + (lane >> 2)) * 36 + wc;
    const int voff = (lane >> 2) * 36 + wc;

    for (int lc = 0; lc < 2; lc++) {
        if (lc == 1) asm volatile("cp.async.wait_group 0;" ::: "memory");
        else         asm volatile("cp.async.wait_group 1;" ::: "memory");
        barh(half);
        const uint32_t* S   = SW + (cBase + lc) * STAGE_W;
        const uint32_t* XHs = S;
        const uint32_t* XLs = S + 1152;
        const uint32_t* WHs = S + 2304;
        const uint32_t* WLs = S + 3456;
        const uint32_t* VHs = S + 4608;
        const uint32_t* VLs = S + 4896;
#pragma unroll
        for (int wb = 0; wb < 32; wb += 8) {
            uint32_t ah[4], al[4];
            ah[0] = XHs[aoff0 + wb];     ah[1] = XHs[aoff1 + wb];
            ah[2] = XHs[aoff0 + wb + 4]; ah[3] = XHs[aoff1 + wb + 4];
            al[0] = XLs[aoff0 + wb];     al[1] = XLs[aoff1 + wb];
            al[2] = XLs[aoff0 + wb + 4]; al[3] = XLs[aoff1 + wb + 4];
            uint32_t bh0 = WHs[boff + wb], bh1 = WHs[boff + wb + 4];
            uint32_t bl0 = WLs[boff + wb], bl1 = WLs[boff + wb + 4];
            mma16(ahh, ah, bh0, bh1);
            mma16(ahl, ah, bl0, bl1);
            mma16(alh, al, bh0, bh1);
            if (nw == 0) {
                uint32_t vh0 = VHs[voff + wb], vh1 = VHs[voff + wb + 4];
                uint32_t vl0 = VLs[voff + wb], vl1 = VLs[voff + wb + 4];
                mma16(whh, ah, vh0, vh1);
                mma16(whl, ah, vl0, vl1);
                mma16(wlh, al, vh0, vh1);
            }
        }
        barh(half);
    }

    float* RED  = (float*)SW + RED_OFF;
    float* REDW = (float*)SW + REDW_OFF;
    const int ocol_l = nw * 8 + wc * 2;
    __syncthreads();
    if (half == 0) {
        RED[r0 * 33 + ocol_l]           = ahh[0] + ahl[0] + alh[0];
        RED[r0 * 33 + ocol_l + 1]       = ahh[1] + ahl[1] + alh[1];
        RED[(r0 + 8) * 33 + ocol_l]     = ahh[2] + ahl[2] + alh[2];
        RED[(r0 + 8) * 33 + ocol_l + 1] = ahh[3] + ahl[3] + alh[3];
        if (nw == 0) {
            REDW[r0 * 9 + wc * 2]           = whh[0] + whl[0] + wlh[0];
            REDW[r0 * 9 + wc * 2 + 1]       = whh[1] + whl[1] + wlh[1];
            REDW[(r0 + 8) * 9 + wc * 2]     = whh[2] + whl[2] + wlh[2];
            REDW[(r0 + 8) * 9 + wc * 2 + 1] = whh[3] + whl[3] + wlh[3];
        }
    }
    __syncthreads();

    if (half == 1) {
        const int orow = mT + r0;
        const int ocol = nT + ocol_l;
        float2 bb = *(const float2*)(bias + ocol);
        float v0 = RED[r0 * 33 + ocol_l]           + ahh[0] + ahl[0] + alh[0] + bb.x;
        float v1 = RED[r0 * 33 + ocol_l + 1]       + ahh[1] + ahl[1] + alh[1] + bb.y;
        float v2 = RED[(r0 + 8) * 33 + ocol_l]     + ahh[2] + ahl[2] + alh[2] + bb.x;
        float v3 = RED[(r0 + 8) * 33 + ocol_l + 1] + ahh[3] + ahl[3] + alh[3] + bb.y;
        v0 = fmaxf(v0, 0.f); v1 = fmaxf(v1, 0.f);
        v2 = fmaxf(v2, 0.f); v3 = fmaxf(v3, 0.f);
        uint32_t hw, lw;
        split_pack(v0, v1, hw, lw);
        __stcg((uint32_t*)&Yh[(size_t)orow * HID + ocol], hw);
        __stcg((uint32_t*)&Yl[(size_t)orow * HID + ocol], lw);
        split_pack(v2, v3, hw, lw);
        __stcg((uint32_t*)&Yh[(size_t)(orow + 8) * HID + ocol], hw);
        __stcg((uint32_t*)&Yl[(size_t)(orow + 8) * HID + ocol], lw);
        if (nw == 0) {
            const int wcol = whCol0 + wc * 2;
            float w0 = REDW[r0 * 9 + wc * 2]           + whh[0] + whl[0] + wlh[0];
            float w1 = REDW[r0 * 9 + wc * 2 + 1]       + whh[1] + whl[1] + wlh[1];
            float w2 = REDW[(r0 + 8) * 9 + wc * 2]     + whh[2] + whl[2] + wlh[2];
            float w3 = REDW[(r0 + 8) * 9 + wc * 2 + 1] + whh[3] + whl[3] + wlh[3];
            __stcg((float2*)&Cout[(size_t)(mT + r0) * LAT + wcol], make_float2(w0, w1));
            __stcg((float2*)&Cout[(size_t)(mT + r0 + 8) * LAT + wcol], make_float2(w2, w3));
        }
    }
}

// ---------------------------------------------------------------------------
// Phase-2 R2-R4 W prologue (unchanged from round 15)
// ---------------------------------------------------------------------------
__device__ __forceinline__ void prologueW2(
    uint32_t sbase, int nT,
    const bf16* __restrict__ Wh, const bf16* __restrict__ Wl)
{
    const int tid = threadIdx.x;
    const int half = tid >> 8, lt = tid & 255;
#pragma unroll
    for (int s = 0; s < 2; s++) {
        const int c = half * 4 + s;
        const int k0 = c << 7;
        const uint32_t base = (uint32_t)(half * 2 + s) * (uint32_t)STAGE2_W;
#pragma unroll
        for (int ii = 0; ii < 4; ii++) {
            const int o = lt + ii * 256;
            const int p = o >> 9, q = o & 511, row = q >> 4, sx = q & 15;
            const uint32_t dw = base + 4352u + (uint32_t)p * 2176u + row * 68u + sx * 4u;
            const bf16* src = (p ? Wl : Wh) + (size_t)(nT + row) * HID + k0 + sx * 8;
            cpa16(sbase + dw * 4u, src);
        }
        asm volatile("cp.async.commit_group;" ::: "memory");
    }
}

// ---------------------------------------------------------------------------
// Phase-2 R2-R4 region (unchanged from round 15)
// ---------------------------------------------------------------------------
template<bool DOL5>
__device__ void mma_region2(
    uint32_t* SW, uint32_t sbase,
    int mT, int nT,
    const bf16* __restrict__ Xh, const bf16* __restrict__ Xl,
    const bf16* __restrict__ Wh, const bf16* __restrict__ Wl,
    const float* __restrict__ bias,
    bf16* __restrict__ Yh, bf16* __restrict__ Yl,
    const float* __restrict__ W5, float* __restrict__ yhpart, int jIdx)
{
    const int tid = threadIdx.x;
    const int half = tid >> 8, lt = tid & 255;
    const int lane = tid & 31, lwid = (tid >> 5) & 7;
    const int mw = lwid >> 2, nw = lwid & 3;
    const int cBase = half * 4;
    const int sBase = half * 2;

#pragma unroll
    for (int s = 0; s < 2; s++) {
        const int k0 = (cBase + s) << 7;
        const uint32_t base = (uint32_t)(sBase + s) * (uint32_t)STAGE2_W;
#pragma unroll
        for (int ii = 0; ii < 4; ii++) {
            const int o = lt + ii * 256;
            const int p = o >> 9, q = o & 511, row = q >> 4, sx = q & 15;
            const uint32_t dw = base + (uint32_t)p * 2176u + row * 68u + sx * 4u;
            const bf16* src = (p ? Xl : Xh) + (size_t)(mT + row) * HID + k0 + sx * 8;
            cpa16(sbase + dw * 4u, src);
        }
        asm volatile("cp.async.commit_group;" ::: "memory");
    }

    auto issueC = [&](int lc) {
        const int k0 = (cBase + lc) << 7;
        const uint32_t base = (uint32_t)(sBase + (lc & 1)) * (uint32_t)STAGE2_W;
#pragma unroll
        for (int ii = 0; ii < 8; ii++) {
            const int o = lt + ii * 256;
            const int p = o >> 9, q = o & 511, row = q >> 4, sx = q & 15;
            const int plane = p & 1;
            const uint32_t dw = base + (uint32_t)(p >> 1) * 4352u
                              + (uint32_t)plane * 2176u + row * 68u + sx * 4u;
            const bf16* src;
            if (p == 0)      src = Xh + (size_t)(mT + row) * HID + k0 + sx * 8;
            else if (p == 1) src = Xl + (size_t)(mT + row) * HID + k0 + sx * 8;
            else if (p == 2) src = Wh + (size_t)(nT + row) * HID + k0 + sx * 8;
            else             src = Wl + (size_t)(nT + row) * HID + k0 + sx * 8;
            cpa16(sbase + dw * 4u, src);
        }
        asm volatile("cp.async.commit_group;" ::: "memory");
    };

    float ahh[4] = {0,0,0,0}, ahl[4] = {0,0,0,0}, alh[4] = {0,0,0,0};

    const int r0 = mw * 16 + (lane >> 2);
    const int wc = lane & 3;
    const int aoff0 = r0 * 68 + wc;
    const int aoff1 = (r0 + 8) * 68 + wc;
    const int boff = (nw * 8 + (lane >> 2)) * 68 + wc;

    for (int lc = 0; lc < 4; lc++) {
        if (lc >= 3) asm volatile("cp.async.wait_group 0;" ::: "memory");
        else         asm volatile("cp.async.wait_group 1;" ::: "memory");
        barh(half);
        const uint32_t* S   = SW + (sBase + (lc & 1)) * STAGE2_W;
        const uint32_t* XHs = S;
        const uint32_t* XLs = S + 2176;
        const uint32_t* WHs = S + 4352;
        const uint32_t* WLs = S + 6528;
#pragma unroll
        for (int wb = 0; wb < 64; wb += 8) {
            uint32_t ah[4], al[4];
            ah[0] = XHs[aoff0 + wb];     ah[1] = XHs[aoff1 + wb];
            ah[2] = XHs[aoff0 + wb + 4]; ah[3] = XHs[aoff1 + wb + 4];
            al[0] = XLs[aoff0 + wb];     al[1] = XLs[aoff1 + wb];
            al[2] = XLs[aoff0 + wb + 4]; al[3] = XLs[aoff1 + wb + 4];
            uint32_t bh0 = WHs[boff + wb], bh1 = WHs[boff + wb + 4];
            uint32_t bl0 = WLs[boff + wb], bl1 = WLs[boff + wb + 4];
            mma16(ahh, ah, bh0, bh1);
            mma16(ahl, ah, bl0, bl1);
            mma16(alh, al, bh0, bh1);
        }
        barh(half);
        if (lc + 2 < 4) issueC(lc + 2);
    }

    float* RED = (float*)SW + RED_OFF;
    const int ocol_l = nw * 8 + wc * 2;
    __syncthreads();
    if (half == 0) {
        RED[r0 * 33 + ocol_l]           = ahh[0] + ahl[0] + alh[0];
        RED[r0 * 33 + ocol_l + 1]       = ahh[1] + ahl[1] + alh[1];
        RED[(r0 + 8) * 33 + ocol_l]     = ahh[2] + ahl[2] + alh[2];
        RED[(r0 + 8) * 33 + ocol_l + 1] = ahh[3] + ahl[3] + alh[3];
    }
    __syncthreads();

    float* sh4 = (float*)SW + SH4_OFF;
    if (half == 1) {
        const int orow = mT + r0;
        const int ocol = nT + ocol_l;
        float2 bb = *(const float2*)(bias + ocol);
        float v0 = RED[r0 * 33 + ocol_l]           + ahh[0] + ahl[0] + alh[0] + bb.x;
        float v1 = RED[r0 * 33 + ocol_l + 1]       + ahh[1] + ahl[1] + alh[1] + bb.y;
        float v2 = RED[(r0 + 8) * 33 + ocol_l]     + ahh[2] + ahl[2] + alh[2] + bb.x;
        float v3 = RED[(r0 + 8) * 33 + ocol_l + 1] + ahh[3] + ahl[3] + alh[3] + bb.y;
        v0 = fmaxf(v0, 0.f); v1 = fmaxf(v1, 0.f);
        v2 = fmaxf(v2, 0.f); v3 = fmaxf(v3, 0.f);
        if (DOL5) {
            sh4[r0 * 33 + ocol_l]           = v0;
            sh4[r0 * 33 + ocol_l + 1]       = v1;
            sh4[(r0 + 8) * 33 + ocol_l]     = v2;
            sh4[(r0 + 8) * 33 + ocol_l + 1] = v3;
        } else {
            uint32_t hw, lw;
            split_pack(v0, v1, hw, lw);
            __stcg((uint32_t*)&Yh[(size_t)orow * HID + ocol], hw);
            __stcg((uint32_t*)&Yl[(size_t)orow * HID + ocol], lw);
            split_pack(v2, v3, hw, lw);
            __stcg((uint32_t*)&Yh[(size_t)(orow + 8) * HID + ocol], hw);
            __stcg((uint32_t*)&Yl[(size_t)(orow + 8) * HID + ocol], lw);
        }
    }

    if (DOL5) {
        __syncthreads();
        const float* w5r = W5 + (size_t)lane * HID + nT;
        float w5f[32];
#pragma unroll
        for (int q = 0; q < 8; q++) {
            float4 w = __ldg((const float4*)(w5r + q * 4));
            w5f[q*4+0] = w.x; w5f[q*4+1] = w.y; w5f[q*4+2] = w.z; w5f[q*4+3] = w.w;
        }
        const int wfull = tid >> 5;
#pragma unroll
        for (int i = 0; i < 2; i++) {
            const int r = wfull * 2 + i;
            const float* hr = sh4 + r * 33;
            float s = 0.f;
#pragma unroll
            for (int n = 0; n < 32; n++) s += hr[n] * w5f[n];
            __stcg(yhpart + (size_t)jIdx * (BATCH * 32) + (mT + r) * 32 + lane, s);
        }
    }
}

// ---------------------------------------------------------------------------
// Phase 2 (unchanged from round 15)
// ---------------------------------------------------------------------------
__global__ void __launch_bounds__(512, 1) phase2_kernel(
    const float* __restrict__ b1, const float* __restrict__ b2,
    const float* __restrict__ b3, const float* __restrict__ b4,
    const float* __restrict__ W5, const float* __restrict__ b5,
    const float* __restrict__ Wih,
    const float* __restrict__ bih, const float* __restrict__ bhh,
    const float* __restrict__ Z,
    float* __restrict__ PL,
    float* __restrict__ out)
{
    extern __shared__ __align__(16) uint32_t SW[];
    const uint32_t sbase = (uint32_t)__cvta_generic_to_shared(SW);
    const int bid = blockIdx.x, tid = threadIdx.x;
    const int g = bid >> 5, j = bid & 31;
    const int mT = g * 32, nT = j * 32;
    const int b = bid;
    unsigned target = 0;

    bf16* AH = (bf16*)(PL + C_AH);
    bf16* AL = (bf16*)(PL + C_AL);
    bf16* BH = (bf16*)(PL + C_BH);
    bf16* BL = (bf16*)(PL + C_BL);
    bf16* ZH = (bf16*)(PL + C_ZH);
    bf16* ZL = (bf16*)(PL + C_ZL);
    float* C  = PL + C_C;
    float* YP = PL + C_YP;

    const bf16 *W1H = g_WHB + OFF_W1,  *W1L = g_WLB + OFF_W1;
    const bf16 *W2H = g_WHB + OFF_W2,  *W2L = g_WLB + OFF_W2;
    const bf16 *W3H = g_WHB + OFF_W3,  *W3L = g_WLB + OFF_W3;
    const bf16 *W4H = g_WHB + OFF_W4,  *W4L = g_WLB + OFF_W4;
    const bf16 *VH  = g_WHB + OFF_WHH, *VL  = g_WLB + OFF_WHH;

    if (tid < 128) {
        float2 z2 = __ldcg((const float2*)(Z + (size_t)TSTEPS * ZSTRIDE + (size_t)b * LAT) + tid);
        uint32_t hw, lw;
        split_pack(z2.x, z2.y, hw, lw);
        __stcg((uint32_t*)(ZH + (size_t)b * LAT) + tid, hw);
        __stcg((uint32_t*)(ZL + (size_t)b * LAT) + tid, lw);
    }
    prologueW1(sbase, nT, W1H, W1L, VH, VL, j * 8);
    ggsync(g, target);

    for (int t = TSTEPS; t < HORIZON; t++) {
        mma_region1(SW, sbase, mT, nT, ZH, ZL, W1H, W1L, b1, AH, AL, C, j * 8);
        prologueW2(sbase, nT, W2H, W2L);
        ggsync(g, target);
        mma_region2<false>(SW, sbase, mT, nT, AH, AL, W2H, W2L, b2, BH, BL,
                           (const float*)0, (float*)0, 0);
        prologueW2(sbase, nT, W3H, W3L);
        ggsync(g, target);
        mma_region2<false>(SW, sbase, mT, nT, BH, BL, W3H, W3L, b3, AH, AL,
                           (const float*)0, (float*)0, 0);
        prologueW2(sbase, nT, W4H, W4L);
        ggsync(g, target);
        mma_region2<true>(SW, sbase, mT, nT, AH, AL, W4H, W4L, b4,
                          (bf16*)0, (bf16*)0, W5, YP, j);
        ggsync(g, target);

        {
            float* FS = (float*)SW;
            if (tid < OBS) {
                float s = __ldg(b5 + tid);
                const float* yp = YP + (size_t)b * 32 + tid;
#pragma unroll
                for (int jj = 0; jj < 32; jj++)
                    s += __ldcg(yp + (size_t)jj * (BATCH * 32));
                __stcg(out + ((size_t)b * HORIZON + t) * OBS + tid, s);
                FS[tid] = s;
            }
            __syncthreads();
            if (t < HORIZON - 1) {
                if (tid < 256) {
                    const int n = tid;
                    float acc = __ldcg(C + (size_t)b * LAT + n)
                              + __ldg(bih + n) + __ldg(bhh + n);
                    const float4* wr = (const float4*)(Wih + (size_t)n * OBS);
#pragma unroll
                    for (int k = 0; k < 8; k++) {
                        float4 wv = __ldg(wr + k);
                        acc += FS[k*4+0]*wv.x + FS[k*4+1]*wv.y
                             + FS[k*4+2]*wv.z + FS[k*4+3]*wv.w;
                    }
                    FS[64 + n] = tanhf(acc);
                }
                __syncthreads();
                if (tid < 128) {
                    float z0 = FS[64 + 2*tid], z1 = FS[64 + 2*tid + 1];
                    uint32_t hw, lw;
                    split_pack(z0, z1, hw, lw);
                    __stcg((uint32_t*)(ZH + (size_t)b * LAT) + tid, hw);
                    __stcg((uint32_t*)(ZL + (size_t)b * LAT) + tid, lw);
                }
                __syncthreads();
                prologueW1(sbase, nT, W1H, W1L, VH, VL, j * 8);
            }
        }
        ggsync(g, target);
    }
}

// ---------------------------------------------------------------------------
// Launch: phase 1b forked onto a second stream, overlapping phase 2.
// Disjoint data: phase2 writes out[:,256:], uses g_Z tail; 1b writes
// out[:,:256], uses g_A/g_B; weight planes read-only for both.
// ---------------------------------------------------------------------------
extern "C" void kernel_launch(void* const* d_in, const int* in_sizes, int n_in,
                              void* d_out, int out_size)
{
    const float* y   = (const float*)d_in[0];
    const float* Wih = (const float*)d_in[2];
    const float* Whh = (const float*)d_in[3];
    const float* bih = (const float*)d_in[4];
    const float* bhh = (const float*)d_in[5];
    const float* W1  = (const float*)d_in[6];
    const float* b1  = (const float*)d_in[7];
    const float* W2  = (const float*)d_in[8];
    const float* b2  = (const float*)d_in[9];
    const float* W3  = (const float*)d_in[10];
    const float* b3  = (const float*)d_in[11];
    const float* W4  = (const float*)d_in[12];
    const float* b4  = (const float*)d_in[13];
    const float* W5  = (const float*)d_in[14];
    const float* b5  = (const float*)d_in[15];
    float* out = (float*)d_out;

    float *Z, *A, *Bf;
    bf16 *WHB, *WLB, *ZPH, *ZPL;
    cudaGetSymbolAddress((void**)&Z,    g_Z);
    cudaGetSymbolAddress((void**)&A,    g_A);
    cudaGetSymbolAddress((void**)&Bf,   g_B);
    cudaGetSymbolAddress((void**)&WHB,  g_WHB);
    cudaGetSymbolAddress((void**)&WLB,  g_WLB);
    cudaGetSymbolAddress((void**)&ZPH,  g_ZPH);
    cudaGetSymbolAddress((void**)&ZPL,  g_ZPL);

    static cudaStream_t s2 = 0;
    static cudaEvent_t evFork = 0, evJoin = 0;
    static int attr_done = 0;
    if (!attr_done) {
        cudaFuncSetAttribute(phase2_kernel,
                             cudaFuncAttributeMaxDynamicSharedMemorySize, P2_SMEM);
        cudaFuncSetAttribute(gemm_mma_128,
                             cudaFuncAttributeMaxDynamicSharedMemorySize, SMEM1B);
        cudaStreamCreateWithFlags(&s2, cudaStreamNonBlocking);
        cudaEventCreateWithFlags(&evFork, cudaEventDisableTiming);
        cudaEventCreateWithFlags(&evJoin, cudaEventDisableTiming);
        attr_done = 1;
    }

    // [0] fused weight hi/lo split
    splitw_all<<<(NW_TOT + 255)/256, 256>>>(W1, W2, W3, W4, Whh);

    // [1] phase 1a (also zeroes group barriers)
    phase1a_kernel<<<BATCH / 2, 256>>>(y, Wih, Whh, bih, bhh, Z);

    // [2] split teacher-forced z states into bf16 planes
    splitw_bf16<<<(TSTEPS * ZSTRIDE + 255)/256, 256>>>(Z, ZPH, ZPL, TSTEPS * ZSTRIDE);

    // fork s2 off the main stream (both branches depend on the z split)
    cudaEventRecord(evFork, 0);
    cudaStreamWaitEvent(s2, evFork, 0);

    // [main] phase 2 (persistent AR rollout)
    phase2_kernel<<<128, 512, P2_SMEM>>>(b1, b2, b3, b4, W5, b5, Wih, bih, bhh,
                                         Z, Z + (size_t)P2_BASE, out);

    // [s2] phase 1b: 2 chunks of 128 steps, runs on SMs phase 2 leaves free
    const int CHUNK = 128;
    const int MBIG  = CHUNK * BATCH;
    bf16* AH = (bf16*)A;
    bf16* AL = (bf16*)A + (size_t)MBIG * HID;
    bf16* BH = (bf16*)Bf;
    bf16* BL = (bf16*)Bf + (size_t)MBIG * HID;
    for (int c = 0; c < TSTEPS / CHUNK; c++) {
        const bf16* XzH = ZPH + (size_t)c * CHUNK * ZSTRIDE;
        const bf16* XzL = ZPL + (size_t)c * CHUNK * ZSTRIDE;
        gemm_mma_128<<<dim3(HID/128, MBIG/128), 256, SMEM1B, s2>>>(
            XzH, XzL, LAT, WHB + OFF_W1, WLB + OFF_W1, LAT, b1, AH, AL, HID, LAT);
        gemm_mma_128<<<dim3(HID/128, MBIG/128), 256, SMEM1B, s2>>>(
            AH, AL, HID, WHB + OFF_W2, WLB + OFF_W2, HID, b2, BH, BL, HID, HID);
        gemm_mma_128<<<dim3(HID/128, MBIG/128), 256, SMEM1B, s2>>>(
            BH, BL, HID, WHB + OFF_W3, WLB + OFF_W3, HID, b3, AH, AL, HID, HID);
        gemm_mma_128<<<dim3(HID/128, MBIG/128), 256, SMEM1B, s2>>>(
            AH, AL, HID, WHB + OFF_W4, WLB + OFF_W4, HID, b4, BH, BL, HID, HID);
        gemm_out_bf<<<dim3(1, MBIG/128), 256, 0, s2>>>(
            BH, BL, HID, W5, HID, b5, out, HID, c * CHUNK);
    }

    // join s2 back into the main stream before returning
    cudaEventRecord(evJoin, s2);
    cudaStreamWaitEvent(0, evJoin, 0);
}